// round 15
// baseline (speedup 1.0000x reference)
#include <cuda_runtime.h>
#include <cuda_fp16.h>
#include <cstdint>
#include <cstdio>
#include <cstring>
#include <cmath>
#include <dlfcn.h>

#define IN_F   4096
#define OUT_F  4096
#define M_ROWS 8192

// Host-module fp16 scratch (used by the host fallback path).
__device__ __half g_Xh[(size_t)M_ROWS * IN_F];
__device__ __half g_Wh[(size_t)OUT_F * IN_F];

__constant__ float NF4[16] = {
    -1.0f, -0.6961928009986877f, -0.5250730514526367f, -0.39491748809814453f,
    -0.28444138169288635f, -0.18477343022823334f, -0.09105003625154495f, 0.0f,
    0.07958029955625534f, 0.16093020141124725f, 0.24611230194568634f,
    0.33791524171829224f, 0.4407098889350891f, 0.5626170039176941f,
    0.7229568362236023f, 1.0f
};

static const float NF4H[16] = {
    -1.0f, -0.6961928009986877f, -0.5250730514526367f, -0.39491748809814453f,
    -0.28444138169288635f, -0.18477343022823334f, -0.09105003625154495f, 0.0f,
    0.07958029955625534f, 0.16093020141124725f, 0.24611230194568634f,
    0.33791524171829224f, 0.4407098889350891f, 0.5626170039176941f,
    0.7229568362236023f, 1.0f
};

__device__ __forceinline__ uint32_t smem_u32(const void* p) {
    uint32_t a;
    asm("{ .reg .u64 t; cvta.to.shared.u64 t, %1; cvt.u32.u64 %0, t; }" : "=r"(a) : "l"(p));
    return a;
}

// ---------------------------------------------------------------------------
// Kernel A: convert x (fp32) -> dst (fp16) row-major. 8 elems/thread.
// ---------------------------------------------------------------------------
__global__ void convert_x_kernel(const float* __restrict__ x, __half* __restrict__ dst) {
    size_t i = ((size_t)blockIdx.x * 256 + threadIdx.x) * 8;
    float4 v0 = *(const float4*)(x + i);
    float4 v1 = *(const float4*)(x + i + 4);
    __half2 h0 = __floats2half2_rn(v0.x, v0.y);
    __half2 h1 = __floats2half2_rn(v0.z, v0.w);
    __half2 h2 = __floats2half2_rn(v1.x, v1.y);
    __half2 h3 = __floats2half2_rn(v1.z, v1.w);
    uint4 o;
    o.x = *(uint32_t*)&h0; o.y = *(uint32_t*)&h1;
    o.z = *(uint32_t*)&h2; o.w = *(uint32_t*)&h3;
    *(uint4*)&dst[i] = o;
}

// Kernel A': convert x -> TILED layout: tile (m>>7, k>>6) contiguous 16KB SW128.
__global__ void convert_x_tiled_kernel(const float* __restrict__ x, char* __restrict__ dst) {
    size_t i = ((size_t)blockIdx.x * 256 + threadIdx.x) * 8;
    float4 v0 = *(const float4*)(x + i);
    float4 v1 = *(const float4*)(x + i + 4);
    __half2 h0 = __floats2half2_rn(v0.x, v0.y);
    __half2 h1 = __floats2half2_rn(v0.z, v0.w);
    __half2 h2 = __floats2half2_rn(v1.x, v1.y);
    __half2 h3 = __floats2half2_rn(v1.z, v1.w);
    uint4 o;
    o.x = *(uint32_t*)&h0; o.y = *(uint32_t*)&h1;
    o.z = *(uint32_t*)&h2; o.w = *(uint32_t*)&h3;
    const uint32_t m = (uint32_t)(i >> 12), k = (uint32_t)(i & 4095);
    uint32_t off = (m & 127) * 128 + (k & 63) * 2;
    off = off ^ ((off >> 3) & 0x70);
    const size_t boff = ((size_t)((m >> 7) * 64 + (k >> 6))) * 16384 + off;
    *(uint4*)(dst + boff) = o;
}

// lora_B [4096][64] fp32 -> fp16 same layout
__global__ void cvt_lb_kernel(const float* __restrict__ lB, __half* __restrict__ lb) {
    size_t i = ((size_t)blockIdx.x * 256 + threadIdx.x) * 4;
    float4 v = *(const float4*)(lB + i);
    __half h[4] = {__float2half_rn(v.x), __float2half_rn(v.y),
                   __float2half_rn(v.z), __float2half_rn(v.w)};
    *(uint2*)&lb[i] = *(uint2*)h;
}

// lora_A [64][4096] fp32 -> lat [4096][64] fp16 (transpose)
__global__ void cvt_lat_kernel(const float* __restrict__ lA, __half* __restrict__ lat) {
    __shared__ float s[64][65];
    const int tid = threadIdx.x;
    const int i0 = blockIdx.x * 64;
    for (int idx = tid; idx < 4096; idx += 256) {
        int r = idx >> 6, ii = idx & 63;
        s[r][ii] = lA[r * IN_F + i0 + ii];
    }
    __syncthreads();
    int ii = tid >> 2, rs = (tid & 3) * 16;
    __half h[16];
#pragma unroll
    for (int j = 0; j < 16; j++) h[j] = __float2half_rn(s[rs + j][ii]);
    uint4* dst = (uint4*)&lat[(size_t)(i0 + ii) * 64 + rs];
    dst[0] = *(uint4*)&h[0];
    dst[1] = *(uint4*)&h[8];
}

// ---------------------------------------------------------------------------
// Host fallback: W_eff = NF4 dequant * absmax + lora_B @ lora_A  (fp16, row-major)
// ---------------------------------------------------------------------------
__global__ void build_weff_kernel(const int* __restrict__ qweight,
                                  const float* __restrict__ absmax,
                                  const float* __restrict__ lA,
                                  const float* __restrict__ lB,
                                  __half* __restrict__ dst) {
    __shared__ float Bsh[64][64];
    __shared__ float Ash[64][128];

    const int tid = threadIdx.x;
    const int o0 = blockIdx.y * 64;
    const int i0 = blockIdx.x * 128;

    for (int t = tid; t < 64 * 64; t += 256) {
        int o = t >> 6, r = t & 63;
        Bsh[r][o] = lB[(o0 + o) * 64 + r];
    }
    for (int t = tid; t < 64 * 128; t += 256) {
        int r = t >> 7, c = t & 127;
        Ash[r][c] = lA[r * IN_F + i0 + c];
    }
    __syncthreads();

    const int oo0 = (tid >> 4) * 4;
    const int ii0 = (tid & 15) * 8;

    float acc[4][8];
#pragma unroll
    for (int a = 0; a < 4; a++)
#pragma unroll
        for (int b = 0; b < 8; b++) acc[a][b] = 0.0f;

#pragma unroll 4
    for (int r = 0; r < 64; r++) {
        float4 a0 = *(const float4*)&Ash[r][ii0];
        float4 a1 = *(const float4*)&Ash[r][ii0 + 4];
#pragma unroll
        for (int oo = 0; oo < 4; oo++) {
            float bv = Bsh[r][oo0 + oo];
            acc[oo][0] += bv * a0.x; acc[oo][1] += bv * a0.y;
            acc[oo][2] += bv * a0.z; acc[oo][3] += bv * a0.w;
            acc[oo][4] += bv * a1.x; acc[oo][5] += bv * a1.y;
            acc[oo][6] += bv * a1.z; acc[oo][7] += bv * a1.w;
        }
    }

#pragma unroll
    for (int oo = 0; oo < 4; oo++) {
        const int o = o0 + oo0 + oo;
        const size_t k = (size_t)o * IN_F + i0 + ii0;
        const int4 qv = ((const int4*)qweight)[k >> 3];
        const float am = absmax[k >> 6];

        float w[8];
        w[0] = NF4[qv.x & 15];  w[1] = NF4[(qv.x >> 4) & 15];
        w[2] = NF4[qv.y & 15];  w[3] = NF4[(qv.y >> 4) & 15];
        w[4] = NF4[qv.z & 15];  w[5] = NF4[(qv.z >> 4) & 15];
        w[6] = NF4[qv.w & 15];  w[7] = NF4[(qv.w >> 4) & 15];

        __half2 h0 = __floats2half2_rn(w[0] * am + acc[oo][0], w[1] * am + acc[oo][1]);
        __half2 h1 = __floats2half2_rn(w[2] * am + acc[oo][2], w[3] * am + acc[oo][3]);
        __half2 h2 = __floats2half2_rn(w[4] * am + acc[oo][4], w[5] * am + acc[oo][5]);
        __half2 h3 = __floats2half2_rn(w[6] * am + acc[oo][6], w[7] * am + acc[oo][7]);
        uint4 pk;
        pk.x = *(uint32_t*)&h0; pk.y = *(uint32_t*)&h1;
        pk.z = *(uint32_t*)&h2; pk.w = *(uint32_t*)&h3;
        *(uint4*)&dst[k] = pk;
    }
}

// ---------------------------------------------------------------------------
// Host fallback GEMM (proven 778us): fp16 mma.sync, 512 thr, 4-stage.
// ---------------------------------------------------------------------------
constexpr int BM = 128, BN = 256, BK = 64, S = 4;
constexpr int NT = IN_F / BK;
constexpr int A_BYTES = BM * 128;
constexpr int B_BYTES = BN * 128;
constexpr int STAGE = A_BYTES + B_BYTES;
constexpr int SMEM_TOTAL = 1024 + S * STAGE;
constexpr int TOTAL_TILES = (M_ROWS / BM) * (OUT_F / BN);

__device__ __forceinline__ void mma_f16(float c[4], const uint32_t a[4],
                                        uint32_t b0, uint32_t b1) {
    asm volatile(
        "mma.sync.aligned.m16n8k16.row.col.f32.f16.f16.f32 "
        "{%0,%1,%2,%3}, {%4,%5,%6,%7}, {%8,%9}, {%0,%1,%2,%3};"
        : "+f"(c[0]), "+f"(c[1]), "+f"(c[2]), "+f"(c[3])
        : "r"(a[0]), "r"(a[1]), "r"(a[2]), "r"(a[3]), "r"(b0), "r"(b1));
}

__device__ __forceinline__ void ldsm4(uint32_t& r0, uint32_t& r1,
                                      uint32_t& r2, uint32_t& r3, uint32_t addr) {
    asm volatile("ldmatrix.sync.aligned.m8n8.x4.shared.b16 {%0,%1,%2,%3}, [%4];"
                 : "=r"(r0), "=r"(r1), "=r"(r2), "=r"(r3) : "r"(addr));
}

__device__ __forceinline__ void st_cs_f2(float* p, float a, float b) {
    asm volatile("st.global.cs.v2.f32 [%0], {%1,%2};" :: "l"(p), "f"(a), "f"(b)
                 : "memory");
}

__device__ __forceinline__ void issue_stage(uint32_t sA, uint32_t sB,
                                            const __half* xb, const __half* wb,
                                            int tid) {
#pragma unroll
    for (int r = 0; r < 2; r++) {
        int i = tid + r * 512;
        int row = i >> 3, c = i & 7;
        uint32_t off = (uint32_t)(row * 128 + ((c * 16) ^ ((row & 7) << 4)));
        const __half* src = xb + (size_t)row * IN_F + c * 8;
        asm volatile("cp.async.cg.shared.global.L2::256B [%0], [%1], 16;\n"
                     :: "r"(sA + off), "l"(src));
    }
#pragma unroll
    for (int r = 0; r < 4; r++) {
        int i = tid + r * 512;
        int row = i >> 3, c = i & 7;
        uint32_t off = (uint32_t)(row * 128 + ((c * 16) ^ ((row & 7) << 4)));
        const __half* src = wb + (size_t)row * IN_F + c * 8;
        asm volatile("cp.async.cg.shared.global.L2::256B [%0], [%1], 16;\n"
                     :: "r"(sB + off), "l"(src));
    }
}

__global__ void __launch_bounds__(512, 1)
gemm_f16_kernel(const __half* __restrict__ Xh, const __half* __restrict__ Wh,
                float* __restrict__ out) {
    extern __shared__ char sm[];
    const uint32_t stage0 = (smem_u32(sm) + 1023) & ~1023u;

    const int tid = threadIdx.x;
    const int wid = tid >> 5;
    const int lane = tid & 31;
    const int warp_m = wid & 3;
    const int warp_n = wid >> 2;
    const int g = lane >> 3;
    const int r = lane & 7;

    uint32_t a_rowoff[2], a_xr[2];
    const uint32_t a_kc = (uint32_t)((g >> 1) * 16);
#pragma unroll
    for (int mf = 0; mf < 2; mf++) {
        int row = warp_m * 32 + mf * 16 + (g & 1) * 8 + r;
        a_rowoff[mf] = row * 128;
        a_xr[mf] = (row & 7) << 4;
    }
    uint32_t b_rowoff[4], b_xr[4];
    const uint32_t b_kc = (uint32_t)((g & 1) * 16);
#pragma unroll
    for (int p = 0; p < 4; p++) {
        int row = warp_n * 64 + p * 16 + (g >> 1) * 8 + r;
        b_rowoff[p] = row * 128;
        b_xr[p] = (row & 7) << 4;
    }

    for (int t = blockIdx.x; t < TOTAL_TILES; t += gridDim.x) {
        const int mBase = (t >> 4) * BM;
        const int nBase = (t & 15) * BN;
        const __half* xt = Xh + (size_t)mBase * IN_F;
        const __half* wt = Wh + (size_t)nBase * IN_F;

        float acc[2][8][4];
#pragma unroll
        for (int i = 0; i < 2; i++)
#pragma unroll
            for (int j = 0; j < 8; j++)
#pragma unroll
                for (int l = 0; l < 4; l++) acc[i][j][l] = 0.0f;

#pragma unroll
        for (int p = 0; p < S - 1; p++) {
            uint32_t sA = stage0 + p * STAGE;
            issue_stage(sA, sA + A_BYTES, xt + p * BK, wt + p * BK, tid);
            asm volatile("cp.async.commit_group;\n" ::: "memory");
        }

        for (int kt = 0; kt < NT; kt++) {
            asm volatile("cp.async.wait_group %0;\n" :: "n"(S - 2) : "memory");
            __syncthreads();

            if (kt + S - 1 < NT) {
                const int s2 = (kt + S - 1) % S;
                uint32_t sA = stage0 + s2 * STAGE;
                issue_stage(sA, sA + A_BYTES,
                            xt + (kt + S - 1) * BK, wt + (kt + S - 1) * BK, tid);
            }
            asm volatile("cp.async.commit_group;\n" ::: "memory");

            const uint32_t sA = stage0 + (kt % S) * STAGE;
            const uint32_t sB = sA + A_BYTES;

#pragma unroll
            for (int q = 0; q < 4; q++) {
                uint32_t a[2][4];
#pragma unroll
                for (int mf = 0; mf < 2; mf++)
                    ldsm4(a[mf][0], a[mf][1], a[mf][2], a[mf][3],
                          sA + a_rowoff[mf] + (((q * 32) + a_kc) ^ a_xr[mf]));
                uint32_t b[8][2];
#pragma unroll
                for (int p = 0; p < 4; p++)
                    ldsm4(b[2 * p][0], b[2 * p][1], b[2 * p + 1][0], b[2 * p + 1][1],
                          sB + b_rowoff[p] + (((q * 32) + b_kc) ^ b_xr[p]));
#pragma unroll
                for (int mf = 0; mf < 2; mf++)
#pragma unroll
                    for (int nf = 0; nf < 8; nf++)
                        mma_f16(acc[mf][nf], a[mf], b[nf][0], b[nf][1]);
            }
        }
        asm volatile("cp.async.wait_group 0;\n" ::: "memory");

#pragma unroll
        for (int mf = 0; mf < 2; mf++) {
#pragma unroll
            for (int nf = 0; nf < 8; nf++) {
                const int row = mBase + warp_m * 32 + mf * 16 + (lane >> 2);
                const int col = nBase + warp_n * 64 + nf * 8 + (lane & 3) * 2;
                st_cs_f2(&out[(size_t)row * OUT_F + col],
                         acc[mf][nf][0], acc[mf][nf][1]);
                st_cs_f2(&out[(size_t)(row + 8) * OUT_F + col],
                         acc[mf][nf][2], acc[mf][nf][3]);
            }
        }
        __syncthreads();
    }
}

// ===========================================================================
// NVRTC module: gemm7b (early loads + prologue prefetch), gemm7 (proven),
// gemm5c/5 backstops, wbuild, init kernels.
// ===========================================================================
static const char* NVRTC_SRC = R"NVSRC(
typedef unsigned int u32;
typedef unsigned long long u64;
typedef unsigned short u16;

__device__ __align__(128) u16 GX[33554432];  // X fp16 (row-major OR tiled)
__device__ __align__(128) u16 GW[16777216];  // W fp16 (row-major OR tiled)
__device__ float GOUT[33554432];             // gemm self-test output
__device__ u16 GLB[262144];                  // lora_B fp16 [4096][64]
__device__ u16 GLAT[262144];                 // lora_A^T fp16 [4096][64]
__device__ int GTQW[8388608];                // wbuild self-test qweight
__device__ float GTAM[262144];               // wbuild self-test absmax

__constant__ float NF4D[16] = {
    -1.0f, -0.6961928009986877f, -0.5250730514526367f, -0.39491748809814453f,
    -0.28444138169288635f, -0.18477343022823334f, -0.09105003625154495f, 0.0f,
    0.07958029955625534f, 0.16093020141124725f, 0.24611230194568634f,
    0.33791524171829224f, 0.4407098889350891f, 0.5626170039176941f,
    0.7229568362236023f, 1.0f
};

#define MWAIT(ba, ph) do { u32 _d; \
    asm volatile("{ .reg .pred p; mbarrier.try_wait.parity.acquire.cta.shared::cta.b64 p, [%1], %2; selp.b32 %0,1,0,p; }" \
                 : "=r"(_d) : "r"(ba), "r"(ph) : "memory"); \
    if (!_d) { \
        asm volatile("{ .reg .pred P1; WL%=: mbarrier.try_wait.parity.acquire.cta.shared::cta.b64 P1, [%0], %1, 0x989680; @P1 bra.uni WD%=; bra.uni WL%=; WD%=: }" \
                     :: "r"(ba), "r"(ph) : "memory"); } } while(0)

#define LDTM32(rr, addr) \
    asm volatile("tcgen05.ld.sync.aligned.32x32b.x32.b32 " \
        "{%0,%1,%2,%3,%4,%5,%6,%7,%8,%9,%10,%11,%12,%13,%14,%15," \
        "%16,%17,%18,%19,%20,%21,%22,%23,%24,%25,%26,%27,%28,%29,%30,%31}, [%32];" \
        : "=r"(rr[0]), "=r"(rr[1]), "=r"(rr[2]), "=r"(rr[3]), \
          "=r"(rr[4]), "=r"(rr[5]), "=r"(rr[6]), "=r"(rr[7]), \
          "=r"(rr[8]), "=r"(rr[9]), "=r"(rr[10]), "=r"(rr[11]), \
          "=r"(rr[12]), "=r"(rr[13]), "=r"(rr[14]), "=r"(rr[15]), \
          "=r"(rr[16]), "=r"(rr[17]), "=r"(rr[18]), "=r"(rr[19]), \
          "=r"(rr[20]), "=r"(rr[21]), "=r"(rr[22]), "=r"(rr[23]), \
          "=r"(rr[24]), "=r"(rr[25]), "=r"(rr[26]), "=r"(rr[27]), \
          "=r"(rr[28]), "=r"(rr[29]), "=r"(rr[30]), "=r"(rr[31]) \
        : "r"(addr))

#define BULK(dst, src, sz, mbar) \
    asm volatile("cp.async.bulk.shared::cta.global.mbarrier::complete_tx::bytes " \
                 "[%0], [%1], %2, [%3];" \
                 :: "r"(dst), "l"(src), "r"(sz), "r"(mbar) : "memory")

#define EXPECT_TX(mbar, n) \
    asm volatile("mbarrier.arrive.expect_tx.shared.b64 _, [%0], %1;" \
                 :: "r"(mbar), "r"(n) : "memory")

#define MMA8(tmem, a0, a1, bd, IDESC, en) do { \
    asm volatile("{ .reg .pred p; setp.ne.u32 p, %5, 0; " \
        "tcgen05.mma.cta_group::1.kind::f16 [%0], %1, %2, %3, {%4,%4,%4,%4}, p; }" \
        :: "r"(tmem), "l"(a0), "l"(bd), "r"(IDESC), "r"(0u), "r"(en) : "memory"); \
    asm volatile("{ .reg .pred p; setp.ne.u32 p, %5, 0; " \
        "tcgen05.mma.cta_group::1.kind::f16 [%0], %1, %2, %3, {%4,%4,%4,%4}, p; }" \
        :: "r"((tmem) + 256), "l"(a1), "l"(bd), "r"(IDESC), "r"(0u), "r"(en) : "memory"); \
} while(0)

__device__ __forceinline__ u32 sm2u32(const void* p) {
    u32 a;
    asm("{ .reg .u64 t; cvta.to.shared.u64 t, %1; cvt.u32.u64 %0, t; }" : "=r"(a) : "l"(p));
    return a;
}

__device__ __forceinline__ u32 swz(u32 off) { return off ^ ((off >> 3) & 0x70); }

extern "C" __global__ void initt() {
    u64 i = (u64)blockIdx.x * 256 + threadIdx.x;
    const u16 T[9] = {0xBC00,0xBA00,0xB800,0xB400,0,0x3400,0x3800,0x3A00,0x3C00};
    if (i < 33554432ull) {
        u32 m = (u32)(i >> 12), k = (u32)(i & 4095);
        GX[i] = T[(k*131u + m*7u) % 9u];
    }
    if (i < 16777216ull) {
        u32 n = (u32)(i >> 12), k = (u32)(i & 4095);
        GW[i] = T[(k*17u + n*3u) % 7u + 1u];
    }
}

extern "C" __global__ void init7() {
    u64 i = (u64)blockIdx.x * 256 + threadIdx.x;
    const u16 T[9] = {0xBC00,0xBA00,0xB800,0xB400,0,0x3400,0x3800,0x3A00,0x3C00};
    if (i < 33554432ull) {
        u32 m = (u32)(i >> 12), k = (u32)(i & 4095);
        u64 boff = ((u64)((m >> 7) * 64u + (k >> 6))) * 16384ull
                 + (u64)swz((m & 127u) * 128u + (k & 63u) * 2u);
        GX[boff >> 1] = T[(k*131u + m*7u) % 9u];
    }
    if (i < 16777216ull) {
        u32 n = (u32)(i >> 12), k = (u32)(i & 4095);
        u64 boff = ((u64)((n >> 7) * 64u + (k >> 6))) * 16384ull
                 + (u64)swz((n & 127u) * 128u + (k & 63u) * 2u);
        GW[boff >> 1] = T[(k*17u + n*3u) % 7u + 1u];
    }
}

extern "C" __global__ void wtinit() {
    u64 i = (u64)blockIdx.x * 256 + threadIdx.x;
    if (i < 8388608ull) GTQW[i] = (int)((i * 37ull) & 255ull);
    if (i < 262144ull) {
        GTAM[i] = (float)((u32)(i * 13ull) % 31u + 1u) * 0.03125f;
        u32 o = (u32)(i >> 6), r = (u32)(i & 63);
        float lb = (float)((int)((o*3u + r*7u) % 17u) - 8) * 0.015625f;
        float la = (float)((int)((o*5u + r*11u) % 19u) - 9) * 0.015625f;
        u16 hb, ha;
        asm("cvt.rn.f16.f32 %0, %1;" : "=h"(hb) : "f"(lb));
        asm("cvt.rn.f16.f32 %0, %1;" : "=h"(ha) : "f"(la));
        GLB[i] = hb;
        GLAT[i] = ha;
    }
}

__device__ __forceinline__ void ld_sub(u32 dst, const char* src, int tid, int iters) {
#pragma unroll
    for (int r = 0; r < 8; r++) {
        if (r >= iters) break;
        int i = tid + r * 256; int row = i >> 3, c = i & 7;
        u32 off = (u32)(row * 128 + ((c * 16) ^ ((row & 7) << 4)));
        asm volatile("cp.async.cg.shared.global.L2::256B [%0], [%1], 16;"
                     :: "r"(dst + off), "l"(src + (u64)row * 8192 + c * 16));
    }
}

// ---------------- gemm5 (single M-tile backstop, row-major operands) ----------------
__device__ __forceinline__ void ld_stage(u32 sA, u32 sB, const char* xb,
                                         const char* wb, int tid) {
#pragma unroll
    for (int r = 0; r < 4; r++) {
        int i = tid + r * 256; int row = i >> 3, c = i & 7;
        u32 off = (u32)(row * 128 + ((c * 16) ^ ((row & 7) << 4)));
        asm volatile("cp.async.cg.shared.global.L2::256B [%0], [%1], 16;"
                     :: "r"(sA + off), "l"(xb + (u64)row * 8192 + c * 16));
    }
#pragma unroll
    for (int r = 0; r < 8; r++) {
        int i = tid + r * 256; int row = i >> 3, c = i & 7;
        u32 off = (u32)(row * 128 + ((c * 16) ^ ((row & 7) << 4)));
        asm volatile("cp.async.cg.shared.global.L2::256B [%0], [%1], 16;"
                     :: "r"(sB + off), "l"(wb + (u64)row * 8192 + c * 16));
    }
}

extern "C" __global__ void __launch_bounds__(256, 1)
gemm5(const char* __restrict__ X, const char* __restrict__ W,
      float* __restrict__ out) {
    extern __shared__ char sm[];
    u32 base = (sm2u32(sm) + 1023) & ~1023u;
    const u32 tptr = base;
    const u32 mb = base + 16;
    const u32 st0 = base + 1024;
    const int tid = threadIdx.x, wid = tid >> 5, lid = tid & 31;

    if (wid == 0)
        asm volatile("tcgen05.alloc.cta_group::1.sync.aligned.shared::cta.b32 [%0], %1;"
                     :: "r"(tptr), "r"(256u) : "memory");
    if (tid == 0) {
#pragma unroll
        for (int s = 0; s < 4; s++)
            asm volatile("mbarrier.init.shared.b64 [%0], %1;"
                         :: "r"(mb + s * 8), "r"(1u) : "memory");
    }
    __syncthreads();
    u32 tmem; asm volatile("ld.shared.b32 %0,[%1];" : "=r"(tmem) : "r"(tptr));

    const u64 DBASE = (2ull << 61) | (1ull << 46) | (64ull << 32) | (1ull << 16);
    const u32 IDESC = (1u << 4) | (32u << 17) | (8u << 24);

#pragma unroll 1
    for (int t = blockIdx.x; t < 1024; t += gridDim.x) {
        const int mBase = (t >> 4) * 128, nBase = (t & 15) * 256;
        const char* xt = X + (u64)mBase * 8192;
        const char* wt = W + (u64)nBase * 8192;

#pragma unroll
        for (int p = 0; p < 4; p++) {
            u32 sA = st0 + p * 49152;
            ld_stage(sA, sA + 16384, xt + p * 128, wt + p * 128, tid);
            asm volatile("cp.async.commit_group;" ::: "memory");
        }

#pragma unroll 1
        for (int kt = 0; kt < 64; kt++) {
            const int s = kt & 3;
            const u32 sA = st0 + s * 49152, sB = sA + 16384;
            asm volatile("cp.async.wait_group 3;" ::: "memory");
            __syncthreads();

            if (wid == 0) {
                u32 ep;
                asm volatile("{ .reg .pred p; elect.sync _|p, 0xFFFFFFFF; selp.b32 %0,1,0,p; }"
                             : "=r"(ep));
                if (ep) {
                    asm volatile("fence.proxy.async.shared::cta;" ::: "memory");
                    u64 ad = DBASE | ((u64)(sA >> 4) & 0x3FFF);
                    u64 bd = DBASE | ((u64)(sB >> 4) & 0x3FFF);
#pragma unroll
                    for (int q = 0; q < 4; q++) {
                        u32 en = (kt > 0 || q > 0) ? 1u : 0u;
                        asm volatile("{ .reg .pred p; setp.ne.u32 p, %5, 0; "
                            "tcgen05.mma.cta_group::1.kind::f16 [%0], %1, %2, %3, {%4,%4,%4,%4}, p; }"
                            :: "r"(tmem), "l"(ad + q * 2), "l"(bd + q * 2),
                               "r"(IDESC), "r"(0u), "r"(en) : "memory");
                    }
                    asm volatile("tcgen05.commit.cta_group::1.mbarrier::arrive::one.shared::cluster.b64 [%0];"
                                 :: "r"(mb + s * 8) : "memory");
                }
            }

            if (kt + 4 < 64) {
                u32 ph = (u32)((kt >> 2) & 1);
                MWAIT(mb + s * 8, ph);
                ld_stage(sA, sB, xt + (kt + 4) * 128, wt + (kt + 4) * 128, tid);
            }
            asm volatile("cp.async.commit_group;" ::: "memory");
        }

        MWAIT(mb + 24, 1u);
        asm volatile("tcgen05.fence::after_thread_sync;" ::: "memory");

        if (wid < 4) {
            float* dst = out + (u64)(mBase + wid * 32 + lid) * 4096 + nBase;
#pragma unroll
            for (int ch = 0; ch < 8; ch++) {
                u32 rr[32];
                LDTM32(rr, tmem + ch * 32);
                asm volatile("tcgen05.wait::ld.sync.aligned;" ::: "memory");
#pragma unroll
                for (int j = 0; j < 8; j++)
                    asm volatile("st.global.cs.v4.b32 [%0], {%1,%2,%3,%4};"
                                 :: "l"(dst + ch * 32 + j * 4),
                                    "r"(rr[4 * j]), "r"(rr[4 * j + 1]),
                                    "r"(rr[4 * j + 2]), "r"(rr[4 * j + 3]) : "memory");
            }
            asm volatile("tcgen05.fence::before_thread_sync;" ::: "memory");
        }
        __syncthreads();
    }

    __syncthreads();
    if (wid == 0) {
        asm volatile("tcgen05.relinquish_alloc_permit.cta_group::1.sync.aligned;");
        asm volatile("tcgen05.dealloc.cta_group::1.sync.aligned.b32 %0, %1;"
                     :: "r"(tmem), "r"(256u));
    }
}

// ---------------- gemm5c: 2 M-tiles, decoupled cp.async (row-major) ----------------
extern "C" __global__ void __launch_bounds__(256, 1)
gemm5c(const char* __restrict__ X, const char* __restrict__ W,
       float* __restrict__ out) {
    extern __shared__ char sm[];
    u32 base = (sm2u32(sm) + 1023) & ~1023u;
    const u32 tptr = base;
    const u32 mb = base + 16;
    const u32 st0 = base + 1024;
    const int tid = threadIdx.x, wid = tid >> 5, lid = tid & 31;

    if (wid == 0)
        asm volatile("tcgen05.alloc.cta_group::1.sync.aligned.shared::cta.b32 [%0], %1;"
                     :: "r"(tptr), "r"(512u) : "memory");
    if (tid == 0) {
#pragma unroll
        for (int s = 0; s < 3; s++)
            asm volatile("mbarrier.init.shared.b64 [%0], %1;"
                         :: "r"(mb + s * 8), "r"(1u) : "memory");
    }
    __syncthreads();
    u32 tmem; asm volatile("ld.shared.b32 %0,[%1];" : "=r"(tmem) : "r"(tptr));

    const u64 DBASE = (2ull << 61) | (1ull << 46) | (64ull << 32) | (1ull << 16);
    const u32 IDESC = (1u << 4) | (32u << 17) | (8u << 24);

    int bp1 = 0, bp2 = 0;

#pragma unroll 1
    for (int t = blockIdx.x; t < 512; t += gridDim.x) {
        const int mBase = (t >> 4) * 256, nBase = (t & 15) * 256;
        const char* x0 = X + (u64)mBase * 8192;
        const char* x1 = x0 + 1048576;
        const char* wt = W + (u64)nBase * 8192;

#pragma unroll
        for (int p = 0; p < 2; p++) {
            u32 sA0 = st0 + p * 65536;
            ld_sub(sA0,         x0 + p * 128, tid, 4);
            ld_sub(sA0 + 16384, x1 + p * 128, tid, 4);
            ld_sub(sA0 + 32768, wt + p * 128, tid, 8);
            asm volatile("cp.async.commit_group;" ::: "memory");
        }

#pragma unroll 1
        for (int kt = 0; kt < 64; kt++) {
            const int kdiv = kt / 3;
            const int s = kt - kdiv * 3;
            const u32 sA0 = st0 + s * 65536, sA1 = sA0 + 16384, sB = sA0 + 32768;
            asm volatile("cp.async.wait_group 1;" ::: "memory");
            __syncthreads();

            if (wid == 0) {
                u32 ep;
                asm volatile("{ .reg .pred p; elect.sync _|p, 0xFFFFFFFF; selp.b32 %0,1,0,p; }"
                             : "=r"(ep));
                if (ep) {
                    asm volatile("fence.proxy.async.shared::cta;" ::: "memory");
                    u64 a0 = DBASE | ((u64)(sA0 >> 4) & 0x3FFF);
                    u64 a1 = DBASE | ((u64)(sA1 >> 4) & 0x3FFF);
                    u64 bd = DBASE | ((u64)(sB >> 4) & 0x3FFF);
#pragma unroll
                    for (int q = 0; q < 4; q++) {
                        u32 en = (kt > 0 || q > 0) ? 1u : 0u;
                        MMA8(tmem, a0 + q * 2, a1 + q * 2, bd + q * 2, IDESC, en);
                    }
                    asm volatile("tcgen05.commit.cta_group::1.mbarrier::arrive::one.shared::cluster.b64 [%0];"
                                 :: "r"(mb + s * 8) : "memory");
                }
            }

            if (kt + 2 < 64) {
                const int sd = (kt + 2) - ((kt + 2) / 3) * 3;
                const u32 dA0 = st0 + sd * 65536;
                if (kt >= 1) {
                    const int kp = kt - 1;
                    const int kdv = kp / 3;
                    const int sp = kp - kdv * 3;
                    int bps = (sp == 0) ? 0 : ((sp == 1) ? bp1 : bp2);
                    u32 ph = (u32)(bps ^ (kdv & 1));
                    MWAIT(mb + sp * 8, ph);
                }
                ld_sub(dA0,         x0 + (kt + 2) * 128, tid, 4);
                ld_sub(dA0 + 16384, x1 + (kt + 2) * 128, tid, 4);
                ld_sub(dA0 + 32768, wt + (kt + 2) * 128, tid, 8);
            }
            asm volatile("cp.async.commit_group;" ::: "memory");
        }

        MWAIT(mb, 1u);
        asm volatile("tcgen05.fence::after_thread_sync;" ::: "memory");

        {
            const int half = wid >> 2, wr = wid & 3;
            float* dst = out + (u64)(mBase + half * 128 + wr * 32 + lid) * 4096 + nBase;
            const u32 tm = tmem + half * 256;
#pragma unroll
            for (int ch = 0; ch < 8; ch++) {
                u32 rr[32];
                LDTM32(rr, tm + ch * 32);
                asm volatile("tcgen05.wait::ld.sync.aligned;" ::: "memory");
#pragma unroll
                for (int j = 0; j < 8; j++)
                    asm volatile("st.global.cs.v4.b32 [%0], {%1,%2,%3,%4};"
                                 :: "l"(dst + ch * 32 + j * 4),
                                    "r"(rr[4 * j]), "r"(rr[4 * j + 1]),
                                    "r"(rr[4 * j + 2]), "r"(rr[4 * j + 3]) : "memory");
            }
            asm volatile("tcgen05.fence::before_thread_sync;" ::: "memory");
        }
        __syncthreads();
        bp1 ^= 1; bp2 ^= 1;
    }

    __syncthreads();
    if (wid == 0) {
        asm volatile("tcgen05.relinquish_alloc_permit.cta_group::1.sync.aligned;");
        asm volatile("tcgen05.dealloc.cta_group::1.sync.aligned.b32 %0, %1;"
                     :: "r"(tmem), "r"(512u));
    }
}

// ---------------- gemm7: bulk-copy pipeline, TILED operands (PROVEN R13) ----------
extern "C" __global__ void __launch_bounds__(256, 1)
gemm7(const char* __restrict__ X, const char* __restrict__ W,
      float* __restrict__ out) {
    extern __shared__ char sm[];
    u32 base = (sm2u32(sm) + 1023) & ~1023u;
    const u32 tptr = base;
    const u32 mbc = base + 16;
    const u32 mbf = base + 48;
    const u32 st0 = base + 1024;
    const int tid = threadIdx.x, wid = tid >> 5, lid = tid & 31;

    if (wid == 0)
        asm volatile("tcgen05.alloc.cta_group::1.sync.aligned.shared::cta.b32 [%0], %1;"
                     :: "r"(tptr), "r"(512u) : "memory");
    if (tid == 0) {
#pragma unroll
        for (int s = 0; s < 3; s++) {
            asm volatile("mbarrier.init.shared.b64 [%0], %1;"
                         :: "r"(mbc + s * 8), "r"(1u) : "memory");
            asm volatile("mbarrier.init.shared.b64 [%0], %1;"
                         :: "r"(mbf + s * 8), "r"(1u) : "memory");
        }
    }
    __syncthreads();
    u32 tmem; asm volatile("ld.shared.b32 %0,[%1];" : "=r"(tmem) : "r"(tptr));

    const u64 DBASE = (2ull << 61) | (1ull << 46) | (64ull << 32) | (1ull << 16);
    const u32 IDESC = (1u << 4) | (32u << 17) | (8u << 24);

    int pf0 = 0, pf1 = 0, pf2 = 0;
    int pc0 = 0, pc1 = 0, pc2 = 0;

#pragma unroll 1
    for (int t = blockIdx.x; t < 512; t += gridDim.x) {
        const int mBase = (t >> 4) * 256, nBase = (t & 15) * 256;
        const u64 mt0 = (u64)((t >> 4) * 2) * 64;
        const u64 nt0 = (u64)((t & 15) * 2) * 64;

        if (wid == 0) {
            u32 ep;
            asm volatile("{ .reg .pred p; elect.sync _|p, 0xFFFFFFFF; selp.b32 %0,1,0,p; }"
                         : "=r"(ep));
            if (ep) {
#pragma unroll
                for (int p = 0; p < 2; p++) {
                    u32 sl = st0 + p * 65536;
                    EXPECT_TX(mbf + p * 8, 65536u);
                    BULK(sl,          X + (mt0 + p) * 16384ull,        16384u, mbf + p * 8);
                    BULK(sl + 16384,  X + (mt0 + 64 + p) * 16384ull,   16384u, mbf + p * 8);
                    BULK(sl + 32768,  W + (nt0 + p) * 16384ull,        16384u, mbf + p * 8);
                    BULK(sl + 49152,  W + (nt0 + 64 + p) * 16384ull,   16384u, mbf + p * 8);
                }
#pragma unroll 1
                for (int kt = 0; kt < 64; kt++) {
                    const int kdiv = kt / 3;
                    const int s = kt - kdiv * 3;
                    const u32 sA0 = st0 + s * 65536, sA1 = sA0 + 16384, sB = sA0 + 32768;
                    u32 ph;
                    if (s == 0) { ph = (u32)pf0; pf0 ^= 1; }
                    else if (s == 1) { ph = (u32)pf1; pf1 ^= 1; }
                    else { ph = (u32)pf2; pf2 ^= 1; }
                    MWAIT(mbf + s * 8, ph);

                    u64 a0 = DBASE | ((u64)(sA0 >> 4) & 0x3FFF);
                    u64 a1 = DBASE | ((u64)(sA1 >> 4) & 0x3FFF);
                    u64 bd = DBASE | ((u64)(sB >> 4) & 0x3FFF);
#pragma unroll
                    for (int q = 0; q < 4; q++) {
                        u32 en = (kt > 0 || q > 0) ? 1u : 0u;
                        MMA8(tmem, a0 + q * 2, a1 + q * 2, bd + q * 2, IDESC, en);
                    }
                    asm volatile("tcgen05.commit.cta_group::1.mbarrier::arrive::one.shared::cluster.b64 [%0];"
                                 :: "r"(mbc + s * 8) : "memory");

                    if (kt >= 1) {
                        const int sp = (kt - 1) - ((kt - 1) / 3) * 3;
                        u32 p2;
                        if (sp == 0) { p2 = (u32)pc0; pc0 ^= 1; }
                        else if (sp == 1) { p2 = (u32)pc1; pc1 ^= 1; }
                        else { p2 = (u32)pc2; pc2 ^= 1; }
                        MWAIT(mbc + sp * 8, p2);
                    }

                    if (kt + 2 < 64) {
                        const int sd = (kt + 2) - ((kt + 2) / 3) * 3;
                        const u32 dA0 = st0 + sd * 65536;
                        const u64 kk = (u64)(kt + 2);
                        EXPECT_TX(mbf + sd * 8, 65536u);
                        BULK(dA0,          X + (mt0 + kk) * 16384ull,      16384u, mbf + sd * 8);
                        BULK(dA0 + 16384,  X + (mt0 + 64 + kk) * 16384ull, 16384u, mbf + sd * 8);
                        BULK(dA0 + 32768,  W + (nt0 + kk) * 16384ull,      16384u, mbf + sd * 8);
                        BULK(dA0 + 49152,  W + (nt0 + 64 + kk) * 16384ull, 16384u, mbf + sd * 8);
                    }
                }
                { u32 p2 = (u32)pc0; pc0 ^= 1; MWAIT(mbc, p2); }
            }
        }

        __syncthreads();
        asm volatile("tcgen05.fence::after_thread_sync;" ::: "memory");

        {
            const int half = wid >> 2, wr = wid & 3;
            float* dst = out + (u64)(mBase + half * 128 + wr * 32 + lid) * 4096 + nBase;
            const u32 tm = tmem + half * 256;
#pragma unroll
            for (int ch = 0; ch < 8; ch++) {
                u32 rr[32];
                LDTM32(rr, tm + ch * 32);
                asm volatile("tcgen05.wait::ld.sync.aligned;" ::: "memory");
#pragma unroll
                for (int j = 0; j < 8; j++)
                    asm volatile("st.global.cs.v4.b32 [%0], {%1,%2,%3,%4};"
                                 :: "l"(dst + ch * 32 + j * 4),
                                    "r"(rr[4 * j]), "r"(rr[4 * j + 1]),
                                    "r"(rr[4 * j + 2]), "r"(rr[4 * j + 3]) : "memory");
            }
            asm volatile("tcgen05.fence::before_thread_sync;" ::: "memory");
        }
        __syncthreads();
    }

    __syncthreads();
    if (wid == 0) {
        asm volatile("tcgen05.relinquish_alloc_permit.cta_group::1.sync.aligned;");
        asm volatile("tcgen05.dealloc.cta_group::1.sync.aligned.b32 %0, %1;"
                     :: "r"(tmem), "r"(512u));
    }
}

// ---------------- gemm7b: gemm7 + earlier load issue + prologue prefetch ----------
// Per-iter order: [wait commit(kt-1); issue loads(kt+2)] -> wait full(kt) -> MMA(kt).
// At tile end, after the drain, issue the NEXT tile's prologue (slots 0,1)
// before the epilogue so loads overlap the TMEM readout. Phase audit:
// commits consumed 63 in-loop + 1 drain = 64 produced; fulls 2+1+61 = 64.
extern "C" __global__ void __launch_bounds__(256, 1)
gemm7b(const char* __restrict__ X, const char* __restrict__ W,
       float* __restrict__ out) {
    extern __shared__ char sm[];
    u32 base = (sm2u32(sm) + 1023) & ~1023u;
    const u32 tptr = base;
    const u32 mbc = base + 16;
    const u32 mbf = base + 48;
    const u32 st0 = base + 1024;
    const int tid = threadIdx.x, wid = tid >> 5, lid = tid & 31;

    if (wid == 0)
        asm volatile("tcgen05.alloc.cta_group::1.sync.aligned.shared::cta.b32 [%0], %1;"
                     :: "r"(tptr), "r"(512u) : "memory");
    if (tid == 0) {
#pragma unroll
        for (int s = 0; s < 3; s++) {
            asm volatile("mbarrier.init.shared.b64 [%0], %1;"
                         :: "r"(mbc + s * 8), "r"(1u) : "memory");
            asm volatile("mbarrier.init.shared.b64 [%0], %1;"
                         :: "r"(mbf + s * 8), "r"(1u) : "memory");
        }
    }
    __syncthreads();
    u32 tmem; asm volatile("ld.shared.b32 %0,[%1];" : "=r"(tmem) : "r"(tptr));

    const u64 DBASE = (2ull << 61) | (1ull << 46) | (64ull << 32) | (1ull << 16);
    const u32 IDESC = (1u << 4) | (32u << 17) | (8u << 24);

    int pf0 = 0, pf1 = 0, pf2 = 0;
    int pc0 = 0, pc1 = 0, pc2 = 0;
    int did_prol = 0;   // per-thread; the elected lane is stable across iters

#pragma unroll 1
    for (int t = blockIdx.x; t < 512; t += gridDim.x) {
        const int mBase = (t >> 4) * 256, nBase = (t & 15) * 256;
        const u64 mt0 = (u64)((t >> 4) * 2) * 64;
        const u64 nt0 = (u64)((t & 15) * 2) * 64;

        if (wid == 0) {
            u32 ep;
            asm volatile("{ .reg .pred p; elect.sync _|p, 0xFFFFFFFF; selp.b32 %0,1,0,p; }"
                         : "=r"(ep));
            if (ep) {
                if (!did_prol) {
                    did_prol = 1;
#pragma unroll
                    for (int p = 0; p < 2; p++) {
                        u32 sl = st0 + p * 65536;
                        EXPECT_TX(mbf + p * 8, 65536u);
                        BULK(sl,          X + (mt0 + p) * 16384ull,        16384u, mbf + p * 8);
                        BULK(sl + 16384,  X + (mt0 + 64 + p) * 16384ull,   16384u, mbf + p * 8);
                        BULK(sl + 32768,  W + (nt0 + p) * 16384ull,        16384u, mbf + p * 8);
                        BULK(sl + 49152,  W + (nt0 + 64 + p) * 16384ull,   16384u, mbf + p * 8);
                    }
                }
#pragma unroll 1
                for (int kt = 0; kt < 64; kt++) {
                    const int s = kt - (kt / 3) * 3;
                    const u32 sA0 = st0 + s * 65536, sA1 = sA0 + 16384, sB = sA0 + 32768;

                    // ---- early loads: wait commit(kt-1), issue loads(kt+2) ----
                    if (kt == 0) {
                        // slot 2 is free (previous tile fully drained)
                        u32 dA0 = st0 + 2 * 65536;
                        EXPECT_TX(mbf + 16, 65536u);
                        BULK(dA0,          X + (mt0 + 2) * 16384ull,      16384u, mbf + 16);
                        BULK(dA0 + 16384,  X + (mt0 + 64 + 2) * 16384ull, 16384u, mbf + 16);
                        BULK(dA0 + 32768,  W + (nt0 + 2) * 16384ull,      16384u, mbf + 16);
                        BULK(dA0 + 49152,  W + (nt0 + 64 + 2) * 16384ull, 16384u, mbf + 16);
                    } else {
                        const int sp = (kt - 1) - ((kt - 1) / 3) * 3;
                        u32 p2;
                        if (sp == 0) { p2 = (u32)pc0; pc0 ^= 1; }
                        else if (sp == 1) { p2 = (u32)pc1; pc1 ^= 1; }
                        else { p2 = (u32)pc2; pc2 ^= 1; }
                        MWAIT(mbc + sp * 8, p2);
                        if (kt + 2 < 64) {
                            const u32 dA0 = st0 + sp * 65536;   // sd == sp
                            const u64 kk = (u64)(kt + 2);
                            EXPECT_TX(mbf + sp * 8, 65536u);
                            BULK(dA0,          X + (mt0 + kk) * 16384ull,      16384u, mbf + sp * 8);
                            BULK(dA0 + 16384,  X + (mt0 + 64 + kk) * 16384ull, 16384u, mbf + sp * 8);
                            BULK(dA0 + 32768,  W + (nt0 + kk) * 16384ull,      16384u, mbf + sp * 8);
                            BULK(dA0 + 49152,  W + (nt0 + 64 + kk) * 16384ull, 16384u, mbf + sp * 8);
                        }
                    }

                    // ---- compute ----
                    u32 ph;
                    if (s == 0) { ph = (u32)pf0; pf0 ^= 1; }
                    else if (s == 1) { ph = (u32)pf1; pf1 ^= 1; }
                    else { ph = (u32)pf2; pf2 ^= 1; }
                    MWAIT(mbf + s * 8, ph);

                    u64 a0 = DBASE | ((u64)(sA0 >> 4) & 0x3FFF);
                    u64 a1 = DBASE | ((u64)(sA1 >> 4) & 0x3FFF);
                    u64 bd = DBASE | ((u64)(sB >> 4) & 0x3FFF);
#pragma unroll
                    for (int q = 0; q < 4; q++) {
                        u32 en = (kt > 0 || q > 0) ? 1u : 0u;
                        MMA8(tmem, a0 + q * 2, a1 + q * 2, bd + q * 2, IDESC, en);
                    }
                    asm volatile("tcgen05.commit.cta_group::1.mbarrier::arrive::one.shared::cluster.b64 [%0];"
                                 :: "r"(mbc + s * 8) : "memory");
                }
                // final drain: commit(63), slot 0
                { u32 p2 = (u32)pc0; pc0 ^= 1; MWAIT(mbc, p2); }

                // prologue prefetch for NEXT tile (slots 0,1) — overlaps epilogue
                {
                    const int tn = t + (int)gridDim.x;
                    if (tn < 512) {
                        const u64 nmt0 = (u64)((tn >> 4) * 2) * 64;
                        const u64 nnt0 = (u64)((tn & 15) * 2) * 64;
#pragma unroll
                        for (int p = 0; p < 2; p++) {
                            u32 sl = st0 + p * 65536;
                            EXPECT_TX(mbf + p * 8, 65536u);
                            BULK(sl,          X + (nmt0 + p) * 16384ull,        16384u, mbf + p * 8);
                            BULK(sl + 16384,  X + (nmt0 + 64 + p) * 16384ull,   16384u, mbf + p * 8);
                            BULK(sl + 32768,  W + (nnt0 + p) * 16384ull,        16384u, mbf + p * 8);
                            BULK(sl + 49152,  W + (nnt0 + 64 + p) * 16384ull,   16384u, mbf + p * 8);
                        }
                    }
                }
            }
        }

        __syncthreads();
        asm volatile("tcgen05.fence::after_thread_sync;" ::: "memory");

        {
            const int half = wid >> 2, wr = wid & 3;
            float* dst = out + (u64)(mBase + half * 128 + wr * 32 + lid) * 4096 + nBase;
            const u32 tm = tmem + half * 256;
#pragma unroll
            for (int ch = 0; ch < 8; ch++) {
                u32 rr[32];
                LDTM32(rr, tm + ch * 32);
                asm volatile("tcgen05.wait::ld.sync.aligned;" ::: "memory");
#pragma unroll
                for (int j = 0; j < 8; j++)
                    asm volatile("st.global.cs.v4.b32 [%0], {%1,%2,%3,%4};"
                                 :: "l"(dst + ch * 32 + j * 4),
                                    "r"(rr[4 * j]), "r"(rr[4 * j + 1]),
                                    "r"(rr[4 * j + 2]), "r"(rr[4 * j + 3]) : "memory");
            }
            asm volatile("tcgen05.fence::before_thread_sync;" ::: "memory");
        }
        __syncthreads();   // gates next tile's MMAs behind epilogue (TMEM reuse)
    }

    __syncthreads();
    if (wid == 0) {
        asm volatile("tcgen05.relinquish_alloc_permit.cta_group::1.sync.aligned;");
        asm volatile("tcgen05.dealloc.cta_group::1.sync.aligned.b32 %0, %1;"
                     :: "r"(tmem), "r"(512u));
    }
}

// ---------------- wbuild: fused LoRA GEMM + NF4 dequant (row-major or tiled) ------
extern "C" __global__ void __launch_bounds__(256, 1)
wbuild(const int* __restrict__ qw, const float* __restrict__ am,
       const u16* __restrict__ lb, const u16* __restrict__ lat,
       u16* __restrict__ w, int tiled) {
    extern __shared__ char sm[];
    u32 base = (sm2u32(sm) + 1023) & ~1023u;
    const u32 tptr = base;
    const u32 mb = base + 16;
    const u32 sa = base + 1024;
    const u32 sb = sa + 16384;
    const int tid = threadIdx.x, wid = tid >> 5, lid = tid & 31;
    const int ti = blockIdx.x;
    const int o0 = (ti >> 4) * 128, i0 = (ti & 15) * 256;

    if (wid == 0)
        asm volatile("tcgen05.alloc.cta_group::1.sync.aligned.shared::cta.b32 [%0], %1;"
                     :: "r"(tptr), "r"(256u) : "memory");
    if (tid == 0)
        asm volatile("mbarrier.init.shared.b64 [%0], %1;" :: "r"(mb), "r"(1u) : "memory");
    __syncthreads();
    u32 tmem; asm volatile("ld.shared.b32 %0,[%1];" : "=r"(tmem) : "r"(tptr));

#pragma unroll
    for (int r = 0; r < 4; r++) {
        int i = tid + r * 256; int row = i >> 3, c = i & 7;
        u32 off = (u32)(row * 128 + ((c * 16) ^ ((row & 7) << 4)));
        asm volatile("cp.async.cg.shared.global [%0], [%1], 16;"
                     :: "r"(sa + off), "l"((const char*)lb + (u64)(o0 + row) * 128 + c * 16));
    }
#pragma unroll
    for (int r = 0; r < 8; r++) {
        int i = tid + r * 256; int row = i >> 3, c = i & 7;
        u32 off = (u32)(row * 128 + ((c * 16) ^ ((row & 7) << 4)));
        asm volatile("cp.async.cg.shared.global [%0], [%1], 16;"
                     :: "r"(sb + off), "l"((const char*)lat + (u64)(i0 + row) * 128 + c * 16));
    }
    asm volatile("cp.async.commit_group;" ::: "memory");
    asm volatile("cp.async.wait_group 0;" ::: "memory");
    __syncthreads();

    const u64 DBASE = (2ull << 61) | (1ull << 46) | (64ull << 32) | (1ull << 16);
    const u32 IDESC = (1u << 4) | (32u << 17) | (8u << 24);

    if (wid == 0) {
        u32 ep;
        asm volatile("{ .reg .pred p; elect.sync _|p, 0xFFFFFFFF; selp.b32 %0,1,0,p; }"
                     : "=r"(ep));
        if (ep) {
            asm volatile("fence.proxy.async.shared::cta;" ::: "memory");
            u64 ad = DBASE | ((u64)(sa >> 4) & 0x3FFF);
            u64 bd = DBASE | ((u64)(sb >> 4) & 0x3FFF);
#pragma unroll
            for (int q = 0; q < 4; q++) {
                u32 en = (q > 0) ? 1u : 0u;
                asm volatile("{ .reg .pred p; setp.ne.u32 p, %5, 0; "
                    "tcgen05.mma.cta_group::1.kind::f16 [%0], %1, %2, %3, {%4,%4,%4,%4}, p; }"
                    :: "r"(tmem), "l"(ad + q * 2), "l"(bd + q * 2),
                       "r"(IDESC), "r"(0u), "r"(en) : "memory");
            }
            asm volatile("tcgen05.commit.cta_group::1.mbarrier::arrive::one.shared::cluster.b64 [%0];"
                         :: "r"(mb) : "memory");
        }
    }
    __syncthreads();
    MWAIT(mb, 0u);
    asm volatile("tcgen05.fence::after_thread_sync;" ::: "memory");

    const int half = wid >> 2, wr = wid & 3;
    const int o = o0 + wr * 32 + lid;
#pragma unroll
    for (int c4 = 0; c4 < 4; c4++) {
        u32 rr[32];
        LDTM32(rr, tmem + half * 128 + c4 * 32);
        asm volatile("tcgen05.wait::ld.sync.aligned;" ::: "memory");
        const int ib = i0 + half * 128 + c4 * 32;
        const u64 k = (u64)o * 4096 + (u64)ib;
        const float a = am[k >> 6];
        const int4* qp = (const int4*)qw + (k >> 3);
        u32 ov[16];
#pragma unroll
        for (int u = 0; u < 4; u++) {
            int4 qv = qp[u];
            int e[8] = {qv.x & 15, (qv.x >> 4) & 15, qv.y & 15, (qv.y >> 4) & 15,
                        qv.z & 15, (qv.z >> 4) & 15, qv.w & 15, (qv.w >> 4) & 15};
#pragma unroll
            for (int j = 0; j < 4; j++) {
                union { u32 u_; float f_; } c0, c1;
                c0.u_ = rr[u * 8 + 2 * j];
                c1.u_ = rr[u * 8 + 2 * j + 1];
                float w0 = NF4D[e[2 * j]] * a + c0.f_;
                float w1 = NF4D[e[2 * j + 1]] * a + c1.f_;
                asm("cvt.rn.f16x2.f32 %0, %1, %2;" : "=r"(ov[u * 4 + j]) : "f"(w1), "f"(w0));
            }
        }
        if (!tiled) {
            char* wp = (char*)w + k * 2;
#pragma unroll
            for (int j = 0; j < 4; j++)
                asm volatile("st.global.cs.v4.b32 [%0], {%1,%2,%3,%4};"
                             :: "l"(wp + j * 16), "r"(ov[4 * j]), "r"(ov[4 * j + 1]),
                                "r"(ov[4 * j + 2]), "r"(ov[4 * j + 3]) : "memory");
        } else {
            const u64 tbase = ((u64)((o >> 7) * 64 + (ib >> 6))) * 16384ull;
            const u32 rowoff = (u32)((o & 127) * 128 + (ib & 63) * 2);
#pragma unroll
            for (int j = 0; j < 4; j++) {
                u32 off = rowoff + (u32)(j * 16);
                off = off ^ ((off >> 3) & 0x70);
                asm volatile("st.global.cs.v4.b32 [%0], {%1,%2,%3,%4};"
                             :: "l"((char*)w + tbase + off),
                                "r"(ov[4 * j]), "r"(ov[4 * j + 1]),
                                "r"(ov[4 * j + 2]), "r"(ov[4 * j + 3]) : "memory");
            }
        }
    }
    asm volatile("tcgen05.fence::before_thread_sync;" ::: "memory");
    __syncthreads();
    if (wid == 0) {
        asm volatile("tcgen05.relinquish_alloc_permit.cta_group::1.sync.aligned;");
        asm volatile("tcgen05.dealloc.cta_group::1.sync.aligned.b32 %0, %1;"
                     :: "r"(tmem), "r"(256u));
    }
}
)NVSRC";

// --- driver/nvrtc plumbing ---
typedef int (*nvrtcCreateProgram_t)(void**, const char*, const char*, int,
                                    const char* const*, const char* const*);
typedef int (*nvrtcCompileProgram_t)(void*, int, const char* const*);
typedef int (*nvrtcGetCUBINSize_t)(void*, size_t*);
typedef int (*nvrtcGetCUBIN_t)(void*, char*);
typedef int (*cuInit_t)(unsigned);
typedef int (*cuDevicePrimaryCtxRetain_t)(void**, int);
typedef int (*cuCtxSetCurrent_t)(void*);
typedef int (*cuModuleLoadDataEx_t)(void**, const void*, unsigned, int*, void**);
typedef int (*cuModuleGetFunction_t)(void**, void*, const char*);
typedef int (*cuModuleGetGlobal_t)(unsigned long long*, size_t*, void*, const char*);
typedef int (*cuFuncSetAttribute_t)(void*, int, int);
typedef int (*cuLaunchKernel_t)(void*, unsigned, unsigned, unsigned,
                                unsigned, unsigned, unsigned,
                                unsigned, void*, void**, void**);
typedef int (*cuCtxSynchronize_t)(void);
typedef int (*cuMemcpyDtoH_t)(void*, unsigned long long, size_t);

#if defined(CUDA_API_PER_THREAD_DEFAULT_STREAM) || defined(__CUDA_API_PER_THREAD_DEFAULT_STREAM)
#define DRV_STREAM ((void*)0x2)
#else
#define DRV_STREAM ((void*)0x1)
#endif

static bool g_ok_gemm = false, g_ok_wb = false;
static int g_mode = 0;  // 4 = tiled bulk (7b/7), 1 = row-major (5c/5), 0 = host
static cuLaunchKernel_t p_cuLaunchKernel = nullptr;
static void* g_fn_gemm = nullptr;
static void* g_fn_wbuild = nullptr;
static unsigned long long g_gx = 0, g_gw = 0, g_glb = 0, g_glat = 0;
constexpr int SMEM5 = 198656;
constexpr int SMEMW = 51200;

static float h2f(uint16_t h) {
    uint32_t s = (h >> 15) & 1, e = (h >> 10) & 31, m = h & 1023;
    uint32_t f;
    if (e == 0) {
        if (m == 0) f = s << 31;
        else {
            e = 127 - 15 + 1;
            while (!(m & 1024)) { m <<= 1; e--; }
            m &= 1023;
            f = (s << 31) | (e << 23) | (m << 13);
        }
    } else if (e == 31) f = (s << 31) | 0x7F800000 | (m << 13);
    else f = (s << 31) | ((e - 15 + 127) << 23) | (m << 13);
    float r; memcpy(&r, &f, 4); return r;
}

static bool try_init_tcgen05() {
    void* hcu = dlopen("libcuda.so.1", RTLD_NOW | RTLD_GLOBAL);
    if (!hcu) hcu = dlopen("libcuda.so", RTLD_NOW | RTLD_GLOBAL);
    if (!hcu) return false;
    void* hnv = dlopen("libnvrtc.so.13", RTLD_NOW | RTLD_GLOBAL);
    if (!hnv) hnv = dlopen("libnvrtc.so", RTLD_NOW | RTLD_GLOBAL);
    if (!hnv) hnv = dlopen("libnvrtc.so.12", RTLD_NOW | RTLD_GLOBAL);
    if (!hnv) return false;

    auto nCreate  = (nvrtcCreateProgram_t)dlsym(hnv, "nvrtcCreateProgram");
    auto nCompile = (nvrtcCompileProgram_t)dlsym(hnv, "nvrtcCompileProgram");
    auto nCbSize  = (nvrtcGetCUBINSize_t)dlsym(hnv, "nvrtcGetCUBINSize");
    auto nCb      = (nvrtcGetCUBIN_t)dlsym(hnv, "nvrtcGetCUBIN");
    auto cInit    = (cuInit_t)dlsym(hcu, "cuInit");
    auto cRetain  = (cuDevicePrimaryCtxRetain_t)dlsym(hcu, "cuDevicePrimaryCtxRetain");
    auto cSetCur  = (cuCtxSetCurrent_t)dlsym(hcu, "cuCtxSetCurrent");
    auto cModLoad = (cuModuleLoadDataEx_t)dlsym(hcu, "cuModuleLoadDataEx");
    auto cGetFn   = (cuModuleGetFunction_t)dlsym(hcu, "cuModuleGetFunction");
    auto cGetGlb  = (cuModuleGetGlobal_t)dlsym(hcu, "cuModuleGetGlobal_v2");
    auto cSetAttr = (cuFuncSetAttribute_t)dlsym(hcu, "cuFuncSetAttribute");
    auto cLaunch  = (cuLaunchKernel_t)dlsym(hcu, "cuLaunchKernel");
    auto cSync    = (cuCtxSynchronize_t)dlsym(hcu, "cuCtxSynchronize");
    auto cD2H     = (cuMemcpyDtoH_t)dlsym(hcu, "cuMemcpyDtoH_v2");
    if (!nCreate || !nCompile || !nCbSize || !nCb || !cInit || !cRetain ||
        !cSetCur || !cModLoad || !cGetFn || !cGetGlb || !cSetAttr ||
        !cLaunch || !cSync || !cD2H)
        return false;

    if (cInit(0)) return false;
    void* ctx = nullptr;
    if (cRetain(&ctx, 0)) return false;
    if (cSetCur(ctx)) return false;

    void* prog = nullptr;
    if (nCreate(&prog, NVRTC_SRC, "gemm7b.cu", 0, nullptr, nullptr)) return false;
    const char* opts[] = {"--gpu-architecture=sm_103a"};
    if (nCompile(prog, 1, opts)) return false;
    size_t cbsz = 0;
    if (nCbSize(prog, &cbsz) || cbsz == 0) return false;
    static char* cubin = new char[cbsz];
    if (nCb(prog, cubin)) return false;

    void* mod = nullptr;
    if (cModLoad(&mod, cubin, 0, nullptr, nullptr)) return false;
    void *fG5 = nullptr, *fG5c = nullptr, *fG7 = nullptr, *fG7b = nullptr;
    void *fInit = nullptr, *fInit7 = nullptr, *fWb = nullptr, *fWti = nullptr;
    if (cGetFn(&fG5, mod, "gemm5")) return false;
    if (cGetFn(&fG5c, mod, "gemm5c")) return false;
    if (cGetFn(&fG7, mod, "gemm7")) return false;
    if (cGetFn(&fG7b, mod, "gemm7b")) return false;
    if (cGetFn(&fInit, mod, "initt")) return false;
    if (cGetFn(&fInit7, mod, "init7")) return false;
    if (cGetFn(&fWb, mod, "wbuild")) return false;
    if (cGetFn(&fWti, mod, "wtinit")) return false;
    unsigned long long gx = 0, gw = 0, gout = 0, glb = 0, glat = 0,
                       gtqw = 0, gtam = 0;
    size_t sz;
    if (cGetGlb(&gx, &sz, mod, "GX")) return false;
    if (cGetGlb(&gw, &sz, mod, "GW")) return false;
    if (cGetGlb(&gout, &sz, mod, "GOUT")) return false;
    if (cGetGlb(&glb, &sz, mod, "GLB")) return false;
    if (cGetGlb(&glat, &sz, mod, "GLAT")) return false;
    if (cGetGlb(&gtqw, &sz, mod, "GTQW")) return false;
    if (cGetGlb(&gtam, &sz, mod, "GTAM")) return false;
    if (cSetAttr(fG5, 8, SMEM5)) return false;
    if (cSetAttr(fG5c, 8, SMEM5)) return false;
    if (cSetAttr(fG7, 8, SMEM5)) return false;
    if (cSetAttr(fG7b, 8, SMEM5)) return false;
    if (cSetAttr(fWb, 8, SMEMW)) return false;

    p_cuLaunchKernel = cLaunch;
    g_gx = gx; g_gw = gw; g_glb = glb; g_glat = glat;

    static float row[OUT_F];
    const int ms4[4] = {0, 97, 4095, 8191};
    auto check_out = [&](unsigned long long gout_) -> bool {
        for (int ri = 0; ri < 4; ri++) {
            int m = ms4[ri];
            if (cD2H(row, gout_ + (unsigned long long)m * OUT_F * 4, OUT_F * 4))
                return false;
            for (int n = 0; n < OUT_F; n++) {
                float ref = 0.0f;
                for (int k = 0; k < IN_F; k++) {
                    int av = (k * 131 + m * 7) % 9 - 4;
                    int bv = (k * 17 + n * 3) % 7 - 3;
                    ref += (av * 0.25f) * (bv * 0.25f);
                }
                if (fabsf(row[n] - ref) > 0.01f) return false;
            }
        }
        return true;
    };

    // ---- tiled init ----
    bool tiled_ready =
        (cLaunch(fInit7, 131072, 1, 1, 256, 1, 1, 0, DRV_STREAM, nullptr, nullptr) == 0 &&
         cSync() == 0);

    // ---- TEST gemm7b, then gemm7 ----
    bool g7bok = false, g7ok = false;
    if (tiled_ready) {
        unsigned long long px = gx, pw = gw, po = gout;
        void* args[3] = {&px, &pw, &po};
        if (cLaunch(fG7b, 148, 1, 1, 256, 1, 1, SMEM5, DRV_STREAM, args, nullptr) == 0 &&
            cSync() == 0 && check_out(gout))
            g7bok = true;
        if (!g7bok) {
            if (cLaunch(fG7, 148, 1, 1, 256, 1, 1, SMEM5, DRV_STREAM, args, nullptr) == 0 &&
                cSync() == 0 && check_out(gout))
                g7ok = true;
        }
    }

    // ---- wbuild math + tiled layout tests ----
    bool wb_math_ok = false, wb_tiled_ok = false;
    if (cLaunch(fWti, 32768, 1, 1, 256, 1, 1, 0, DRV_STREAM, nullptr, nullptr) == 0 &&
        cSync() == 0) {
        auto wref = [&](int o, int i) -> float {
            uint64_t k = (uint64_t)o * 4096 + i;
            int qv = (int)(((k >> 1) * 37ull) & 255ull);
            int nib = (k & 1) ? (qv >> 4) & 15 : qv & 15;
            float a = (float)(((uint32_t)((k >> 6) * 13ull)) % 31u + 1u) * 0.03125f;
            float lora = 0.0f;
            for (int r = 0; r < 64; r++) {
                float lb = (float)((int)(((uint32_t)o * 3u + r * 7u) % 17u) - 8) * 0.015625f;
                float la = (float)((int)(((uint32_t)i * 5u + r * 11u) % 19u) - 9) * 0.015625f;
                lora += lb * la;
            }
            return NF4H[nib] * a + lora;
        };
        auto run_wb = [&](int tiled) -> bool {
            unsigned long long pq = gtqw, pa = gtam, pl = glb, pt = glat, pw2 = gw;
            int tf = tiled;
            void* args[6] = {&pq, &pa, &pl, &pt, &pw2, &tf};
            if (cLaunch(fWb, 512, 1, 1, 256, 1, 1, SMEMW, DRV_STREAM, args, nullptr))
                return false;
            return cSync() == 0;
        };
        const int os[4] = {0, 1, 255, 4095};
        static uint16_t wrow[IN_F];
        if (run_wb(0)) {
            bool ok = true;
            for (int oi = 0; oi < 4 && ok; oi++) {
                int o = os[oi];
                if (cD2H(wrow, gw + (unsigned long long)o * IN_F * 2, IN_F * 2)) { ok = false; break; }
                for (int i = 0; i < IN_F; i++)
                    if (fabsf(h2f(wrow[i]) - wref(o, i)) > 0.01f) { ok = false; break; }
            }
            wb_math_ok = ok;
        }
        if (wb_math_ok && (g7bok || g7ok) && run_wb(1)) {
            static uint16_t* hw = new uint16_t[16777216];
            if (cD2H(hw, gw, (size_t)16777216 * 2) == 0) {
                bool ok = true;
                for (int oi = 0; oi < 4 && ok; oi++) {
                    int o = os[oi];
                    for (int i = 0; i < IN_F; i++) {
                        uint32_t off = (uint32_t)((o & 127) * 128 + (i & 63) * 2);
                        off = off ^ ((off >> 3) & 0x70);
                        uint64_t boff = ((uint64_t)((o >> 7) * 64 + (i >> 6))) * 16384ull + off;
                        if (fabsf(h2f(hw[boff >> 1]) - wref(o, i)) > 0.01f) { ok = false; break; }
                    }
                }
                wb_tiled_ok = ok;
            }
        }
    }

    if ((g7bok || g7ok) && wb_tiled_ok) {
        g_fn_gemm = g7bok ? fG7b : fG7;
        g_ok_gemm = true; g_mode = 4;
        g_fn_wbuild = fWb; g_ok_wb = true;
        return true;
    }
    // row-major ladder
    if (cLaunch(fInit, 131072, 1, 1, 256, 1, 1, 0, DRV_STREAM, nullptr, nullptr) ||
        cSync())
        return false;
    {
        unsigned long long px = gx, pw = gw, po = gout;
        void* args[3] = {&px, &pw, &po};
        if (cLaunch(fG5c, 148, 1, 1, 256, 1, 1, SMEM5, DRV_STREAM, args, nullptr) == 0 &&
            cSync() == 0 && check_out(gout)) {
            g_fn_gemm = fG5c; g_ok_gemm = true; g_mode = 1;
        } else if (cLaunch(fG5, 148, 1, 1, 256, 1, 1, SMEM5, DRV_STREAM, args, nullptr) == 0 &&
                   cSync() == 0 && check_out(gout)) {
            g_fn_gemm = fG5; g_ok_gemm = true; g_mode = 1;
        }
    }
    if (g_ok_gemm && wb_math_ok) { g_fn_wbuild = fWb; g_ok_wb = true; }
    return g_ok_gemm;
}

__attribute__((constructor))
static void _init_drv() {
    try_init_tcgen05();
}

// ---------------------------------------------------------------------------
extern "C" void kernel_launch(void* const* d_in, const int* in_sizes, int n_in,
                              void* d_out, int out_size) {
    const float* x  = (const float*)d_in[0];
    const int*   qw = (const int*)d_in[1];
    const float* am = (const float*)d_in[2];
    const float* lA = (const float*)d_in[3];
    const float* lB = (const float*)d_in[4];
    float*       out = (float*)d_out;

    (void)in_sizes; (void)n_in; (void)out_size;

    if (g_ok_gemm) {
        __half* xh = (__half*)(uintptr_t)g_gx;
        __half* wh = (__half*)(uintptr_t)g_gw;

        if (g_mode >= 4)
            convert_x_tiled_kernel<<<(M_ROWS * IN_F / 8) / 256, 256>>>(x, (char*)xh);
        else
            convert_x_kernel<<<(M_ROWS * IN_F / 8) / 256, 256>>>(x, xh);

        if (g_ok_wb) {
            cvt_lb_kernel<<<256, 256>>>(lB, (__half*)(uintptr_t)g_glb);
            cvt_lat_kernel<<<64, 256>>>(lA, (__half*)(uintptr_t)g_glat);
            unsigned long long pq = (unsigned long long)(uintptr_t)qw;
            unsigned long long pa = (unsigned long long)(uintptr_t)am;
            unsigned long long pl = g_glb, pt = g_glat, pw = g_gw;
            int tf = (g_mode >= 4) ? 1 : 0;
            void* args[6] = {&pq, &pa, &pl, &pt, &pw, &tf};
            p_cuLaunchKernel(g_fn_wbuild, 512, 1, 1, 256, 1, 1, SMEMW,
                             DRV_STREAM, args, nullptr);
        } else {
            build_weff_kernel<<<dim3(IN_F / 128, OUT_F / 64), 256>>>(qw, am, lA, lB, wh);
        }

        unsigned long long px = g_gx, pw2 = g_gw;
        void* po = (void*)out;
        void* args[3] = {&px, &pw2, &po};
        p_cuLaunchKernel(g_fn_gemm, 148, 1, 1, 256, 1, 1, SMEM5,
                         DRV_STREAM, args, nullptr);
    } else {
        __half* xh; __half* wh;
        cudaGetSymbolAddress((void**)&xh, g_Xh);
        cudaGetSymbolAddress((void**)&wh, g_Wh);
        convert_x_kernel<<<(M_ROWS * IN_F / 8) / 256, 256>>>(x, xh);
        build_weff_kernel<<<dim3(IN_F / 128, OUT_F / 64), 256>>>(qw, am, lA, lB, wh);
        cudaFuncSetAttribute(gemm_f16_kernel,
                             cudaFuncAttributeMaxDynamicSharedMemorySize, SMEM_TOTAL);
        gemm_f16_kernel<<<148, 512, SMEM_TOTAL>>>(xh, wh, out);
    }
}

// round 16
// speedup vs baseline: 1.0908x; 1.0908x over previous
#include <cuda_runtime.h>
#include <cuda_fp16.h>
#include <cstdint>
#include <cstdio>
#include <cstring>
#include <cmath>
#include <dlfcn.h>

#define IN_F   4096
#define OUT_F  4096
#define M_ROWS 8192

// Host-module fp16 scratch (used by the host fallback path).
__device__ __half g_Xh[(size_t)M_ROWS * IN_F];
__device__ __half g_Wh[(size_t)OUT_F * IN_F];

__constant__ float NF4[16] = {
    -1.0f, -0.6961928009986877f, -0.5250730514526367f, -0.39491748809814453f,
    -0.28444138169288635f, -0.18477343022823334f, -0.09105003625154495f, 0.0f,
    0.07958029955625534f, 0.16093020141124725f, 0.24611230194568634f,
    0.33791524171829224f, 0.4407098889350891f, 0.5626170039176941f,
    0.7229568362236023f, 1.0f
};

static const float NF4H[16] = {
    -1.0f, -0.6961928009986877f, -0.5250730514526367f, -0.39491748809814453f,
    -0.28444138169288635f, -0.18477343022823334f, -0.09105003625154495f, 0.0f,
    0.07958029955625534f, 0.16093020141124725f, 0.24611230194568634f,
    0.33791524171829224f, 0.4407098889350891f, 0.5626170039176941f,
    0.7229568362236023f, 1.0f
};

__device__ __forceinline__ uint32_t smem_u32(const void* p) {
    uint32_t a;
    asm("{ .reg .u64 t; cvta.to.shared.u64 t, %1; cvt.u32.u64 %0, t; }" : "=r"(a) : "l"(p));
    return a;
}

// ---------------------------------------------------------------------------
// Kernel A: convert x (fp32) -> dst (fp16) row-major. 8 elems/thread.
// ---------------------------------------------------------------------------
__global__ void convert_x_kernel(const float* __restrict__ x, __half* __restrict__ dst) {
    size_t i = ((size_t)blockIdx.x * 256 + threadIdx.x) * 8;
    float4 v0 = *(const float4*)(x + i);
    float4 v1 = *(const float4*)(x + i + 4);
    __half2 h0 = __floats2half2_rn(v0.x, v0.y);
    __half2 h1 = __floats2half2_rn(v0.z, v0.w);
    __half2 h2 = __floats2half2_rn(v1.x, v1.y);
    __half2 h3 = __floats2half2_rn(v1.z, v1.w);
    uint4 o;
    o.x = *(uint32_t*)&h0; o.y = *(uint32_t*)&h1;
    o.z = *(uint32_t*)&h2; o.w = *(uint32_t*)&h3;
    *(uint4*)&dst[i] = o;
}

// Kernel A': convert x -> TILED layout: tile (m>>7, k>>6) contiguous 16KB SW128.
__global__ void convert_x_tiled_kernel(const float* __restrict__ x, char* __restrict__ dst) {
    size_t i = ((size_t)blockIdx.x * 256 + threadIdx.x) * 8;
    float4 v0 = *(const float4*)(x + i);
    float4 v1 = *(const float4*)(x + i + 4);
    __half2 h0 = __floats2half2_rn(v0.x, v0.y);
    __half2 h1 = __floats2half2_rn(v0.z, v0.w);
    __half2 h2 = __floats2half2_rn(v1.x, v1.y);
    __half2 h3 = __floats2half2_rn(v1.z, v1.w);
    uint4 o;
    o.x = *(uint32_t*)&h0; o.y = *(uint32_t*)&h1;
    o.z = *(uint32_t*)&h2; o.w = *(uint32_t*)&h3;
    const uint32_t m = (uint32_t)(i >> 12), k = (uint32_t)(i & 4095);
    uint32_t off = (m & 127) * 128 + (k & 63) * 2;
    off = off ^ ((off >> 3) & 0x70);
    const size_t boff = ((size_t)((m >> 7) * 64 + (k >> 6))) * 16384 + off;
    *(uint4*)(dst + boff) = o;
}

// lora_B [4096][64] fp32 -> fp16 same layout
__global__ void cvt_lb_kernel(const float* __restrict__ lB, __half* __restrict__ lb) {
    size_t i = ((size_t)blockIdx.x * 256 + threadIdx.x) * 4;
    float4 v = *(const float4*)(lB + i);
    __half h[4] = {__float2half_rn(v.x), __float2half_rn(v.y),
                   __float2half_rn(v.z), __float2half_rn(v.w)};
    *(uint2*)&lb[i] = *(uint2*)h;
}

// lora_A [64][4096] fp32 -> lat [4096][64] fp16 (transpose)
__global__ void cvt_lat_kernel(const float* __restrict__ lA, __half* __restrict__ lat) {
    __shared__ float s[64][65];
    const int tid = threadIdx.x;
    const int i0 = blockIdx.x * 64;
    for (int idx = tid; idx < 4096; idx += 256) {
        int r = idx >> 6, ii = idx & 63;
        s[r][ii] = lA[r * IN_F + i0 + ii];
    }
    __syncthreads();
    int ii = tid >> 2, rs = (tid & 3) * 16;
    __half h[16];
#pragma unroll
    for (int j = 0; j < 16; j++) h[j] = __float2half_rn(s[rs + j][ii]);
    uint4* dst = (uint4*)&lat[(size_t)(i0 + ii) * 64 + rs];
    dst[0] = *(uint4*)&h[0];
    dst[1] = *(uint4*)&h[8];
}

// ---------------------------------------------------------------------------
// Host fallback: W_eff = NF4 dequant * absmax + lora_B @ lora_A  (fp16, row-major)
// ---------------------------------------------------------------------------
__global__ void build_weff_kernel(const int* __restrict__ qweight,
                                  const float* __restrict__ absmax,
                                  const float* __restrict__ lA,
                                  const float* __restrict__ lB,
                                  __half* __restrict__ dst) {
    __shared__ float Bsh[64][64];
    __shared__ float Ash[64][128];

    const int tid = threadIdx.x;
    const int o0 = blockIdx.y * 64;
    const int i0 = blockIdx.x * 128;

    for (int t = tid; t < 64 * 64; t += 256) {
        int o = t >> 6, r = t & 63;
        Bsh[r][o] = lB[(o0 + o) * 64 + r];
    }
    for (int t = tid; t < 64 * 128; t += 256) {
        int r = t >> 7, c = t & 127;
        Ash[r][c] = lA[r * IN_F + i0 + c];
    }
    __syncthreads();

    const int oo0 = (tid >> 4) * 4;
    const int ii0 = (tid & 15) * 8;

    float acc[4][8];
#pragma unroll
    for (int a = 0; a < 4; a++)
#pragma unroll
        for (int b = 0; b < 8; b++) acc[a][b] = 0.0f;

#pragma unroll 4
    for (int r = 0; r < 64; r++) {
        float4 a0 = *(const float4*)&Ash[r][ii0];
        float4 a1 = *(const float4*)&Ash[r][ii0 + 4];
#pragma unroll
        for (int oo = 0; oo < 4; oo++) {
            float bv = Bsh[r][oo0 + oo];
            acc[oo][0] += bv * a0.x; acc[oo][1] += bv * a0.y;
            acc[oo][2] += bv * a0.z; acc[oo][3] += bv * a0.w;
            acc[oo][4] += bv * a1.x; acc[oo][5] += bv * a1.y;
            acc[oo][6] += bv * a1.z; acc[oo][7] += bv * a1.w;
        }
    }

#pragma unroll
    for (int oo = 0; oo < 4; oo++) {
        const int o = o0 + oo0 + oo;
        const size_t k = (size_t)o * IN_F + i0 + ii0;
        const int4 qv = ((const int4*)qweight)[k >> 3];
        const float am = absmax[k >> 6];

        float w[8];
        w[0] = NF4[qv.x & 15];  w[1] = NF4[(qv.x >> 4) & 15];
        w[2] = NF4[qv.y & 15];  w[3] = NF4[(qv.y >> 4) & 15];
        w[4] = NF4[qv.z & 15];  w[5] = NF4[(qv.z >> 4) & 15];
        w[6] = NF4[qv.w & 15];  w[7] = NF4[(qv.w >> 4) & 15];

        __half2 h0 = __floats2half2_rn(w[0] * am + acc[oo][0], w[1] * am + acc[oo][1]);
        __half2 h1 = __floats2half2_rn(w[2] * am + acc[oo][2], w[3] * am + acc[oo][3]);
        __half2 h2 = __floats2half2_rn(w[4] * am + acc[oo][4], w[5] * am + acc[oo][5]);
        __half2 h3 = __floats2half2_rn(w[6] * am + acc[oo][6], w[7] * am + acc[oo][7]);
        uint4 pk;
        pk.x = *(uint32_t*)&h0; pk.y = *(uint32_t*)&h1;
        pk.z = *(uint32_t*)&h2; pk.w = *(uint32_t*)&h3;
        *(uint4*)&dst[k] = pk;
    }
}

// ---------------------------------------------------------------------------
// Host fallback GEMM (proven 778us): fp16 mma.sync, 512 thr, 4-stage.
// ---------------------------------------------------------------------------
constexpr int BM = 128, BN = 256, BK = 64, S = 4;
constexpr int NT = IN_F / BK;
constexpr int A_BYTES = BM * 128;
constexpr int B_BYTES = BN * 128;
constexpr int STAGE = A_BYTES + B_BYTES;
constexpr int SMEM_TOTAL = 1024 + S * STAGE;
constexpr int TOTAL_TILES = (M_ROWS / BM) * (OUT_F / BN);

__device__ __forceinline__ void mma_f16(float c[4], const uint32_t a[4],
                                        uint32_t b0, uint32_t b1) {
    asm volatile(
        "mma.sync.aligned.m16n8k16.row.col.f32.f16.f16.f32 "
        "{%0,%1,%2,%3}, {%4,%5,%6,%7}, {%8,%9}, {%0,%1,%2,%3};"
        : "+f"(c[0]), "+f"(c[1]), "+f"(c[2]), "+f"(c[3])
        : "r"(a[0]), "r"(a[1]), "r"(a[2]), "r"(a[3]), "r"(b0), "r"(b1));
}

__device__ __forceinline__ void ldsm4(uint32_t& r0, uint32_t& r1,
                                      uint32_t& r2, uint32_t& r3, uint32_t addr) {
    asm volatile("ldmatrix.sync.aligned.m8n8.x4.shared.b16 {%0,%1,%2,%3}, [%4];"
                 : "=r"(r0), "=r"(r1), "=r"(r2), "=r"(r3) : "r"(addr));
}

__device__ __forceinline__ void st_cs_f2(float* p, float a, float b) {
    asm volatile("st.global.cs.v2.f32 [%0], {%1,%2};" :: "l"(p), "f"(a), "f"(b)
                 : "memory");
}

__device__ __forceinline__ void issue_stage(uint32_t sA, uint32_t sB,
                                            const __half* xb, const __half* wb,
                                            int tid) {
#pragma unroll
    for (int r = 0; r < 2; r++) {
        int i = tid + r * 512;
        int row = i >> 3, c = i & 7;
        uint32_t off = (uint32_t)(row * 128 + ((c * 16) ^ ((row & 7) << 4)));
        const __half* src = xb + (size_t)row * IN_F + c * 8;
        asm volatile("cp.async.cg.shared.global.L2::256B [%0], [%1], 16;\n"
                     :: "r"(sA + off), "l"(src));
    }
#pragma unroll
    for (int r = 0; r < 4; r++) {
        int i = tid + r * 512;
        int row = i >> 3, c = i & 7;
        uint32_t off = (uint32_t)(row * 128 + ((c * 16) ^ ((row & 7) << 4)));
        const __half* src = wb + (size_t)row * IN_F + c * 8;
        asm volatile("cp.async.cg.shared.global.L2::256B [%0], [%1], 16;\n"
                     :: "r"(sB + off), "l"(src));
    }
}

__global__ void __launch_bounds__(512, 1)
gemm_f16_kernel(const __half* __restrict__ Xh, const __half* __restrict__ Wh,
                float* __restrict__ out) {
    extern __shared__ char sm[];
    const uint32_t stage0 = (smem_u32(sm) + 1023) & ~1023u;

    const int tid = threadIdx.x;
    const int wid = tid >> 5;
    const int lane = tid & 31;
    const int warp_m = wid & 3;
    const int warp_n = wid >> 2;
    const int g = lane >> 3;
    const int r = lane & 7;

    uint32_t a_rowoff[2], a_xr[2];
    const uint32_t a_kc = (uint32_t)((g >> 1) * 16);
#pragma unroll
    for (int mf = 0; mf < 2; mf++) {
        int row = warp_m * 32 + mf * 16 + (g & 1) * 8 + r;
        a_rowoff[mf] = row * 128;
        a_xr[mf] = (row & 7) << 4;
    }
    uint32_t b_rowoff[4], b_xr[4];
    const uint32_t b_kc = (uint32_t)((g & 1) * 16);
#pragma unroll
    for (int p = 0; p < 4; p++) {
        int row = warp_n * 64 + p * 16 + (g >> 1) * 8 + r;
        b_rowoff[p] = row * 128;
        b_xr[p] = (row & 7) << 4;
    }

    for (int t = blockIdx.x; t < TOTAL_TILES; t += gridDim.x) {
        const int mBase = (t >> 4) * BM;
        const int nBase = (t & 15) * BN;
        const __half* xt = Xh + (size_t)mBase * IN_F;
        const __half* wt = Wh + (size_t)nBase * IN_F;

        float acc[2][8][4];
#pragma unroll
        for (int i = 0; i < 2; i++)
#pragma unroll
            for (int j = 0; j < 8; j++)
#pragma unroll
                for (int l = 0; l < 4; l++) acc[i][j][l] = 0.0f;

#pragma unroll
        for (int p = 0; p < S - 1; p++) {
            uint32_t sA = stage0 + p * STAGE;
            issue_stage(sA, sA + A_BYTES, xt + p * BK, wt + p * BK, tid);
            asm volatile("cp.async.commit_group;\n" ::: "memory");
        }

        for (int kt = 0; kt < NT; kt++) {
            asm volatile("cp.async.wait_group %0;\n" :: "n"(S - 2) : "memory");
            __syncthreads();

            if (kt + S - 1 < NT) {
                const int s2 = (kt + S - 1) % S;
                uint32_t sA = stage0 + s2 * STAGE;
                issue_stage(sA, sA + A_BYTES,
                            xt + (kt + S - 1) * BK, wt + (kt + S - 1) * BK, tid);
            }
            asm volatile("cp.async.commit_group;\n" ::: "memory");

            const uint32_t sA = stage0 + (kt % S) * STAGE;
            const uint32_t sB = sA + A_BYTES;

#pragma unroll
            for (int q = 0; q < 4; q++) {
                uint32_t a[2][4];
#pragma unroll
                for (int mf = 0; mf < 2; mf++)
                    ldsm4(a[mf][0], a[mf][1], a[mf][2], a[mf][3],
                          sA + a_rowoff[mf] + (((q * 32) + a_kc) ^ a_xr[mf]));
                uint32_t b[8][2];
#pragma unroll
                for (int p = 0; p < 4; p++)
                    ldsm4(b[2 * p][0], b[2 * p][1], b[2 * p + 1][0], b[2 * p + 1][1],
                          sB + b_rowoff[p] + (((q * 32) + b_kc) ^ b_xr[p]));
#pragma unroll
                for (int mf = 0; mf < 2; mf++)
#pragma unroll
                    for (int nf = 0; nf < 8; nf++)
                        mma_f16(acc[mf][nf], a[mf], b[nf][0], b[nf][1]);
            }
        }
        asm volatile("cp.async.wait_group 0;\n" ::: "memory");

#pragma unroll
        for (int mf = 0; mf < 2; mf++) {
#pragma unroll
            for (int nf = 0; nf < 8; nf++) {
                const int row = mBase + warp_m * 32 + mf * 16 + (lane >> 2);
                const int col = nBase + warp_n * 64 + nf * 8 + (lane & 3) * 2;
                st_cs_f2(&out[(size_t)row * OUT_F + col],
                         acc[mf][nf][0], acc[mf][nf][1]);
                st_cs_f2(&out[(size_t)(row + 8) * OUT_F + col],
                         acc[mf][nf][2], acc[mf][nf][3]);
            }
        }
        __syncthreads();
    }
}

// ===========================================================================
// NVRTC module: gemm7c (gemm7 loop + tile-boundary prologue prefetch),
// gemm7 (proven R13), gemm5c/5 backstops, wbuild, init kernels.
// ===========================================================================
static const char* NVRTC_SRC = R"NVSRC(
typedef unsigned int u32;
typedef unsigned long long u64;
typedef unsigned short u16;

__device__ __align__(128) u16 GX[33554432];  // X fp16 (row-major OR tiled)
__device__ __align__(128) u16 GW[16777216];  // W fp16 (row-major OR tiled)
__device__ float GOUT[33554432];             // gemm self-test output
__device__ u16 GLB[262144];                  // lora_B fp16 [4096][64]
__device__ u16 GLAT[262144];                 // lora_A^T fp16 [4096][64]
__device__ int GTQW[8388608];                // wbuild self-test qweight
__device__ float GTAM[262144];               // wbuild self-test absmax

__constant__ float NF4D[16] = {
    -1.0f, -0.6961928009986877f, -0.5250730514526367f, -0.39491748809814453f,
    -0.28444138169288635f, -0.18477343022823334f, -0.09105003625154495f, 0.0f,
    0.07958029955625534f, 0.16093020141124725f, 0.24611230194568634f,
    0.33791524171829224f, 0.4407098889350891f, 0.5626170039176941f,
    0.7229568362236023f, 1.0f
};

#define MWAIT(ba, ph) do { u32 _d; \
    asm volatile("{ .reg .pred p; mbarrier.try_wait.parity.acquire.cta.shared::cta.b64 p, [%1], %2; selp.b32 %0,1,0,p; }" \
                 : "=r"(_d) : "r"(ba), "r"(ph) : "memory"); \
    if (!_d) { \
        asm volatile("{ .reg .pred P1; WL%=: mbarrier.try_wait.parity.acquire.cta.shared::cta.b64 P1, [%0], %1, 0x989680; @P1 bra.uni WD%=; bra.uni WL%=; WD%=: }" \
                     :: "r"(ba), "r"(ph) : "memory"); } } while(0)

#define LDTM32(rr, addr) \
    asm volatile("tcgen05.ld.sync.aligned.32x32b.x32.b32 " \
        "{%0,%1,%2,%3,%4,%5,%6,%7,%8,%9,%10,%11,%12,%13,%14,%15," \
        "%16,%17,%18,%19,%20,%21,%22,%23,%24,%25,%26,%27,%28,%29,%30,%31}, [%32];" \
        : "=r"(rr[0]), "=r"(rr[1]), "=r"(rr[2]), "=r"(rr[3]), \
          "=r"(rr[4]), "=r"(rr[5]), "=r"(rr[6]), "=r"(rr[7]), \
          "=r"(rr[8]), "=r"(rr[9]), "=r"(rr[10]), "=r"(rr[11]), \
          "=r"(rr[12]), "=r"(rr[13]), "=r"(rr[14]), "=r"(rr[15]), \
          "=r"(rr[16]), "=r"(rr[17]), "=r"(rr[18]), "=r"(rr[19]), \
          "=r"(rr[20]), "=r"(rr[21]), "=r"(rr[22]), "=r"(rr[23]), \
          "=r"(rr[24]), "=r"(rr[25]), "=r"(rr[26]), "=r"(rr[27]), \
          "=r"(rr[28]), "=r"(rr[29]), "=r"(rr[30]), "=r"(rr[31]) \
        : "r"(addr))

#define BULK(dst, src, sz, mbar) \
    asm volatile("cp.async.bulk.shared::cta.global.mbarrier::complete_tx::bytes " \
                 "[%0], [%1], %2, [%3];" \
                 :: "r"(dst), "l"(src), "r"(sz), "r"(mbar) : "memory")

#define EXPECT_TX(mbar, n) \
    asm volatile("mbarrier.arrive.expect_tx.shared.b64 _, [%0], %1;" \
                 :: "r"(mbar), "r"(n) : "memory")

#define MMA8(tmem, a0, a1, bd, IDESC, en) do { \
    asm volatile("{ .reg .pred p; setp.ne.u32 p, %5, 0; " \
        "tcgen05.mma.cta_group::1.kind::f16 [%0], %1, %2, %3, {%4,%4,%4,%4}, p; }" \
        :: "r"(tmem), "l"(a0), "l"(bd), "r"(IDESC), "r"(0u), "r"(en) : "memory"); \
    asm volatile("{ .reg .pred p; setp.ne.u32 p, %5, 0; " \
        "tcgen05.mma.cta_group::1.kind::f16 [%0], %1, %2, %3, {%4,%4,%4,%4}, p; }" \
        :: "r"((tmem) + 256), "l"(a1), "l"(bd), "r"(IDESC), "r"(0u), "r"(en) : "memory"); \
} while(0)

__device__ __forceinline__ u32 sm2u32(const void* p) {
    u32 a;
    asm("{ .reg .u64 t; cvta.to.shared.u64 t, %1; cvt.u32.u64 %0, t; }" : "=r"(a) : "l"(p));
    return a;
}

__device__ __forceinline__ u32 swz(u32 off) { return off ^ ((off >> 3) & 0x70); }

extern "C" __global__ void initt() {
    u64 i = (u64)blockIdx.x * 256 + threadIdx.x;
    const u16 T[9] = {0xBC00,0xBA00,0xB800,0xB400,0,0x3400,0x3800,0x3A00,0x3C00};
    if (i < 33554432ull) {
        u32 m = (u32)(i >> 12), k = (u32)(i & 4095);
        GX[i] = T[(k*131u + m*7u) % 9u];
    }
    if (i < 16777216ull) {
        u32 n = (u32)(i >> 12), k = (u32)(i & 4095);
        GW[i] = T[(k*17u + n*3u) % 7u + 1u];
    }
}

extern "C" __global__ void init7() {
    u64 i = (u64)blockIdx.x * 256 + threadIdx.x;
    const u16 T[9] = {0xBC00,0xBA00,0xB800,0xB400,0,0x3400,0x3800,0x3A00,0x3C00};
    if (i < 33554432ull) {
        u32 m = (u32)(i >> 12), k = (u32)(i & 4095);
        u64 boff = ((u64)((m >> 7) * 64u + (k >> 6))) * 16384ull
                 + (u64)swz((m & 127u) * 128u + (k & 63u) * 2u);
        GX[boff >> 1] = T[(k*131u + m*7u) % 9u];
    }
    if (i < 16777216ull) {
        u32 n = (u32)(i >> 12), k = (u32)(i & 4095);
        u64 boff = ((u64)((n >> 7) * 64u + (k >> 6))) * 16384ull
                 + (u64)swz((n & 127u) * 128u + (k & 63u) * 2u);
        GW[boff >> 1] = T[(k*17u + n*3u) % 7u + 1u];
    }
}

extern "C" __global__ void wtinit() {
    u64 i = (u64)blockIdx.x * 256 + threadIdx.x;
    if (i < 8388608ull) GTQW[i] = (int)((i * 37ull) & 255ull);
    if (i < 262144ull) {
        GTAM[i] = (float)((u32)(i * 13ull) % 31u + 1u) * 0.03125f;
        u32 o = (u32)(i >> 6), r = (u32)(i & 63);
        float lb = (float)((int)((o*3u + r*7u) % 17u) - 8) * 0.015625f;
        float la = (float)((int)((o*5u + r*11u) % 19u) - 9) * 0.015625f;
        u16 hb, ha;
        asm("cvt.rn.f16.f32 %0, %1;" : "=h"(hb) : "f"(lb));
        asm("cvt.rn.f16.f32 %0, %1;" : "=h"(ha) : "f"(la));
        GLB[i] = hb;
        GLAT[i] = ha;
    }
}

__device__ __forceinline__ void ld_sub(u32 dst, const char* src, int tid, int iters) {
#pragma unroll
    for (int r = 0; r < 8; r++) {
        if (r >= iters) break;
        int i = tid + r * 256; int row = i >> 3, c = i & 7;
        u32 off = (u32)(row * 128 + ((c * 16) ^ ((row & 7) << 4)));
        asm volatile("cp.async.cg.shared.global.L2::256B [%0], [%1], 16;"
                     :: "r"(dst + off), "l"(src + (u64)row * 8192 + c * 16));
    }
}

// ---------------- gemm5 (single M-tile backstop, row-major operands) ----------------
__device__ __forceinline__ void ld_stage(u32 sA, u32 sB, const char* xb,
                                         const char* wb, int tid) {
#pragma unroll
    for (int r = 0; r < 4; r++) {
        int i = tid + r * 256; int row = i >> 3, c = i & 7;
        u32 off = (u32)(row * 128 + ((c * 16) ^ ((row & 7) << 4)));
        asm volatile("cp.async.cg.shared.global.L2::256B [%0], [%1], 16;"
                     :: "r"(sA + off), "l"(xb + (u64)row * 8192 + c * 16));
    }
#pragma unroll
    for (int r = 0; r < 8; r++) {
        int i = tid + r * 256; int row = i >> 3, c = i & 7;
        u32 off = (u32)(row * 128 + ((c * 16) ^ ((row & 7) << 4)));
        asm volatile("cp.async.cg.shared.global.L2::256B [%0], [%1], 16;"
                     :: "r"(sB + off), "l"(wb + (u64)row * 8192 + c * 16));
    }
}

extern "C" __global__ void __launch_bounds__(256, 1)
gemm5(const char* __restrict__ X, const char* __restrict__ W,
      float* __restrict__ out) {
    extern __shared__ char sm[];
    u32 base = (sm2u32(sm) + 1023) & ~1023u;
    const u32 tptr = base;
    const u32 mb = base + 16;
    const u32 st0 = base + 1024;
    const int tid = threadIdx.x, wid = tid >> 5, lid = tid & 31;

    if (wid == 0)
        asm volatile("tcgen05.alloc.cta_group::1.sync.aligned.shared::cta.b32 [%0], %1;"
                     :: "r"(tptr), "r"(256u) : "memory");
    if (tid == 0) {
#pragma unroll
        for (int s = 0; s < 4; s++)
            asm volatile("mbarrier.init.shared.b64 [%0], %1;"
                         :: "r"(mb + s * 8), "r"(1u) : "memory");
    }
    __syncthreads();
    u32 tmem; asm volatile("ld.shared.b32 %0,[%1];" : "=r"(tmem) : "r"(tptr));

    const u64 DBASE = (2ull << 61) | (1ull << 46) | (64ull << 32) | (1ull << 16);
    const u32 IDESC = (1u << 4) | (32u << 17) | (8u << 24);

#pragma unroll 1
    for (int t = blockIdx.x; t < 1024; t += gridDim.x) {
        const int mBase = (t >> 4) * 128, nBase = (t & 15) * 256;
        const char* xt = X + (u64)mBase * 8192;
        const char* wt = W + (u64)nBase * 8192;

#pragma unroll
        for (int p = 0; p < 4; p++) {
            u32 sA = st0 + p * 49152;
            ld_stage(sA, sA + 16384, xt + p * 128, wt + p * 128, tid);
            asm volatile("cp.async.commit_group;" ::: "memory");
        }

#pragma unroll 1
        for (int kt = 0; kt < 64; kt++) {
            const int s = kt & 3;
            const u32 sA = st0 + s * 49152, sB = sA + 16384;
            asm volatile("cp.async.wait_group 3;" ::: "memory");
            __syncthreads();

            if (wid == 0) {
                u32 ep;
                asm volatile("{ .reg .pred p; elect.sync _|p, 0xFFFFFFFF; selp.b32 %0,1,0,p; }"
                             : "=r"(ep));
                if (ep) {
                    asm volatile("fence.proxy.async.shared::cta;" ::: "memory");
                    u64 ad = DBASE | ((u64)(sA >> 4) & 0x3FFF);
                    u64 bd = DBASE | ((u64)(sB >> 4) & 0x3FFF);
#pragma unroll
                    for (int q = 0; q < 4; q++) {
                        u32 en = (kt > 0 || q > 0) ? 1u : 0u;
                        asm volatile("{ .reg .pred p; setp.ne.u32 p, %5, 0; "
                            "tcgen05.mma.cta_group::1.kind::f16 [%0], %1, %2, %3, {%4,%4,%4,%4}, p; }"
                            :: "r"(tmem), "l"(ad + q * 2), "l"(bd + q * 2),
                               "r"(IDESC), "r"(0u), "r"(en) : "memory");
                    }
                    asm volatile("tcgen05.commit.cta_group::1.mbarrier::arrive::one.shared::cluster.b64 [%0];"
                                 :: "r"(mb + s * 8) : "memory");
                }
            }

            if (kt + 4 < 64) {
                u32 ph = (u32)((kt >> 2) & 1);
                MWAIT(mb + s * 8, ph);
                ld_stage(sA, sB, xt + (kt + 4) * 128, wt + (kt + 4) * 128, tid);
            }
            asm volatile("cp.async.commit_group;" ::: "memory");
        }

        MWAIT(mb + 24, 1u);
        asm volatile("tcgen05.fence::after_thread_sync;" ::: "memory");

        if (wid < 4) {
            float* dst = out + (u64)(mBase + wid * 32 + lid) * 4096 + nBase;
#pragma unroll
            for (int ch = 0; ch < 8; ch++) {
                u32 rr[32];
                LDTM32(rr, tmem + ch * 32);
                asm volatile("tcgen05.wait::ld.sync.aligned;" ::: "memory");
#pragma unroll
                for (int j = 0; j < 8; j++)
                    asm volatile("st.global.cs.v4.b32 [%0], {%1,%2,%3,%4};"
                                 :: "l"(dst + ch * 32 + j * 4),
                                    "r"(rr[4 * j]), "r"(rr[4 * j + 1]),
                                    "r"(rr[4 * j + 2]), "r"(rr[4 * j + 3]) : "memory");
            }
            asm volatile("tcgen05.fence::before_thread_sync;" ::: "memory");
        }
        __syncthreads();
    }

    __syncthreads();
    if (wid == 0) {
        asm volatile("tcgen05.relinquish_alloc_permit.cta_group::1.sync.aligned;");
        asm volatile("tcgen05.dealloc.cta_group::1.sync.aligned.b32 %0, %1;"
                     :: "r"(tmem), "r"(256u));
    }
}

// ---------------- gemm5c: 2 M-tiles, decoupled cp.async (row-major) ----------------
extern "C" __global__ void __launch_bounds__(256, 1)
gemm5c(const char* __restrict__ X, const char* __restrict__ W,
       float* __restrict__ out) {
    extern __shared__ char sm[];
    u32 base = (sm2u32(sm) + 1023) & ~1023u;
    const u32 tptr = base;
    const u32 mb = base + 16;
    const u32 st0 = base + 1024;
    const int tid = threadIdx.x, wid = tid >> 5, lid = tid & 31;

    if (wid == 0)
        asm volatile("tcgen05.alloc.cta_group::1.sync.aligned.shared::cta.b32 [%0], %1;"
                     :: "r"(tptr), "r"(512u) : "memory");
    if (tid == 0) {
#pragma unroll
        for (int s = 0; s < 3; s++)
            asm volatile("mbarrier.init.shared.b64 [%0], %1;"
                         :: "r"(mb + s * 8), "r"(1u) : "memory");
    }
    __syncthreads();
    u32 tmem; asm volatile("ld.shared.b32 %0,[%1];" : "=r"(tmem) : "r"(tptr));

    const u64 DBASE = (2ull << 61) | (1ull << 46) | (64ull << 32) | (1ull << 16);
    const u32 IDESC = (1u << 4) | (32u << 17) | (8u << 24);

    int bp1 = 0, bp2 = 0;

#pragma unroll 1
    for (int t = blockIdx.x; t < 512; t += gridDim.x) {
        const int mBase = (t >> 4) * 256, nBase = (t & 15) * 256;
        const char* x0 = X + (u64)mBase * 8192;
        const char* x1 = x0 + 1048576;
        const char* wt = W + (u64)nBase * 8192;

#pragma unroll
        for (int p = 0; p < 2; p++) {
            u32 sA0 = st0 + p * 65536;
            ld_sub(sA0,         x0 + p * 128, tid, 4);
            ld_sub(sA0 + 16384, x1 + p * 128, tid, 4);
            ld_sub(sA0 + 32768, wt + p * 128, tid, 8);
            asm volatile("cp.async.commit_group;" ::: "memory");
        }

#pragma unroll 1
        for (int kt = 0; kt < 64; kt++) {
            const int kdiv = kt / 3;
            const int s = kt - kdiv * 3;
            const u32 sA0 = st0 + s * 65536, sA1 = sA0 + 16384, sB = sA0 + 32768;
            asm volatile("cp.async.wait_group 1;" ::: "memory");
            __syncthreads();

            if (wid == 0) {
                u32 ep;
                asm volatile("{ .reg .pred p; elect.sync _|p, 0xFFFFFFFF; selp.b32 %0,1,0,p; }"
                             : "=r"(ep));
                if (ep) {
                    asm volatile("fence.proxy.async.shared::cta;" ::: "memory");
                    u64 a0 = DBASE | ((u64)(sA0 >> 4) & 0x3FFF);
                    u64 a1 = DBASE | ((u64)(sA1 >> 4) & 0x3FFF);
                    u64 bd = DBASE | ((u64)(sB >> 4) & 0x3FFF);
#pragma unroll
                    for (int q = 0; q < 4; q++) {
                        u32 en = (kt > 0 || q > 0) ? 1u : 0u;
                        MMA8(tmem, a0 + q * 2, a1 + q * 2, bd + q * 2, IDESC, en);
                    }
                    asm volatile("tcgen05.commit.cta_group::1.mbarrier::arrive::one.shared::cluster.b64 [%0];"
                                 :: "r"(mb + s * 8) : "memory");
                }
            }

            if (kt + 2 < 64) {
                const int sd = (kt + 2) - ((kt + 2) / 3) * 3;
                const u32 dA0 = st0 + sd * 65536;
                if (kt >= 1) {
                    const int kp = kt - 1;
                    const int kdv = kp / 3;
                    const int sp = kp - kdv * 3;
                    int bps = (sp == 0) ? 0 : ((sp == 1) ? bp1 : bp2);
                    u32 ph = (u32)(bps ^ (kdv & 1));
                    MWAIT(mb + sp * 8, ph);
                }
                ld_sub(dA0,         x0 + (kt + 2) * 128, tid, 4);
                ld_sub(dA0 + 16384, x1 + (kt + 2) * 128, tid, 4);
                ld_sub(dA0 + 32768, wt + (kt + 2) * 128, tid, 8);
            }
            asm volatile("cp.async.commit_group;" ::: "memory");
        }

        MWAIT(mb, 1u);
        asm volatile("tcgen05.fence::after_thread_sync;" ::: "memory");

        {
            const int half = wid >> 2, wr = wid & 3;
            float* dst = out + (u64)(mBase + half * 128 + wr * 32 + lid) * 4096 + nBase;
            const u32 tm = tmem + half * 256;
#pragma unroll
            for (int ch = 0; ch < 8; ch++) {
                u32 rr[32];
                LDTM32(rr, tm + ch * 32);
                asm volatile("tcgen05.wait::ld.sync.aligned;" ::: "memory");
#pragma unroll
                for (int j = 0; j < 8; j++)
                    asm volatile("st.global.cs.v4.b32 [%0], {%1,%2,%3,%4};"
                                 :: "l"(dst + ch * 32 + j * 4),
                                    "r"(rr[4 * j]), "r"(rr[4 * j + 1]),
                                    "r"(rr[4 * j + 2]), "r"(rr[4 * j + 3]) : "memory");
            }
            asm volatile("tcgen05.fence::before_thread_sync;" ::: "memory");
        }
        __syncthreads();
        bp1 ^= 1; bp2 ^= 1;
    }

    __syncthreads();
    if (wid == 0) {
        asm volatile("tcgen05.relinquish_alloc_permit.cta_group::1.sync.aligned;");
        asm volatile("tcgen05.dealloc.cta_group::1.sync.aligned.b32 %0, %1;"
                     :: "r"(tmem), "r"(512u));
    }
}

// ---------------- gemm7: bulk-copy pipeline, TILED operands (PROVEN R13) ----------
extern "C" __global__ void __launch_bounds__(256, 1)
gemm7(const char* __restrict__ X, const char* __restrict__ W,
      float* __restrict__ out) {
    extern __shared__ char sm[];
    u32 base = (sm2u32(sm) + 1023) & ~1023u;
    const u32 tptr = base;
    const u32 mbc = base + 16;
    const u32 mbf = base + 48;
    const u32 st0 = base + 1024;
    const int tid = threadIdx.x, wid = tid >> 5, lid = tid & 31;

    if (wid == 0)
        asm volatile("tcgen05.alloc.cta_group::1.sync.aligned.shared::cta.b32 [%0], %1;"
                     :: "r"(tptr), "r"(512u) : "memory");
    if (tid == 0) {
#pragma unroll
        for (int s = 0; s < 3; s++) {
            asm volatile("mbarrier.init.shared.b64 [%0], %1;"
                         :: "r"(mbc + s * 8), "r"(1u) : "memory");
            asm volatile("mbarrier.init.shared.b64 [%0], %1;"
                         :: "r"(mbf + s * 8), "r"(1u) : "memory");
        }
    }
    __syncthreads();
    u32 tmem; asm volatile("ld.shared.b32 %0,[%1];" : "=r"(tmem) : "r"(tptr));

    const u64 DBASE = (2ull << 61) | (1ull << 46) | (64ull << 32) | (1ull << 16);
    const u32 IDESC = (1u << 4) | (32u << 17) | (8u << 24);

    int pf0 = 0, pf1 = 0, pf2 = 0;
    int pc0 = 0, pc1 = 0, pc2 = 0;

#pragma unroll 1
    for (int t = blockIdx.x; t < 512; t += gridDim.x) {
        const int mBase = (t >> 4) * 256, nBase = (t & 15) * 256;
        const u64 mt0 = (u64)((t >> 4) * 2) * 64;
        const u64 nt0 = (u64)((t & 15) * 2) * 64;

        if (wid == 0) {
            u32 ep;
            asm volatile("{ .reg .pred p; elect.sync _|p, 0xFFFFFFFF; selp.b32 %0,1,0,p; }"
                         : "=r"(ep));
            if (ep) {
#pragma unroll
                for (int p = 0; p < 2; p++) {
                    u32 sl = st0 + p * 65536;
                    EXPECT_TX(mbf + p * 8, 65536u);
                    BULK(sl,          X + (mt0 + p) * 16384ull,        16384u, mbf + p * 8);
                    BULK(sl + 16384,  X + (mt0 + 64 + p) * 16384ull,   16384u, mbf + p * 8);
                    BULK(sl + 32768,  W + (nt0 + p) * 16384ull,        16384u, mbf + p * 8);
                    BULK(sl + 49152,  W + (nt0 + 64 + p) * 16384ull,   16384u, mbf + p * 8);
                }
#pragma unroll 1
                for (int kt = 0; kt < 64; kt++) {
                    const int kdiv = kt / 3;
                    const int s = kt - kdiv * 3;
                    const u32 sA0 = st0 + s * 65536, sA1 = sA0 + 16384, sB = sA0 + 32768;
                    u32 ph;
                    if (s == 0) { ph = (u32)pf0; pf0 ^= 1; }
                    else if (s == 1) { ph = (u32)pf1; pf1 ^= 1; }
                    else { ph = (u32)pf2; pf2 ^= 1; }
                    MWAIT(mbf + s * 8, ph);

                    u64 a0 = DBASE | ((u64)(sA0 >> 4) & 0x3FFF);
                    u64 a1 = DBASE | ((u64)(sA1 >> 4) & 0x3FFF);
                    u64 bd = DBASE | ((u64)(sB >> 4) & 0x3FFF);
#pragma unroll
                    for (int q = 0; q < 4; q++) {
                        u32 en = (kt > 0 || q > 0) ? 1u : 0u;
                        MMA8(tmem, a0 + q * 2, a1 + q * 2, bd + q * 2, IDESC, en);
                    }
                    asm volatile("tcgen05.commit.cta_group::1.mbarrier::arrive::one.shared::cluster.b64 [%0];"
                                 :: "r"(mbc + s * 8) : "memory");

                    if (kt >= 1) {
                        const int sp = (kt - 1) - ((kt - 1) / 3) * 3;
                        u32 p2;
                        if (sp == 0) { p2 = (u32)pc0; pc0 ^= 1; }
                        else if (sp == 1) { p2 = (u32)pc1; pc1 ^= 1; }
                        else { p2 = (u32)pc2; pc2 ^= 1; }
                        MWAIT(mbc + sp * 8, p2);
                    }

                    if (kt + 2 < 64) {
                        const int sd = (kt + 2) - ((kt + 2) / 3) * 3;
                        const u32 dA0 = st0 + sd * 65536;
                        const u64 kk = (u64)(kt + 2);
                        EXPECT_TX(mbf + sd * 8, 65536u);
                        BULK(dA0,          X + (mt0 + kk) * 16384ull,      16384u, mbf + sd * 8);
                        BULK(dA0 + 16384,  X + (mt0 + 64 + kk) * 16384ull, 16384u, mbf + sd * 8);
                        BULK(dA0 + 32768,  W + (nt0 + kk) * 16384ull,      16384u, mbf + sd * 8);
                        BULK(dA0 + 49152,  W + (nt0 + 64 + kk) * 16384ull, 16384u, mbf + sd * 8);
                    }
                }
                { u32 p2 = (u32)pc0; pc0 ^= 1; MWAIT(mbc, p2); }
            }
        }

        __syncthreads();
        asm volatile("tcgen05.fence::after_thread_sync;" ::: "memory");

        {
            const int half = wid >> 2, wr = wid & 3;
            float* dst = out + (u64)(mBase + half * 128 + wr * 32 + lid) * 4096 + nBase;
            const u32 tm = tmem + half * 256;
#pragma unroll
            for (int ch = 0; ch < 8; ch++) {
                u32 rr[32];
                LDTM32(rr, tm + ch * 32);
                asm volatile("tcgen05.wait::ld.sync.aligned;" ::: "memory");
#pragma unroll
                for (int j = 0; j < 8; j++)
                    asm volatile("st.global.cs.v4.b32 [%0], {%1,%2,%3,%4};"
                                 :: "l"(dst + ch * 32 + j * 4),
                                    "r"(rr[4 * j]), "r"(rr[4 * j + 1]),
                                    "r"(rr[4 * j + 2]), "r"(rr[4 * j + 3]) : "memory");
            }
            asm volatile("tcgen05.fence::before_thread_sync;" ::: "memory");
        }
        __syncthreads();
    }

    __syncthreads();
    if (wid == 0) {
        asm volatile("tcgen05.relinquish_alloc_permit.cta_group::1.sync.aligned;");
        asm volatile("tcgen05.dealloc.cta_group::1.sync.aligned.b32 %0, %1;"
                     :: "r"(tmem), "r"(512u));
    }
}

// ---------------- gemm7c: gemm7 loop VERBATIM + tile-boundary prologue prefetch ----
// In-loop ordering identical to gemm7 (MMA issued before commit-wait, so the
// tensor pipe never drains). Only change: after the final drain, the elected
// thread issues the NEXT tile's prologue (slots 0,1 — provably free) so those
// loads overlap the epilogue. Fulls/tile 62+2=64=consumed; commits 64/64.
extern "C" __global__ void __launch_bounds__(256, 1)
gemm7c(const char* __restrict__ X, const char* __restrict__ W,
       float* __restrict__ out) {
    extern __shared__ char sm[];
    u32 base = (sm2u32(sm) + 1023) & ~1023u;
    const u32 tptr = base;
    const u32 mbc = base + 16;
    const u32 mbf = base + 48;
    const u32 st0 = base + 1024;
    const int tid = threadIdx.x, wid = tid >> 5, lid = tid & 31;

    if (wid == 0)
        asm volatile("tcgen05.alloc.cta_group::1.sync.aligned.shared::cta.b32 [%0], %1;"
                     :: "r"(tptr), "r"(512u) : "memory");
    if (tid == 0) {
#pragma unroll
        for (int s = 0; s < 3; s++) {
            asm volatile("mbarrier.init.shared.b64 [%0], %1;"
                         :: "r"(mbc + s * 8), "r"(1u) : "memory");
            asm volatile("mbarrier.init.shared.b64 [%0], %1;"
                         :: "r"(mbf + s * 8), "r"(1u) : "memory");
        }
    }
    __syncthreads();
    u32 tmem; asm volatile("ld.shared.b32 %0,[%1];" : "=r"(tmem) : "r"(tptr));

    const u64 DBASE = (2ull << 61) | (1ull << 46) | (64ull << 32) | (1ull << 16);
    const u32 IDESC = (1u << 4) | (32u << 17) | (8u << 24);

    int pf0 = 0, pf1 = 0, pf2 = 0;
    int pc0 = 0, pc1 = 0, pc2 = 0;
    int did_prol = 0;   // elected lane is stable across tiles

#pragma unroll 1
    for (int t = blockIdx.x; t < 512; t += gridDim.x) {
        const int mBase = (t >> 4) * 256, nBase = (t & 15) * 256;
        const u64 mt0 = (u64)((t >> 4) * 2) * 64;
        const u64 nt0 = (u64)((t & 15) * 2) * 64;

        if (wid == 0) {
            u32 ep;
            asm volatile("{ .reg .pred p; elect.sync _|p, 0xFFFFFFFF; selp.b32 %0,1,0,p; }"
                         : "=r"(ep));
            if (ep) {
                if (!did_prol) {
                    did_prol = 1;
#pragma unroll
                    for (int p = 0; p < 2; p++) {
                        u32 sl = st0 + p * 65536;
                        EXPECT_TX(mbf + p * 8, 65536u);
                        BULK(sl,          X + (mt0 + p) * 16384ull,        16384u, mbf + p * 8);
                        BULK(sl + 16384,  X + (mt0 + 64 + p) * 16384ull,   16384u, mbf + p * 8);
                        BULK(sl + 32768,  W + (nt0 + p) * 16384ull,        16384u, mbf + p * 8);
                        BULK(sl + 49152,  W + (nt0 + 64 + p) * 16384ull,   16384u, mbf + p * 8);
                    }
                }
#pragma unroll 1
                for (int kt = 0; kt < 64; kt++) {
                    const int kdiv = kt / 3;
                    const int s = kt - kdiv * 3;
                    const u32 sA0 = st0 + s * 65536, sA1 = sA0 + 16384, sB = sA0 + 32768;
                    u32 ph;
                    if (s == 0) { ph = (u32)pf0; pf0 ^= 1; }
                    else if (s == 1) { ph = (u32)pf1; pf1 ^= 1; }
                    else { ph = (u32)pf2; pf2 ^= 1; }
                    MWAIT(mbf + s * 8, ph);

                    u64 a0 = DBASE | ((u64)(sA0 >> 4) & 0x3FFF);
                    u64 a1 = DBASE | ((u64)(sA1 >> 4) & 0x3FFF);
                    u64 bd = DBASE | ((u64)(sB >> 4) & 0x3FFF);
#pragma unroll
                    for (int q = 0; q < 4; q++) {
                        u32 en = (kt > 0 || q > 0) ? 1u : 0u;
                        MMA8(tmem, a0 + q * 2, a1 + q * 2, bd + q * 2, IDESC, en);
                    }
                    asm volatile("tcgen05.commit.cta_group::1.mbarrier::arrive::one.shared::cluster.b64 [%0];"
                                 :: "r"(mbc + s * 8) : "memory");

                    if (kt >= 1) {
                        const int sp = (kt - 1) - ((kt - 1) / 3) * 3;
                        u32 p2;
                        if (sp == 0) { p2 = (u32)pc0; pc0 ^= 1; }
                        else if (sp == 1) { p2 = (u32)pc1; pc1 ^= 1; }
                        else { p2 = (u32)pc2; pc2 ^= 1; }
                        MWAIT(mbc + sp * 8, p2);
                    }

                    if (kt + 2 < 64) {
                        const int sd = (kt + 2) - ((kt + 2) / 3) * 3;
                        const u32 dA0 = st0 + sd * 65536;
                        const u64 kk = (u64)(kt + 2);
                        EXPECT_TX(mbf + sd * 8, 65536u);
                        BULK(dA0,          X + (mt0 + kk) * 16384ull,      16384u, mbf + sd * 8);
                        BULK(dA0 + 16384,  X + (mt0 + 64 + kk) * 16384ull, 16384u, mbf + sd * 8);
                        BULK(dA0 + 32768,  W + (nt0 + kk) * 16384ull,      16384u, mbf + sd * 8);
                        BULK(dA0 + 49152,  W + (nt0 + 64 + kk) * 16384ull, 16384u, mbf + sd * 8);
                    }
                }
                // final drain: commit(63) on slot 0
                { u32 p2 = (u32)pc0; pc0 ^= 1; MWAIT(mbc, p2); }

                // next tile's prologue (slots 0,1 free) — overlaps the epilogue
                {
                    const int tn = t + (int)gridDim.x;
                    if (tn < 512) {
                        const u64 nmt0 = (u64)((tn >> 4) * 2) * 64;
                        const u64 nnt0 = (u64)((tn & 15) * 2) * 64;
#pragma unroll
                        for (int p = 0; p < 2; p++) {
                            u32 sl = st0 + p * 65536;
                            EXPECT_TX(mbf + p * 8, 65536u);
                            BULK(sl,          X + (nmt0 + p) * 16384ull,        16384u, mbf + p * 8);
                            BULK(sl + 16384,  X + (nmt0 + 64 + p) * 16384ull,   16384u, mbf + p * 8);
                            BULK(sl + 32768,  W + (nnt0 + p) * 16384ull,        16384u, mbf + p * 8);
                            BULK(sl + 49152,  W + (nnt0 + 64 + p) * 16384ull,   16384u, mbf + p * 8);
                        }
                    }
                }
            }
        }

        __syncthreads();
        asm volatile("tcgen05.fence::after_thread_sync;" ::: "memory");

        {
            const int half = wid >> 2, wr = wid & 3;
            float* dst = out + (u64)(mBase + half * 128 + wr * 32 + lid) * 4096 + nBase;
            const u32 tm = tmem + half * 256;
#pragma unroll
            for (int ch = 0; ch < 8; ch++) {
                u32 rr[32];
                LDTM32(rr, tm + ch * 32);
                asm volatile("tcgen05.wait::ld.sync.aligned;" ::: "memory");
#pragma unroll
                for (int j = 0; j < 8; j++)
                    asm volatile("st.global.cs.v4.b32 [%0], {%1,%2,%3,%4};"
                                 :: "l"(dst + ch * 32 + j * 4),
                                    "r"(rr[4 * j]), "r"(rr[4 * j + 1]),
                                    "r"(rr[4 * j + 2]), "r"(rr[4 * j + 3]) : "memory");
            }
            asm volatile("tcgen05.fence::before_thread_sync;" ::: "memory");
        }
        __syncthreads();   // gates next tile's MMAs behind epilogue (TMEM reuse)
    }

    __syncthreads();
    if (wid == 0) {
        asm volatile("tcgen05.relinquish_alloc_permit.cta_group::1.sync.aligned;");
        asm volatile("tcgen05.dealloc.cta_group::1.sync.aligned.b32 %0, %1;"
                     :: "r"(tmem), "r"(512u));
    }
}

// ---------------- wbuild: fused LoRA GEMM + NF4 dequant (row-major or tiled) ------
extern "C" __global__ void __launch_bounds__(256, 1)
wbuild(const int* __restrict__ qw, const float* __restrict__ am,
       const u16* __restrict__ lb, const u16* __restrict__ lat,
       u16* __restrict__ w, int tiled) {
    extern __shared__ char sm[];
    u32 base = (sm2u32(sm) + 1023) & ~1023u;
    const u32 tptr = base;
    const u32 mb = base + 16;
    const u32 sa = base + 1024;
    const u32 sb = sa + 16384;
    const int tid = threadIdx.x, wid = tid >> 5, lid = tid & 31;
    const int ti = blockIdx.x;
    const int o0 = (ti >> 4) * 128, i0 = (ti & 15) * 256;

    if (wid == 0)
        asm volatile("tcgen05.alloc.cta_group::1.sync.aligned.shared::cta.b32 [%0], %1;"
                     :: "r"(tptr), "r"(256u) : "memory");
    if (tid == 0)
        asm volatile("mbarrier.init.shared.b64 [%0], %1;" :: "r"(mb), "r"(1u) : "memory");
    __syncthreads();
    u32 tmem; asm volatile("ld.shared.b32 %0,[%1];" : "=r"(tmem) : "r"(tptr));

#pragma unroll
    for (int r = 0; r < 4; r++) {
        int i = tid + r * 256; int row = i >> 3, c = i & 7;
        u32 off = (u32)(row * 128 + ((c * 16) ^ ((row & 7) << 4)));
        asm volatile("cp.async.cg.shared.global [%0], [%1], 16;"
                     :: "r"(sa + off), "l"((const char*)lb + (u64)(o0 + row) * 128 + c * 16));
    }
#pragma unroll
    for (int r = 0; r < 8; r++) {
        int i = tid + r * 256; int row = i >> 3, c = i & 7;
        u32 off = (u32)(row * 128 + ((c * 16) ^ ((row & 7) << 4)));
        asm volatile("cp.async.cg.shared.global [%0], [%1], 16;"
                     :: "r"(sb + off), "l"((const char*)lat + (u64)(i0 + row) * 128 + c * 16));
    }
    asm volatile("cp.async.commit_group;" ::: "memory");
    asm volatile("cp.async.wait_group 0;" ::: "memory");
    __syncthreads();

    const u64 DBASE = (2ull << 61) | (1ull << 46) | (64ull << 32) | (1ull << 16);
    const u32 IDESC = (1u << 4) | (32u << 17) | (8u << 24);

    if (wid == 0) {
        u32 ep;
        asm volatile("{ .reg .pred p; elect.sync _|p, 0xFFFFFFFF; selp.b32 %0,1,0,p; }"
                     : "=r"(ep));
        if (ep) {
            asm volatile("fence.proxy.async.shared::cta;" ::: "memory");
            u64 ad = DBASE | ((u64)(sa >> 4) & 0x3FFF);
            u64 bd = DBASE | ((u64)(sb >> 4) & 0x3FFF);
#pragma unroll
            for (int q = 0; q < 4; q++) {
                u32 en = (q > 0) ? 1u : 0u;
                asm volatile("{ .reg .pred p; setp.ne.u32 p, %5, 0; "
                    "tcgen05.mma.cta_group::1.kind::f16 [%0], %1, %2, %3, {%4,%4,%4,%4}, p; }"
                    :: "r"(tmem), "l"(ad + q * 2), "l"(bd + q * 2),
                       "r"(IDESC), "r"(0u), "r"(en) : "memory");
            }
            asm volatile("tcgen05.commit.cta_group::1.mbarrier::arrive::one.shared::cluster.b64 [%0];"
                         :: "r"(mb) : "memory");
        }
    }
    __syncthreads();
    MWAIT(mb, 0u);
    asm volatile("tcgen05.fence::after_thread_sync;" ::: "memory");

    const int half = wid >> 2, wr = wid & 3;
    const int o = o0 + wr * 32 + lid;
#pragma unroll
    for (int c4 = 0; c4 < 4; c4++) {
        u32 rr[32];
        LDTM32(rr, tmem + half * 128 + c4 * 32);
        asm volatile("tcgen05.wait::ld.sync.aligned;" ::: "memory");
        const int ib = i0 + half * 128 + c4 * 32;
        const u64 k = (u64)o * 4096 + (u64)ib;
        const float a = am[k >> 6];
        const int4* qp = (const int4*)qw + (k >> 3);
        u32 ov[16];
#pragma unroll
        for (int u = 0; u < 4; u++) {
            int4 qv = qp[u];
            int e[8] = {qv.x & 15, (qv.x >> 4) & 15, qv.y & 15, (qv.y >> 4) & 15,
                        qv.z & 15, (qv.z >> 4) & 15, qv.w & 15, (qv.w >> 4) & 15};
#pragma unroll
            for (int j = 0; j < 4; j++) {
                union { u32 u_; float f_; } c0, c1;
                c0.u_ = rr[u * 8 + 2 * j];
                c1.u_ = rr[u * 8 + 2 * j + 1];
                float w0 = NF4D[e[2 * j]] * a + c0.f_;
                float w1 = NF4D[e[2 * j + 1]] * a + c1.f_;
                asm("cvt.rn.f16x2.f32 %0, %1, %2;" : "=r"(ov[u * 4 + j]) : "f"(w1), "f"(w0));
            }
        }
        if (!tiled) {
            char* wp = (char*)w + k * 2;
#pragma unroll
            for (int j = 0; j < 4; j++)
                asm volatile("st.global.cs.v4.b32 [%0], {%1,%2,%3,%4};"
                             :: "l"(wp + j * 16), "r"(ov[4 * j]), "r"(ov[4 * j + 1]),
                                "r"(ov[4 * j + 2]), "r"(ov[4 * j + 3]) : "memory");
        } else {
            const u64 tbase = ((u64)((o >> 7) * 64 + (ib >> 6))) * 16384ull;
            const u32 rowoff = (u32)((o & 127) * 128 + (ib & 63) * 2);
#pragma unroll
            for (int j = 0; j < 4; j++) {
                u32 off = rowoff + (u32)(j * 16);
                off = off ^ ((off >> 3) & 0x70);
                asm volatile("st.global.cs.v4.b32 [%0], {%1,%2,%3,%4};"
                             :: "l"((char*)w + tbase + off),
                                "r"(ov[4 * j]), "r"(ov[4 * j + 1]),
                                "r"(ov[4 * j + 2]), "r"(ov[4 * j + 3]) : "memory");
            }
        }
    }
    asm volatile("tcgen05.fence::before_thread_sync;" ::: "memory");
    __syncthreads();
    if (wid == 0) {
        asm volatile("tcgen05.relinquish_alloc_permit.cta_group::1.sync.aligned;");
        asm volatile("tcgen05.dealloc.cta_group::1.sync.aligned.b32 %0, %1;"
                     :: "r"(tmem), "r"(256u));
    }
}
)NVSRC";

// --- driver/nvrtc plumbing ---
typedef int (*nvrtcCreateProgram_t)(void**, const char*, const char*, int,
                                    const char* const*, const char* const*);
typedef int (*nvrtcCompileProgram_t)(void*, int, const char* const*);
typedef int (*nvrtcGetCUBINSize_t)(void*, size_t*);
typedef int (*nvrtcGetCUBIN_t)(void*, char*);
typedef int (*cuInit_t)(unsigned);
typedef int (*cuDevicePrimaryCtxRetain_t)(void**, int);
typedef int (*cuCtxSetCurrent_t)(void*);
typedef int (*cuModuleLoadDataEx_t)(void**, const void*, unsigned, int*, void**);
typedef int (*cuModuleGetFunction_t)(void**, void*, const char*);
typedef int (*cuModuleGetGlobal_t)(unsigned long long*, size_t*, void*, const char*);
typedef int (*cuFuncSetAttribute_t)(void*, int, int);
typedef int (*cuLaunchKernel_t)(void*, unsigned, unsigned, unsigned,
                                unsigned, unsigned, unsigned,
                                unsigned, void*, void**, void**);
typedef int (*cuCtxSynchronize_t)(void);
typedef int (*cuMemcpyDtoH_t)(void*, unsigned long long, size_t);

#if defined(CUDA_API_PER_THREAD_DEFAULT_STREAM) || defined(__CUDA_API_PER_THREAD_DEFAULT_STREAM)
#define DRV_STREAM ((void*)0x2)
#else
#define DRV_STREAM ((void*)0x1)
#endif

static bool g_ok_gemm = false, g_ok_wb = false;
static int g_mode = 0;  // 4 = tiled bulk (7c/7), 1 = row-major (5c/5), 0 = host
static cuLaunchKernel_t p_cuLaunchKernel = nullptr;
static void* g_fn_gemm = nullptr;
static void* g_fn_wbuild = nullptr;
static unsigned long long g_gx = 0, g_gw = 0, g_glb = 0, g_glat = 0;
constexpr int SMEM5 = 198656;
constexpr int SMEMW = 51200;

static float h2f(uint16_t h) {
    uint32_t s = (h >> 15) & 1, e = (h >> 10) & 31, m = h & 1023;
    uint32_t f;
    if (e == 0) {
        if (m == 0) f = s << 31;
        else {
            e = 127 - 15 + 1;
            while (!(m & 1024)) { m <<= 1; e--; }
            m &= 1023;
            f = (s << 31) | (e << 23) | (m << 13);
        }
    } else if (e == 31) f = (s << 31) | 0x7F800000 | (m << 13);
    else f = (s << 31) | ((e - 15 + 127) << 23) | (m << 13);
    float r; memcpy(&r, &f, 4); return r;
}

static bool try_init_tcgen05() {
    void* hcu = dlopen("libcuda.so.1", RTLD_NOW | RTLD_GLOBAL);
    if (!hcu) hcu = dlopen("libcuda.so", RTLD_NOW | RTLD_GLOBAL);
    if (!hcu) return false;
    void* hnv = dlopen("libnvrtc.so.13", RTLD_NOW | RTLD_GLOBAL);
    if (!hnv) hnv = dlopen("libnvrtc.so", RTLD_NOW | RTLD_GLOBAL);
    if (!hnv) hnv = dlopen("libnvrtc.so.12", RTLD_NOW | RTLD_GLOBAL);
    if (!hnv) return false;

    auto nCreate  = (nvrtcCreateProgram_t)dlsym(hnv, "nvrtcCreateProgram");
    auto nCompile = (nvrtcCompileProgram_t)dlsym(hnv, "nvrtcCompileProgram");
    auto nCbSize  = (nvrtcGetCUBINSize_t)dlsym(hnv, "nvrtcGetCUBINSize");
    auto nCb      = (nvrtcGetCUBIN_t)dlsym(hnv, "nvrtcGetCUBIN");
    auto cInit    = (cuInit_t)dlsym(hcu, "cuInit");
    auto cRetain  = (cuDevicePrimaryCtxRetain_t)dlsym(hcu, "cuDevicePrimaryCtxRetain");
    auto cSetCur  = (cuCtxSetCurrent_t)dlsym(hcu, "cuCtxSetCurrent");
    auto cModLoad = (cuModuleLoadDataEx_t)dlsym(hcu, "cuModuleLoadDataEx");
    auto cGetFn   = (cuModuleGetFunction_t)dlsym(hcu, "cuModuleGetFunction");
    auto cGetGlb  = (cuModuleGetGlobal_t)dlsym(hcu, "cuModuleGetGlobal_v2");
    auto cSetAttr = (cuFuncSetAttribute_t)dlsym(hcu, "cuFuncSetAttribute");
    auto cLaunch  = (cuLaunchKernel_t)dlsym(hcu, "cuLaunchKernel");
    auto cSync    = (cuCtxSynchronize_t)dlsym(hcu, "cuCtxSynchronize");
    auto cD2H     = (cuMemcpyDtoH_t)dlsym(hcu, "cuMemcpyDtoH_v2");
    if (!nCreate || !nCompile || !nCbSize || !nCb || !cInit || !cRetain ||
        !cSetCur || !cModLoad || !cGetFn || !cGetGlb || !cSetAttr ||
        !cLaunch || !cSync || !cD2H)
        return false;

    if (cInit(0)) return false;
    void* ctx = nullptr;
    if (cRetain(&ctx, 0)) return false;
    if (cSetCur(ctx)) return false;

    void* prog = nullptr;
    if (nCreate(&prog, NVRTC_SRC, "gemm7c.cu", 0, nullptr, nullptr)) return false;
    const char* opts[] = {"--gpu-architecture=sm_103a"};
    if (nCompile(prog, 1, opts)) return false;
    size_t cbsz = 0;
    if (nCbSize(prog, &cbsz) || cbsz == 0) return false;
    static char* cubin = new char[cbsz];
    if (nCb(prog, cubin)) return false;

    void* mod = nullptr;
    if (cModLoad(&mod, cubin, 0, nullptr, nullptr)) return false;
    void *fG5 = nullptr, *fG5c = nullptr, *fG7 = nullptr, *fG7c = nullptr;
    void *fInit = nullptr, *fInit7 = nullptr, *fWb = nullptr, *fWti = nullptr;
    if (cGetFn(&fG5, mod, "gemm5")) return false;
    if (cGetFn(&fG5c, mod, "gemm5c")) return false;
    if (cGetFn(&fG7, mod, "gemm7")) return false;
    if (cGetFn(&fG7c, mod, "gemm7c")) return false;
    if (cGetFn(&fInit, mod, "initt")) return false;
    if (cGetFn(&fInit7, mod, "init7")) return false;
    if (cGetFn(&fWb, mod, "wbuild")) return false;
    if (cGetFn(&fWti, mod, "wtinit")) return false;
    unsigned long long gx = 0, gw = 0, gout = 0, glb = 0, glat = 0,
                       gtqw = 0, gtam = 0;
    size_t sz;
    if (cGetGlb(&gx, &sz, mod, "GX")) return false;
    if (cGetGlb(&gw, &sz, mod, "GW")) return false;
    if (cGetGlb(&gout, &sz, mod, "GOUT")) return false;
    if (cGetGlb(&glb, &sz, mod, "GLB")) return false;
    if (cGetGlb(&glat, &sz, mod, "GLAT")) return false;
    if (cGetGlb(&gtqw, &sz, mod, "GTQW")) return false;
    if (cGetGlb(&gtam, &sz, mod, "GTAM")) return false;
    if (cSetAttr(fG5, 8, SMEM5)) return false;
    if (cSetAttr(fG5c, 8, SMEM5)) return false;
    if (cSetAttr(fG7, 8, SMEM5)) return false;
    if (cSetAttr(fG7c, 8, SMEM5)) return false;
    if (cSetAttr(fWb, 8, SMEMW)) return false;

    p_cuLaunchKernel = cLaunch;
    g_gx = gx; g_gw = gw; g_glb = glb; g_glat = glat;

    static float row[OUT_F];
    const int ms4[4] = {0, 97, 4095, 8191};
    auto check_out = [&](unsigned long long gout_) -> bool {
        for (int ri = 0; ri < 4; ri++) {
            int m = ms4[ri];
            if (cD2H(row, gout_ + (unsigned long long)m * OUT_F * 4, OUT_F * 4))
                return false;
            for (int n = 0; n < OUT_F; n++) {
                float ref = 0.0f;
                for (int k = 0; k < IN_F; k++) {
                    int av = (k * 131 + m * 7) % 9 - 4;
                    int bv = (k * 17 + n * 3) % 7 - 3;
                    ref += (av * 0.25f) * (bv * 0.25f);
                }
                if (fabsf(row[n] - ref) > 0.01f) return false;
            }
        }
        return true;
    };

    // ---- tiled init ----
    bool tiled_ready =
        (cLaunch(fInit7, 131072, 1, 1, 256, 1, 1, 0, DRV_STREAM, nullptr, nullptr) == 0 &&
         cSync() == 0);

    // ---- TEST gemm7c, then gemm7 ----
    bool g7cok = false, g7ok = false;
    if (tiled_ready) {
        unsigned long long px = gx, pw = gw, po = gout;
        void* args[3] = {&px, &pw, &po};
        if (cLaunch(fG7c, 148, 1, 1, 256, 1, 1, SMEM5, DRV_STREAM, args, nullptr) == 0 &&
            cSync() == 0 && check_out(gout))
            g7cok = true;
        if (!g7cok) {
            if (cLaunch(fG7, 148, 1, 1, 256, 1, 1, SMEM5, DRV_STREAM, args, nullptr) == 0 &&
                cSync() == 0 && check_out(gout))
                g7ok = true;
        }
    }

    // ---- wbuild math + tiled layout tests ----
    bool wb_math_ok = false, wb_tiled_ok = false;
    if (cLaunch(fWti, 32768, 1, 1, 256, 1, 1, 0, DRV_STREAM, nullptr, nullptr) == 0 &&
        cSync() == 0) {
        auto wref = [&](int o, int i) -> float {
            uint64_t k = (uint64_t)o * 4096 + i;
            int qv = (int)(((k >> 1) * 37ull) & 255ull);
            int nib = (k & 1) ? (qv >> 4) & 15 : qv & 15;
            float a = (float)(((uint32_t)((k >> 6) * 13ull)) % 31u + 1u) * 0.03125f;
            float lora = 0.0f;
            for (int r = 0; r < 64; r++) {
                float lb = (float)((int)(((uint32_t)o * 3u + r * 7u) % 17u) - 8) * 0.015625f;
                float la = (float)((int)(((uint32_t)i * 5u + r * 11u) % 19u) - 9) * 0.015625f;
                lora += lb * la;
            }
            return NF4H[nib] * a + lora;
        };
        auto run_wb = [&](int tiled) -> bool {
            unsigned long long pq = gtqw, pa = gtam, pl = glb, pt = glat, pw2 = gw;
            int tf = tiled;
            void* args[6] = {&pq, &pa, &pl, &pt, &pw2, &tf};
            if (cLaunch(fWb, 512, 1, 1, 256, 1, 1, SMEMW, DRV_STREAM, args, nullptr))
                return false;
            return cSync() == 0;
        };
        const int os[4] = {0, 1, 255, 4095};
        static uint16_t wrow[IN_F];
        if (run_wb(0)) {
            bool ok = true;
            for (int oi = 0; oi < 4 && ok; oi++) {
                int o = os[oi];
                if (cD2H(wrow, gw + (unsigned long long)o * IN_F * 2, IN_F * 2)) { ok = false; break; }
                for (int i = 0; i < IN_F; i++)
                    if (fabsf(h2f(wrow[i]) - wref(o, i)) > 0.01f) { ok = false; break; }
            }
            wb_math_ok = ok;
        }
        if (wb_math_ok && (g7cok || g7ok) && run_wb(1)) {
            static uint16_t* hw = new uint16_t[16777216];
            if (cD2H(hw, gw, (size_t)16777216 * 2) == 0) {
                bool ok = true;
                for (int oi = 0; oi < 4 && ok; oi++) {
                    int o = os[oi];
                    for (int i = 0; i < IN_F; i++) {
                        uint32_t off = (uint32_t)((o & 127) * 128 + (i & 63) * 2);
                        off = off ^ ((off >> 3) & 0x70);
                        uint64_t boff = ((uint64_t)((o >> 7) * 64 + (i >> 6))) * 16384ull + off;
                        if (fabsf(h2f(hw[boff >> 1]) - wref(o, i)) > 0.01f) { ok = false; break; }
                    }
                }
                wb_tiled_ok = ok;
            }
        }
    }

    if ((g7cok || g7ok) && wb_tiled_ok) {
        g_fn_gemm = g7cok ? fG7c : fG7;
        g_ok_gemm = true; g_mode = 4;
        g_fn_wbuild = fWb; g_ok_wb = true;
        return true;
    }
    // row-major ladder
    if (cLaunch(fInit, 131072, 1, 1, 256, 1, 1, 0, DRV_STREAM, nullptr, nullptr) ||
        cSync())
        return false;
    {
        unsigned long long px = gx, pw = gw, po = gout;
        void* args[3] = {&px, &pw, &po};
        if (cLaunch(fG5c, 148, 1, 1, 256, 1, 1, SMEM5, DRV_STREAM, args, nullptr) == 0 &&
            cSync() == 0 && check_out(gout)) {
            g_fn_gemm = fG5c; g_ok_gemm = true; g_mode = 1;
        } else if (cLaunch(fG5, 148, 1, 1, 256, 1, 1, SMEM5, DRV_STREAM, args, nullptr) == 0 &&
                   cSync() == 0 && check_out(gout)) {
            g_fn_gemm = fG5; g_ok_gemm = true; g_mode = 1;
        }
    }
    if (g_ok_gemm && wb_math_ok) { g_fn_wbuild = fWb; g_ok_wb = true; }
    return g_ok_gemm;
}

__attribute__((constructor))
static void _init_drv() {
    try_init_tcgen05();
}

// ---------------------------------------------------------------------------
extern "C" void kernel_launch(void* const* d_in, const int* in_sizes, int n_in,
                              void* d_out, int out_size) {
    const float* x  = (const float*)d_in[0];
    const int*   qw = (const int*)d_in[1];
    const float* am = (const float*)d_in[2];
    const float* lA = (const float*)d_in[3];
    const float* lB = (const float*)d_in[4];
    float*       out = (float*)d_out;

    (void)in_sizes; (void)n_in; (void)out_size;

    if (g_ok_gemm) {
        __half* xh = (__half*)(uintptr_t)g_gx;
        __half* wh = (__half*)(uintptr_t)g_gw;

        if (g_mode >= 4)
            convert_x_tiled_kernel<<<(M_ROWS * IN_F / 8) / 256, 256>>>(x, (char*)xh);
        else
            convert_x_kernel<<<(M_ROWS * IN_F / 8) / 256, 256>>>(x, xh);

        if (g_ok_wb) {
            cvt_lb_kernel<<<256, 256>>>(lB, (__half*)(uintptr_t)g_glb);
            cvt_lat_kernel<<<64, 256>>>(lA, (__half*)(uintptr_t)g_glat);
            unsigned long long pq = (unsigned long long)(uintptr_t)qw;
            unsigned long long pa = (unsigned long long)(uintptr_t)am;
            unsigned long long pl = g_glb, pt = g_glat, pw = g_gw;
            int tf = (g_mode >= 4) ? 1 : 0;
            void* args[6] = {&pq, &pa, &pl, &pt, &pw, &tf};
            p_cuLaunchKernel(g_fn_wbuild, 512, 1, 1, 256, 1, 1, SMEMW,
                             DRV_STREAM, args, nullptr);
        } else {
            build_weff_kernel<<<dim3(IN_F / 128, OUT_F / 64), 256>>>(qw, am, lA, lB, wh);
        }

        unsigned long long px = g_gx, pw2 = g_gw;
        void* po = (void*)out;
        void* args[3] = {&px, &pw2, &po};
        p_cuLaunchKernel(g_fn_gemm, 148, 1, 1, 256, 1, 1, SMEM5,
                         DRV_STREAM, args, nullptr);
    } else {
        __half* xh; __half* wh;
        cudaGetSymbolAddress((void**)&xh, g_Xh);
        cudaGetSymbolAddress((void**)&wh, g_Wh);
        convert_x_kernel<<<(M_ROWS * IN_F / 8) / 256, 256>>>(x, xh);
        build_weff_kernel<<<dim3(IN_F / 128, OUT_F / 64), 256>>>(qw, am, lA, lB, wh);
        cudaFuncSetAttribute(gemm_f16_kernel,
                             cudaFuncAttributeMaxDynamicSharedMemorySize, SMEM_TOTAL);
        gemm_f16_kernel<<<148, 512, SMEM_TOTAL>>>(xh, wh, out);
    }
}

// round 17
// speedup vs baseline: 1.1198x; 1.0266x over previous
#include <cuda_runtime.h>
#include <cuda_fp16.h>
#include <cstdint>
#include <cstdio>
#include <cstring>
#include <cmath>
#include <dlfcn.h>

#define IN_F   4096
#define OUT_F  4096
#define M_ROWS 8192

// Host-module fp16 scratch (used by the host fallback path).
__device__ __half g_Xh[(size_t)M_ROWS * IN_F];
__device__ __half g_Wh[(size_t)OUT_F * IN_F];

__constant__ float NF4[16] = {
    -1.0f, -0.6961928009986877f, -0.5250730514526367f, -0.39491748809814453f,
    -0.28444138169288635f, -0.18477343022823334f, -0.09105003625154495f, 0.0f,
    0.07958029955625534f, 0.16093020141124725f, 0.24611230194568634f,
    0.33791524171829224f, 0.4407098889350891f, 0.5626170039176941f,
    0.7229568362236023f, 1.0f
};

static const float NF4H[16] = {
    -1.0f, -0.6961928009986877f, -0.5250730514526367f, -0.39491748809814453f,
    -0.28444138169288635f, -0.18477343022823334f, -0.09105003625154495f, 0.0f,
    0.07958029955625534f, 0.16093020141124725f, 0.24611230194568634f,
    0.33791524171829224f, 0.4407098889350891f, 0.5626170039176941f,
    0.7229568362236023f, 1.0f
};

__device__ __forceinline__ uint32_t smem_u32(const void* p) {
    uint32_t a;
    asm("{ .reg .u64 t; cvta.to.shared.u64 t, %1; cvt.u32.u64 %0, t; }" : "=r"(a) : "l"(p));
    return a;
}

// ---------------------------------------------------------------------------
// Kernel A: convert x (fp32) -> dst (fp16) row-major. 8 elems/thread.
// ---------------------------------------------------------------------------
__global__ void convert_x_kernel(const float* __restrict__ x, __half* __restrict__ dst) {
    size_t i = ((size_t)blockIdx.x * 256 + threadIdx.x) * 8;
    float4 v0 = *(const float4*)(x + i);
    float4 v1 = *(const float4*)(x + i + 4);
    __half2 h0 = __floats2half2_rn(v0.x, v0.y);
    __half2 h1 = __floats2half2_rn(v0.z, v0.w);
    __half2 h2 = __floats2half2_rn(v1.x, v1.y);
    __half2 h3 = __floats2half2_rn(v1.z, v1.w);
    uint4 o;
    o.x = *(uint32_t*)&h0; o.y = *(uint32_t*)&h1;
    o.z = *(uint32_t*)&h2; o.w = *(uint32_t*)&h3;
    *(uint4*)&dst[i] = o;
}

// Kernel A': convert x -> TILED layout: tile (m>>7, k>>6) contiguous 16KB SW128.
__global__ void convert_x_tiled_kernel(const float* __restrict__ x, char* __restrict__ dst) {
    size_t i = ((size_t)blockIdx.x * 256 + threadIdx.x) * 8;
    float4 v0 = *(const float4*)(x + i);
    float4 v1 = *(const float4*)(x + i + 4);
    __half2 h0 = __floats2half2_rn(v0.x, v0.y);
    __half2 h1 = __floats2half2_rn(v0.z, v0.w);
    __half2 h2 = __floats2half2_rn(v1.x, v1.y);
    __half2 h3 = __floats2half2_rn(v1.z, v1.w);
    uint4 o;
    o.x = *(uint32_t*)&h0; o.y = *(uint32_t*)&h1;
    o.z = *(uint32_t*)&h2; o.w = *(uint32_t*)&h3;
    const uint32_t m = (uint32_t)(i >> 12), k = (uint32_t)(i & 4095);
    uint32_t off = (m & 127) * 128 + (k & 63) * 2;
    off = off ^ ((off >> 3) & 0x70);
    const size_t boff = ((size_t)((m >> 7) * 64 + (k >> 6))) * 16384 + off;
    *(uint4*)(dst + boff) = o;
}

// lora_B [4096][64] fp32 -> fp16 same layout
__global__ void cvt_lb_kernel(const float* __restrict__ lB, __half* __restrict__ lb) {
    size_t i = ((size_t)blockIdx.x * 256 + threadIdx.x) * 4;
    float4 v = *(const float4*)(lB + i);
    __half h[4] = {__float2half_rn(v.x), __float2half_rn(v.y),
                   __float2half_rn(v.z), __float2half_rn(v.w)};
    *(uint2*)&lb[i] = *(uint2*)h;
}

// lora_A [64][4096] fp32 -> lat [4096][64] fp16 (transpose)
__global__ void cvt_lat_kernel(const float* __restrict__ lA, __half* __restrict__ lat) {
    __shared__ float s[64][65];
    const int tid = threadIdx.x;
    const int i0 = blockIdx.x * 64;
    for (int idx = tid; idx < 4096; idx += 256) {
        int r = idx >> 6, ii = idx & 63;
        s[r][ii] = lA[r * IN_F + i0 + ii];
    }
    __syncthreads();
    int ii = tid >> 2, rs = (tid & 3) * 16;
    __half h[16];
#pragma unroll
    for (int j = 0; j < 16; j++) h[j] = __float2half_rn(s[rs + j][ii]);
    uint4* dst = (uint4*)&lat[(size_t)(i0 + ii) * 64 + rs];
    dst[0] = *(uint4*)&h[0];
    dst[1] = *(uint4*)&h[8];
}

// ---------------------------------------------------------------------------
// Host fallback: W_eff = NF4 dequant * absmax + lora_B @ lora_A  (fp16, row-major)
// ---------------------------------------------------------------------------
__global__ void build_weff_kernel(const int* __restrict__ qweight,
                                  const float* __restrict__ absmax,
                                  const float* __restrict__ lA,
                                  const float* __restrict__ lB,
                                  __half* __restrict__ dst) {
    __shared__ float Bsh[64][64];
    __shared__ float Ash[64][128];

    const int tid = threadIdx.x;
    const int o0 = blockIdx.y * 64;
    const int i0 = blockIdx.x * 128;

    for (int t = tid; t < 64 * 64; t += 256) {
        int o = t >> 6, r = t & 63;
        Bsh[r][o] = lB[(o0 + o) * 64 + r];
    }
    for (int t = tid; t < 64 * 128; t += 256) {
        int r = t >> 7, c = t & 127;
        Ash[r][c] = lA[r * IN_F + i0 + c];
    }
    __syncthreads();

    const int oo0 = (tid >> 4) * 4;
    const int ii0 = (tid & 15) * 8;

    float acc[4][8];
#pragma unroll
    for (int a = 0; a < 4; a++)
#pragma unroll
        for (int b = 0; b < 8; b++) acc[a][b] = 0.0f;

#pragma unroll 4
    for (int r = 0; r < 64; r++) {
        float4 a0 = *(const float4*)&Ash[r][ii0];
        float4 a1 = *(const float4*)&Ash[r][ii0 + 4];
#pragma unroll
        for (int oo = 0; oo < 4; oo++) {
            float bv = Bsh[r][oo0 + oo];
            acc[oo][0] += bv * a0.x; acc[oo][1] += bv * a0.y;
            acc[oo][2] += bv * a0.z; acc[oo][3] += bv * a0.w;
            acc[oo][4] += bv * a1.x; acc[oo][5] += bv * a1.y;
            acc[oo][6] += bv * a1.z; acc[oo][7] += bv * a1.w;
        }
    }

#pragma unroll
    for (int oo = 0; oo < 4; oo++) {
        const int o = o0 + oo0 + oo;
        const size_t k = (size_t)o * IN_F + i0 + ii0;
        const int4 qv = ((const int4*)qweight)[k >> 3];
        const float am = absmax[k >> 6];

        float w[8];
        w[0] = NF4[qv.x & 15];  w[1] = NF4[(qv.x >> 4) & 15];
        w[2] = NF4[qv.y & 15];  w[3] = NF4[(qv.y >> 4) & 15];
        w[4] = NF4[qv.z & 15];  w[5] = NF4[(qv.z >> 4) & 15];
        w[6] = NF4[qv.w & 15];  w[7] = NF4[(qv.w >> 4) & 15];

        __half2 h0 = __floats2half2_rn(w[0] * am + acc[oo][0], w[1] * am + acc[oo][1]);
        __half2 h1 = __floats2half2_rn(w[2] * am + acc[oo][2], w[3] * am + acc[oo][3]);
        __half2 h2 = __floats2half2_rn(w[4] * am + acc[oo][4], w[5] * am + acc[oo][5]);
        __half2 h3 = __floats2half2_rn(w[6] * am + acc[oo][6], w[7] * am + acc[oo][7]);
        uint4 pk;
        pk.x = *(uint32_t*)&h0; pk.y = *(uint32_t*)&h1;
        pk.z = *(uint32_t*)&h2; pk.w = *(uint32_t*)&h3;
        *(uint4*)&dst[k] = pk;
    }
}

// ---------------------------------------------------------------------------
// Host fallback GEMM (proven 778us): fp16 mma.sync, 512 thr, 4-stage.
// ---------------------------------------------------------------------------
constexpr int BM = 128, BN = 256, BK = 64, S = 4;
constexpr int NT = IN_F / BK;
constexpr int A_BYTES = BM * 128;
constexpr int B_BYTES = BN * 128;
constexpr int STAGE = A_BYTES + B_BYTES;
constexpr int SMEM_TOTAL = 1024 + S * STAGE;
constexpr int TOTAL_TILES = (M_ROWS / BM) * (OUT_F / BN);

__device__ __forceinline__ void mma_f16(float c[4], const uint32_t a[4],
                                        uint32_t b0, uint32_t b1) {
    asm volatile(
        "mma.sync.aligned.m16n8k16.row.col.f32.f16.f16.f32 "
        "{%0,%1,%2,%3}, {%4,%5,%6,%7}, {%8,%9}, {%0,%1,%2,%3};"
        : "+f"(c[0]), "+f"(c[1]), "+f"(c[2]), "+f"(c[3])
        : "r"(a[0]), "r"(a[1]), "r"(a[2]), "r"(a[3]), "r"(b0), "r"(b1));
}

__device__ __forceinline__ void ldsm4(uint32_t& r0, uint32_t& r1,
                                      uint32_t& r2, uint32_t& r3, uint32_t addr) {
    asm volatile("ldmatrix.sync.aligned.m8n8.x4.shared.b16 {%0,%1,%2,%3}, [%4];"
                 : "=r"(r0), "=r"(r1), "=r"(r2), "=r"(r3) : "r"(addr));
}

__device__ __forceinline__ void st_cs_f2(float* p, float a, float b) {
    asm volatile("st.global.cs.v2.f32 [%0], {%1,%2};" :: "l"(p), "f"(a), "f"(b)
                 : "memory");
}

__device__ __forceinline__ void issue_stage(uint32_t sA, uint32_t sB,
                                            const __half* xb, const __half* wb,
                                            int tid) {
#pragma unroll
    for (int r = 0; r < 2; r++) {
        int i = tid + r * 512;
        int row = i >> 3, c = i & 7;
        uint32_t off = (uint32_t)(row * 128 + ((c * 16) ^ ((row & 7) << 4)));
        const __half* src = xb + (size_t)row * IN_F + c * 8;
        asm volatile("cp.async.cg.shared.global.L2::256B [%0], [%1], 16;\n"
                     :: "r"(sA + off), "l"(src));
    }
#pragma unroll
    for (int r = 0; r < 4; r++) {
        int i = tid + r * 512;
        int row = i >> 3, c = i & 7;
        uint32_t off = (uint32_t)(row * 128 + ((c * 16) ^ ((row & 7) << 4)));
        const __half* src = wb + (size_t)row * IN_F + c * 8;
        asm volatile("cp.async.cg.shared.global.L2::256B [%0], [%1], 16;\n"
                     :: "r"(sB + off), "l"(src));
    }
}

__global__ void __launch_bounds__(512, 1)
gemm_f16_kernel(const __half* __restrict__ Xh, const __half* __restrict__ Wh,
                float* __restrict__ out) {
    extern __shared__ char sm[];
    const uint32_t stage0 = (smem_u32(sm) + 1023) & ~1023u;

    const int tid = threadIdx.x;
    const int wid = tid >> 5;
    const int lane = tid & 31;
    const int warp_m = wid & 3;
    const int warp_n = wid >> 2;
    const int g = lane >> 3;
    const int r = lane & 7;

    uint32_t a_rowoff[2], a_xr[2];
    const uint32_t a_kc = (uint32_t)((g >> 1) * 16);
#pragma unroll
    for (int mf = 0; mf < 2; mf++) {
        int row = warp_m * 32 + mf * 16 + (g & 1) * 8 + r;
        a_rowoff[mf] = row * 128;
        a_xr[mf] = (row & 7) << 4;
    }
    uint32_t b_rowoff[4], b_xr[4];
    const uint32_t b_kc = (uint32_t)((g & 1) * 16);
#pragma unroll
    for (int p = 0; p < 4; p++) {
        int row = warp_n * 64 + p * 16 + (g >> 1) * 8 + r;
        b_rowoff[p] = row * 128;
        b_xr[p] = (row & 7) << 4;
    }

    for (int t = blockIdx.x; t < TOTAL_TILES; t += gridDim.x) {
        const int mBase = (t >> 4) * BM;
        const int nBase = (t & 15) * BN;
        const __half* xt = Xh + (size_t)mBase * IN_F;
        const __half* wt = Wh + (size_t)nBase * IN_F;

        float acc[2][8][4];
#pragma unroll
        for (int i = 0; i < 2; i++)
#pragma unroll
            for (int j = 0; j < 8; j++)
#pragma unroll
                for (int l = 0; l < 4; l++) acc[i][j][l] = 0.0f;

#pragma unroll
        for (int p = 0; p < S - 1; p++) {
            uint32_t sA = stage0 + p * STAGE;
            issue_stage(sA, sA + A_BYTES, xt + p * BK, wt + p * BK, tid);
            asm volatile("cp.async.commit_group;\n" ::: "memory");
        }

        for (int kt = 0; kt < NT; kt++) {
            asm volatile("cp.async.wait_group %0;\n" :: "n"(S - 2) : "memory");
            __syncthreads();

            if (kt + S - 1 < NT) {
                const int s2 = (kt + S - 1) % S;
                uint32_t sA = stage0 + s2 * STAGE;
                issue_stage(sA, sA + A_BYTES,
                            xt + (kt + S - 1) * BK, wt + (kt + S - 1) * BK, tid);
            }
            asm volatile("cp.async.commit_group;\n" ::: "memory");

            const uint32_t sA = stage0 + (kt % S) * STAGE;
            const uint32_t sB = sA + A_BYTES;

#pragma unroll
            for (int q = 0; q < 4; q++) {
                uint32_t a[2][4];
#pragma unroll
                for (int mf = 0; mf < 2; mf++)
                    ldsm4(a[mf][0], a[mf][1], a[mf][2], a[mf][3],
                          sA + a_rowoff[mf] + (((q * 32) + a_kc) ^ a_xr[mf]));
                uint32_t b[8][2];
#pragma unroll
                for (int p = 0; p < 4; p++)
                    ldsm4(b[2 * p][0], b[2 * p][1], b[2 * p + 1][0], b[2 * p + 1][1],
                          sB + b_rowoff[p] + (((q * 32) + b_kc) ^ b_xr[p]));
#pragma unroll
                for (int mf = 0; mf < 2; mf++)
#pragma unroll
                    for (int nf = 0; nf < 8; nf++)
                        mma_f16(acc[mf][nf], a[mf], b[nf][0], b[nf][1]);
            }
        }
        asm volatile("cp.async.wait_group 0;\n" ::: "memory");

#pragma unroll
        for (int mf = 0; mf < 2; mf++) {
#pragma unroll
            for (int nf = 0; nf < 8; nf++) {
                const int row = mBase + warp_m * 32 + mf * 16 + (lane >> 2);
                const int col = nBase + warp_n * 64 + nf * 8 + (lane & 3) * 2;
                st_cs_f2(&out[(size_t)row * OUT_F + col],
                         acc[mf][nf][0], acc[mf][nf][1]);
                st_cs_f2(&out[(size_t)(row + 8) * OUT_F + col],
                         acc[mf][nf][2], acc[mf][nf][3]);
            }
        }
        __syncthreads();
    }
}

// ===========================================================================
// NVRTC module: gemm7c (proven R16; now launched at grid=128 for perfect
// 4-tiles/CTA balance), gemm7 (R13), gemm5c/5 backstops, wbuild, inits.
// ===========================================================================
static const char* NVRTC_SRC = R"NVSRC(
typedef unsigned int u32;
typedef unsigned long long u64;
typedef unsigned short u16;

__device__ __align__(128) u16 GX[33554432];  // X fp16 (row-major OR tiled)
__device__ __align__(128) u16 GW[16777216];  // W fp16 (row-major OR tiled)
__device__ float GOUT[33554432];             // gemm self-test output
__device__ u16 GLB[262144];                  // lora_B fp16 [4096][64]
__device__ u16 GLAT[262144];                 // lora_A^T fp16 [4096][64]
__device__ int GTQW[8388608];                // wbuild self-test qweight
__device__ float GTAM[262144];               // wbuild self-test absmax

__constant__ float NF4D[16] = {
    -1.0f, -0.6961928009986877f, -0.5250730514526367f, -0.39491748809814453f,
    -0.28444138169288635f, -0.18477343022823334f, -0.09105003625154495f, 0.0f,
    0.07958029955625534f, 0.16093020141124725f, 0.24611230194568634f,
    0.33791524171829224f, 0.4407098889350891f, 0.5626170039176941f,
    0.7229568362236023f, 1.0f
};

#define MWAIT(ba, ph) do { u32 _d; \
    asm volatile("{ .reg .pred p; mbarrier.try_wait.parity.acquire.cta.shared::cta.b64 p, [%1], %2; selp.b32 %0,1,0,p; }" \
                 : "=r"(_d) : "r"(ba), "r"(ph) : "memory"); \
    if (!_d) { \
        asm volatile("{ .reg .pred P1; WL%=: mbarrier.try_wait.parity.acquire.cta.shared::cta.b64 P1, [%0], %1, 0x989680; @P1 bra.uni WD%=; bra.uni WL%=; WD%=: }" \
                     :: "r"(ba), "r"(ph) : "memory"); } } while(0)

#define LDTM32(rr, addr) \
    asm volatile("tcgen05.ld.sync.aligned.32x32b.x32.b32 " \
        "{%0,%1,%2,%3,%4,%5,%6,%7,%8,%9,%10,%11,%12,%13,%14,%15," \
        "%16,%17,%18,%19,%20,%21,%22,%23,%24,%25,%26,%27,%28,%29,%30,%31}, [%32];" \
        : "=r"(rr[0]), "=r"(rr[1]), "=r"(rr[2]), "=r"(rr[3]), \
          "=r"(rr[4]), "=r"(rr[5]), "=r"(rr[6]), "=r"(rr[7]), \
          "=r"(rr[8]), "=r"(rr[9]), "=r"(rr[10]), "=r"(rr[11]), \
          "=r"(rr[12]), "=r"(rr[13]), "=r"(rr[14]), "=r"(rr[15]), \
          "=r"(rr[16]), "=r"(rr[17]), "=r"(rr[18]), "=r"(rr[19]), \
          "=r"(rr[20]), "=r"(rr[21]), "=r"(rr[22]), "=r"(rr[23]), \
          "=r"(rr[24]), "=r"(rr[25]), "=r"(rr[26]), "=r"(rr[27]), \
          "=r"(rr[28]), "=r"(rr[29]), "=r"(rr[30]), "=r"(rr[31]) \
        : "r"(addr))

#define BULK(dst, src, sz, mbar) \
    asm volatile("cp.async.bulk.shared::cta.global.mbarrier::complete_tx::bytes " \
                 "[%0], [%1], %2, [%3];" \
                 :: "r"(dst), "l"(src), "r"(sz), "r"(mbar) : "memory")

#define EXPECT_TX(mbar, n) \
    asm volatile("mbarrier.arrive.expect_tx.shared.b64 _, [%0], %1;" \
                 :: "r"(mbar), "r"(n) : "memory")

#define MMA8(tmem, a0, a1, bd, IDESC, en) do { \
    asm volatile("{ .reg .pred p; setp.ne.u32 p, %5, 0; " \
        "tcgen05.mma.cta_group::1.kind::f16 [%0], %1, %2, %3, {%4,%4,%4,%4}, p; }" \
        :: "r"(tmem), "l"(a0), "l"(bd), "r"(IDESC), "r"(0u), "r"(en) : "memory"); \
    asm volatile("{ .reg .pred p; setp.ne.u32 p, %5, 0; " \
        "tcgen05.mma.cta_group::1.kind::f16 [%0], %1, %2, %3, {%4,%4,%4,%4}, p; }" \
        :: "r"((tmem) + 256), "l"(a1), "l"(bd), "r"(IDESC), "r"(0u), "r"(en) : "memory"); \
} while(0)

__device__ __forceinline__ u32 sm2u32(const void* p) {
    u32 a;
    asm("{ .reg .u64 t; cvta.to.shared.u64 t, %1; cvt.u32.u64 %0, t; }" : "=r"(a) : "l"(p));
    return a;
}

__device__ __forceinline__ u32 swz(u32 off) { return off ^ ((off >> 3) & 0x70); }

extern "C" __global__ void initt() {
    u64 i = (u64)blockIdx.x * 256 + threadIdx.x;
    const u16 T[9] = {0xBC00,0xBA00,0xB800,0xB400,0,0x3400,0x3800,0x3A00,0x3C00};
    if (i < 33554432ull) {
        u32 m = (u32)(i >> 12), k = (u32)(i & 4095);
        GX[i] = T[(k*131u + m*7u) % 9u];
    }
    if (i < 16777216ull) {
        u32 n = (u32)(i >> 12), k = (u32)(i & 4095);
        GW[i] = T[(k*17u + n*3u) % 7u + 1u];
    }
}

extern "C" __global__ void init7() {
    u64 i = (u64)blockIdx.x * 256 + threadIdx.x;
    const u16 T[9] = {0xBC00,0xBA00,0xB800,0xB400,0,0x3400,0x3800,0x3A00,0x3C00};
    if (i < 33554432ull) {
        u32 m = (u32)(i >> 12), k = (u32)(i & 4095);
        u64 boff = ((u64)((m >> 7) * 64u + (k >> 6))) * 16384ull
                 + (u64)swz((m & 127u) * 128u + (k & 63u) * 2u);
        GX[boff >> 1] = T[(k*131u + m*7u) % 9u];
    }
    if (i < 16777216ull) {
        u32 n = (u32)(i >> 12), k = (u32)(i & 4095);
        u64 boff = ((u64)((n >> 7) * 64u + (k >> 6))) * 16384ull
                 + (u64)swz((n & 127u) * 128u + (k & 63u) * 2u);
        GW[boff >> 1] = T[(k*17u + n*3u) % 7u + 1u];
    }
}

extern "C" __global__ void wtinit() {
    u64 i = (u64)blockIdx.x * 256 + threadIdx.x;
    if (i < 8388608ull) GTQW[i] = (int)((i * 37ull) & 255ull);
    if (i < 262144ull) {
        GTAM[i] = (float)((u32)(i * 13ull) % 31u + 1u) * 0.03125f;
        u32 o = (u32)(i >> 6), r = (u32)(i & 63);
        float lb = (float)((int)((o*3u + r*7u) % 17u) - 8) * 0.015625f;
        float la = (float)((int)((o*5u + r*11u) % 19u) - 9) * 0.015625f;
        u16 hb, ha;
        asm("cvt.rn.f16.f32 %0, %1;" : "=h"(hb) : "f"(lb));
        asm("cvt.rn.f16.f32 %0, %1;" : "=h"(ha) : "f"(la));
        GLB[i] = hb;
        GLAT[i] = ha;
    }
}

__device__ __forceinline__ void ld_sub(u32 dst, const char* src, int tid, int iters) {
#pragma unroll
    for (int r = 0; r < 8; r++) {
        if (r >= iters) break;
        int i = tid + r * 256; int row = i >> 3, c = i & 7;
        u32 off = (u32)(row * 128 + ((c * 16) ^ ((row & 7) << 4)));
        asm volatile("cp.async.cg.shared.global.L2::256B [%0], [%1], 16;"
                     :: "r"(dst + off), "l"(src + (u64)row * 8192 + c * 16));
    }
}

// ---------------- gemm5 (single M-tile backstop, row-major operands) ----------------
__device__ __forceinline__ void ld_stage(u32 sA, u32 sB, const char* xb,
                                         const char* wb, int tid) {
#pragma unroll
    for (int r = 0; r < 4; r++) {
        int i = tid + r * 256; int row = i >> 3, c = i & 7;
        u32 off = (u32)(row * 128 + ((c * 16) ^ ((row & 7) << 4)));
        asm volatile("cp.async.cg.shared.global.L2::256B [%0], [%1], 16;"
                     :: "r"(sA + off), "l"(xb + (u64)row * 8192 + c * 16));
    }
#pragma unroll
    for (int r = 0; r < 8; r++) {
        int i = tid + r * 256; int row = i >> 3, c = i & 7;
        u32 off = (u32)(row * 128 + ((c * 16) ^ ((row & 7) << 4)));
        asm volatile("cp.async.cg.shared.global.L2::256B [%0], [%1], 16;"
                     :: "r"(sB + off), "l"(wb + (u64)row * 8192 + c * 16));
    }
}

extern "C" __global__ void __launch_bounds__(256, 1)
gemm5(const char* __restrict__ X, const char* __restrict__ W,
      float* __restrict__ out) {
    extern __shared__ char sm[];
    u32 base = (sm2u32(sm) + 1023) & ~1023u;
    const u32 tptr = base;
    const u32 mb = base + 16;
    const u32 st0 = base + 1024;
    const int tid = threadIdx.x, wid = tid >> 5, lid = tid & 31;

    if (wid == 0)
        asm volatile("tcgen05.alloc.cta_group::1.sync.aligned.shared::cta.b32 [%0], %1;"
                     :: "r"(tptr), "r"(256u) : "memory");
    if (tid == 0) {
#pragma unroll
        for (int s = 0; s < 4; s++)
            asm volatile("mbarrier.init.shared.b64 [%0], %1;"
                         :: "r"(mb + s * 8), "r"(1u) : "memory");
    }
    __syncthreads();
    u32 tmem; asm volatile("ld.shared.b32 %0,[%1];" : "=r"(tmem) : "r"(tptr));

    const u64 DBASE = (2ull << 61) | (1ull << 46) | (64ull << 32) | (1ull << 16);
    const u32 IDESC = (1u << 4) | (32u << 17) | (8u << 24);

#pragma unroll 1
    for (int t = blockIdx.x; t < 1024; t += gridDim.x) {
        const int mBase = (t >> 4) * 128, nBase = (t & 15) * 256;
        const char* xt = X + (u64)mBase * 8192;
        const char* wt = W + (u64)nBase * 8192;

#pragma unroll
        for (int p = 0; p < 4; p++) {
            u32 sA = st0 + p * 49152;
            ld_stage(sA, sA + 16384, xt + p * 128, wt + p * 128, tid);
            asm volatile("cp.async.commit_group;" ::: "memory");
        }

#pragma unroll 1
        for (int kt = 0; kt < 64; kt++) {
            const int s = kt & 3;
            const u32 sA = st0 + s * 49152, sB = sA + 16384;
            asm volatile("cp.async.wait_group 3;" ::: "memory");
            __syncthreads();

            if (wid == 0) {
                u32 ep;
                asm volatile("{ .reg .pred p; elect.sync _|p, 0xFFFFFFFF; selp.b32 %0,1,0,p; }"
                             : "=r"(ep));
                if (ep) {
                    asm volatile("fence.proxy.async.shared::cta;" ::: "memory");
                    u64 ad = DBASE | ((u64)(sA >> 4) & 0x3FFF);
                    u64 bd = DBASE | ((u64)(sB >> 4) & 0x3FFF);
#pragma unroll
                    for (int q = 0; q < 4; q++) {
                        u32 en = (kt > 0 || q > 0) ? 1u : 0u;
                        asm volatile("{ .reg .pred p; setp.ne.u32 p, %5, 0; "
                            "tcgen05.mma.cta_group::1.kind::f16 [%0], %1, %2, %3, {%4,%4,%4,%4}, p; }"
                            :: "r"(tmem), "l"(ad + q * 2), "l"(bd + q * 2),
                               "r"(IDESC), "r"(0u), "r"(en) : "memory");
                    }
                    asm volatile("tcgen05.commit.cta_group::1.mbarrier::arrive::one.shared::cluster.b64 [%0];"
                                 :: "r"(mb + s * 8) : "memory");
                }
            }

            if (kt + 4 < 64) {
                u32 ph = (u32)((kt >> 2) & 1);
                MWAIT(mb + s * 8, ph);
                ld_stage(sA, sB, xt + (kt + 4) * 128, wt + (kt + 4) * 128, tid);
            }
            asm volatile("cp.async.commit_group;" ::: "memory");
        }

        MWAIT(mb + 24, 1u);
        asm volatile("tcgen05.fence::after_thread_sync;" ::: "memory");

        if (wid < 4) {
            float* dst = out + (u64)(mBase + wid * 32 + lid) * 4096 + nBase;
#pragma unroll
            for (int ch = 0; ch < 8; ch++) {
                u32 rr[32];
                LDTM32(rr, tmem + ch * 32);
                asm volatile("tcgen05.wait::ld.sync.aligned;" ::: "memory");
#pragma unroll
                for (int j = 0; j < 8; j++)
                    asm volatile("st.global.cs.v4.b32 [%0], {%1,%2,%3,%4};"
                                 :: "l"(dst + ch * 32 + j * 4),
                                    "r"(rr[4 * j]), "r"(rr[4 * j + 1]),
                                    "r"(rr[4 * j + 2]), "r"(rr[4 * j + 3]) : "memory");
            }
            asm volatile("tcgen05.fence::before_thread_sync;" ::: "memory");
        }
        __syncthreads();
    }

    __syncthreads();
    if (wid == 0) {
        asm volatile("tcgen05.relinquish_alloc_permit.cta_group::1.sync.aligned;");
        asm volatile("tcgen05.dealloc.cta_group::1.sync.aligned.b32 %0, %1;"
                     :: "r"(tmem), "r"(256u));
    }
}

// ---------------- gemm5c: 2 M-tiles, decoupled cp.async (row-major) ----------------
extern "C" __global__ void __launch_bounds__(256, 1)
gemm5c(const char* __restrict__ X, const char* __restrict__ W,
       float* __restrict__ out) {
    extern __shared__ char sm[];
    u32 base = (sm2u32(sm) + 1023) & ~1023u;
    const u32 tptr = base;
    const u32 mb = base + 16;
    const u32 st0 = base + 1024;
    const int tid = threadIdx.x, wid = tid >> 5, lid = tid & 31;

    if (wid == 0)
        asm volatile("tcgen05.alloc.cta_group::1.sync.aligned.shared::cta.b32 [%0], %1;"
                     :: "r"(tptr), "r"(512u) : "memory");
    if (tid == 0) {
#pragma unroll
        for (int s = 0; s < 3; s++)
            asm volatile("mbarrier.init.shared.b64 [%0], %1;"
                         :: "r"(mb + s * 8), "r"(1u) : "memory");
    }
    __syncthreads();
    u32 tmem; asm volatile("ld.shared.b32 %0,[%1];" : "=r"(tmem) : "r"(tptr));

    const u64 DBASE = (2ull << 61) | (1ull << 46) | (64ull << 32) | (1ull << 16);
    const u32 IDESC = (1u << 4) | (32u << 17) | (8u << 24);

    int bp1 = 0, bp2 = 0;

#pragma unroll 1
    for (int t = blockIdx.x; t < 512; t += gridDim.x) {
        const int mBase = (t >> 4) * 256, nBase = (t & 15) * 256;
        const char* x0 = X + (u64)mBase * 8192;
        const char* x1 = x0 + 1048576;
        const char* wt = W + (u64)nBase * 8192;

#pragma unroll
        for (int p = 0; p < 2; p++) {
            u32 sA0 = st0 + p * 65536;
            ld_sub(sA0,         x0 + p * 128, tid, 4);
            ld_sub(sA0 + 16384, x1 + p * 128, tid, 4);
            ld_sub(sA0 + 32768, wt + p * 128, tid, 8);
            asm volatile("cp.async.commit_group;" ::: "memory");
        }

#pragma unroll 1
        for (int kt = 0; kt < 64; kt++) {
            const int kdiv = kt / 3;
            const int s = kt - kdiv * 3;
            const u32 sA0 = st0 + s * 65536, sA1 = sA0 + 16384, sB = sA0 + 32768;
            asm volatile("cp.async.wait_group 1;" ::: "memory");
            __syncthreads();

            if (wid == 0) {
                u32 ep;
                asm volatile("{ .reg .pred p; elect.sync _|p, 0xFFFFFFFF; selp.b32 %0,1,0,p; }"
                             : "=r"(ep));
                if (ep) {
                    asm volatile("fence.proxy.async.shared::cta;" ::: "memory");
                    u64 a0 = DBASE | ((u64)(sA0 >> 4) & 0x3FFF);
                    u64 a1 = DBASE | ((u64)(sA1 >> 4) & 0x3FFF);
                    u64 bd = DBASE | ((u64)(sB >> 4) & 0x3FFF);
#pragma unroll
                    for (int q = 0; q < 4; q++) {
                        u32 en = (kt > 0 || q > 0) ? 1u : 0u;
                        MMA8(tmem, a0 + q * 2, a1 + q * 2, bd + q * 2, IDESC, en);
                    }
                    asm volatile("tcgen05.commit.cta_group::1.mbarrier::arrive::one.shared::cluster.b64 [%0];"
                                 :: "r"(mb + s * 8) : "memory");
                }
            }

            if (kt + 2 < 64) {
                const int sd = (kt + 2) - ((kt + 2) / 3) * 3;
                const u32 dA0 = st0 + sd * 65536;
                if (kt >= 1) {
                    const int kp = kt - 1;
                    const int kdv = kp / 3;
                    const int sp = kp - kdv * 3;
                    int bps = (sp == 0) ? 0 : ((sp == 1) ? bp1 : bp2);
                    u32 ph = (u32)(bps ^ (kdv & 1));
                    MWAIT(mb + sp * 8, ph);
                }
                ld_sub(dA0,         x0 + (kt + 2) * 128, tid, 4);
                ld_sub(dA0 + 16384, x1 + (kt + 2) * 128, tid, 4);
                ld_sub(dA0 + 32768, wt + (kt + 2) * 128, tid, 8);
            }
            asm volatile("cp.async.commit_group;" ::: "memory");
        }

        MWAIT(mb, 1u);
        asm volatile("tcgen05.fence::after_thread_sync;" ::: "memory");

        {
            const int half = wid >> 2, wr = wid & 3;
            float* dst = out + (u64)(mBase + half * 128 + wr * 32 + lid) * 4096 + nBase;
            const u32 tm = tmem + half * 256;
#pragma unroll
            for (int ch = 0; ch < 8; ch++) {
                u32 rr[32];
                LDTM32(rr, tm + ch * 32);
                asm volatile("tcgen05.wait::ld.sync.aligned;" ::: "memory");
#pragma unroll
                for (int j = 0; j < 8; j++)
                    asm volatile("st.global.cs.v4.b32 [%0], {%1,%2,%3,%4};"
                                 :: "l"(dst + ch * 32 + j * 4),
                                    "r"(rr[4 * j]), "r"(rr[4 * j + 1]),
                                    "r"(rr[4 * j + 2]), "r"(rr[4 * j + 3]) : "memory");
            }
            asm volatile("tcgen05.fence::before_thread_sync;" ::: "memory");
        }
        __syncthreads();
        bp1 ^= 1; bp2 ^= 1;
    }

    __syncthreads();
    if (wid == 0) {
        asm volatile("tcgen05.relinquish_alloc_permit.cta_group::1.sync.aligned;");
        asm volatile("tcgen05.dealloc.cta_group::1.sync.aligned.b32 %0, %1;"
                     :: "r"(tmem), "r"(512u));
    }
}

// ---------------- gemm7: bulk-copy pipeline, TILED operands (PROVEN R13) ----------
extern "C" __global__ void __launch_bounds__(256, 1)
gemm7(const char* __restrict__ X, const char* __restrict__ W,
      float* __restrict__ out) {
    extern __shared__ char sm[];
    u32 base = (sm2u32(sm) + 1023) & ~1023u;
    const u32 tptr = base;
    const u32 mbc = base + 16;
    const u32 mbf = base + 48;
    const u32 st0 = base + 1024;
    const int tid = threadIdx.x, wid = tid >> 5, lid = tid & 31;

    if (wid == 0)
        asm volatile("tcgen05.alloc.cta_group::1.sync.aligned.shared::cta.b32 [%0], %1;"
                     :: "r"(tptr), "r"(512u) : "memory");
    if (tid == 0) {
#pragma unroll
        for (int s = 0; s < 3; s++) {
            asm volatile("mbarrier.init.shared.b64 [%0], %1;"
                         :: "r"(mbc + s * 8), "r"(1u) : "memory");
            asm volatile("mbarrier.init.shared.b64 [%0], %1;"
                         :: "r"(mbf + s * 8), "r"(1u) : "memory");
        }
    }
    __syncthreads();
    u32 tmem; asm volatile("ld.shared.b32 %0,[%1];" : "=r"(tmem) : "r"(tptr));

    const u64 DBASE = (2ull << 61) | (1ull << 46) | (64ull << 32) | (1ull << 16);
    const u32 IDESC = (1u << 4) | (32u << 17) | (8u << 24);

    int pf0 = 0, pf1 = 0, pf2 = 0;
    int pc0 = 0, pc1 = 0, pc2 = 0;

#pragma unroll 1
    for (int t = blockIdx.x; t < 512; t += gridDim.x) {
        const int mBase = (t >> 4) * 256, nBase = (t & 15) * 256;
        const u64 mt0 = (u64)((t >> 4) * 2) * 64;
        const u64 nt0 = (u64)((t & 15) * 2) * 64;

        if (wid == 0) {
            u32 ep;
            asm volatile("{ .reg .pred p; elect.sync _|p, 0xFFFFFFFF; selp.b32 %0,1,0,p; }"
                         : "=r"(ep));
            if (ep) {
#pragma unroll
                for (int p = 0; p < 2; p++) {
                    u32 sl = st0 + p * 65536;
                    EXPECT_TX(mbf + p * 8, 65536u);
                    BULK(sl,          X + (mt0 + p) * 16384ull,        16384u, mbf + p * 8);
                    BULK(sl + 16384,  X + (mt0 + 64 + p) * 16384ull,   16384u, mbf + p * 8);
                    BULK(sl + 32768,  W + (nt0 + p) * 16384ull,        16384u, mbf + p * 8);
                    BULK(sl + 49152,  W + (nt0 + 64 + p) * 16384ull,   16384u, mbf + p * 8);
                }
#pragma unroll 1
                for (int kt = 0; kt < 64; kt++) {
                    const int kdiv = kt / 3;
                    const int s = kt - kdiv * 3;
                    const u32 sA0 = st0 + s * 65536, sA1 = sA0 + 16384, sB = sA0 + 32768;
                    u32 ph;
                    if (s == 0) { ph = (u32)pf0; pf0 ^= 1; }
                    else if (s == 1) { ph = (u32)pf1; pf1 ^= 1; }
                    else { ph = (u32)pf2; pf2 ^= 1; }
                    MWAIT(mbf + s * 8, ph);

                    u64 a0 = DBASE | ((u64)(sA0 >> 4) & 0x3FFF);
                    u64 a1 = DBASE | ((u64)(sA1 >> 4) & 0x3FFF);
                    u64 bd = DBASE | ((u64)(sB >> 4) & 0x3FFF);
#pragma unroll
                    for (int q = 0; q < 4; q++) {
                        u32 en = (kt > 0 || q > 0) ? 1u : 0u;
                        MMA8(tmem, a0 + q * 2, a1 + q * 2, bd + q * 2, IDESC, en);
                    }
                    asm volatile("tcgen05.commit.cta_group::1.mbarrier::arrive::one.shared::cluster.b64 [%0];"
                                 :: "r"(mbc + s * 8) : "memory");

                    if (kt >= 1) {
                        const int sp = (kt - 1) - ((kt - 1) / 3) * 3;
                        u32 p2;
                        if (sp == 0) { p2 = (u32)pc0; pc0 ^= 1; }
                        else if (sp == 1) { p2 = (u32)pc1; pc1 ^= 1; }
                        else { p2 = (u32)pc2; pc2 ^= 1; }
                        MWAIT(mbc + sp * 8, p2);
                    }

                    if (kt + 2 < 64) {
                        const int sd = (kt + 2) - ((kt + 2) / 3) * 3;
                        const u32 dA0 = st0 + sd * 65536;
                        const u64 kk = (u64)(kt + 2);
                        EXPECT_TX(mbf + sd * 8, 65536u);
                        BULK(dA0,          X + (mt0 + kk) * 16384ull,      16384u, mbf + sd * 8);
                        BULK(dA0 + 16384,  X + (mt0 + 64 + kk) * 16384ull, 16384u, mbf + sd * 8);
                        BULK(dA0 + 32768,  W + (nt0 + kk) * 16384ull,      16384u, mbf + sd * 8);
                        BULK(dA0 + 49152,  W + (nt0 + 64 + kk) * 16384ull, 16384u, mbf + sd * 8);
                    }
                }
                { u32 p2 = (u32)pc0; pc0 ^= 1; MWAIT(mbc, p2); }
            }
        }

        __syncthreads();
        asm volatile("tcgen05.fence::after_thread_sync;" ::: "memory");

        {
            const int half = wid >> 2, wr = wid & 3;
            float* dst = out + (u64)(mBase + half * 128 + wr * 32 + lid) * 4096 + nBase;
            const u32 tm = tmem + half * 256;
#pragma unroll
            for (int ch = 0; ch < 8; ch++) {
                u32 rr[32];
                LDTM32(rr, tm + ch * 32);
                asm volatile("tcgen05.wait::ld.sync.aligned;" ::: "memory");
#pragma unroll
                for (int j = 0; j < 8; j++)
                    asm volatile("st.global.cs.v4.b32 [%0], {%1,%2,%3,%4};"
                                 :: "l"(dst + ch * 32 + j * 4),
                                    "r"(rr[4 * j]), "r"(rr[4 * j + 1]),
                                    "r"(rr[4 * j + 2]), "r"(rr[4 * j + 3]) : "memory");
            }
            asm volatile("tcgen05.fence::before_thread_sync;" ::: "memory");
        }
        __syncthreads();
    }

    __syncthreads();
    if (wid == 0) {
        asm volatile("tcgen05.relinquish_alloc_permit.cta_group::1.sync.aligned;");
        asm volatile("tcgen05.dealloc.cta_group::1.sync.aligned.b32 %0, %1;"
                     :: "r"(tmem), "r"(512u));
    }
}

// ---------------- gemm7c: gemm7 loop + tile-boundary prologue prefetch (R16) ------
extern "C" __global__ void __launch_bounds__(256, 1)
gemm7c(const char* __restrict__ X, const char* __restrict__ W,
       float* __restrict__ out) {
    extern __shared__ char sm[];
    u32 base = (sm2u32(sm) + 1023) & ~1023u;
    const u32 tptr = base;
    const u32 mbc = base + 16;
    const u32 mbf = base + 48;
    const u32 st0 = base + 1024;
    const int tid = threadIdx.x, wid = tid >> 5, lid = tid & 31;

    if (wid == 0)
        asm volatile("tcgen05.alloc.cta_group::1.sync.aligned.shared::cta.b32 [%0], %1;"
                     :: "r"(tptr), "r"(512u) : "memory");
    if (tid == 0) {
#pragma unroll
        for (int s = 0; s < 3; s++) {
            asm volatile("mbarrier.init.shared.b64 [%0], %1;"
                         :: "r"(mbc + s * 8), "r"(1u) : "memory");
            asm volatile("mbarrier.init.shared.b64 [%0], %1;"
                         :: "r"(mbf + s * 8), "r"(1u) : "memory");
        }
    }
    __syncthreads();
    u32 tmem; asm volatile("ld.shared.b32 %0,[%1];" : "=r"(tmem) : "r"(tptr));

    const u64 DBASE = (2ull << 61) | (1ull << 46) | (64ull << 32) | (1ull << 16);
    const u32 IDESC = (1u << 4) | (32u << 17) | (8u << 24);

    int pf0 = 0, pf1 = 0, pf2 = 0;
    int pc0 = 0, pc1 = 0, pc2 = 0;
    int did_prol = 0;   // elected lane is stable across tiles

#pragma unroll 1
    for (int t = blockIdx.x; t < 512; t += gridDim.x) {
        const int mBase = (t >> 4) * 256, nBase = (t & 15) * 256;
        const u64 mt0 = (u64)((t >> 4) * 2) * 64;
        const u64 nt0 = (u64)((t & 15) * 2) * 64;

        if (wid == 0) {
            u32 ep;
            asm volatile("{ .reg .pred p; elect.sync _|p, 0xFFFFFFFF; selp.b32 %0,1,0,p; }"
                         : "=r"(ep));
            if (ep) {
                if (!did_prol) {
                    did_prol = 1;
#pragma unroll
                    for (int p = 0; p < 2; p++) {
                        u32 sl = st0 + p * 65536;
                        EXPECT_TX(mbf + p * 8, 65536u);
                        BULK(sl,          X + (mt0 + p) * 16384ull,        16384u, mbf + p * 8);
                        BULK(sl + 16384,  X + (mt0 + 64 + p) * 16384ull,   16384u, mbf + p * 8);
                        BULK(sl + 32768,  W + (nt0 + p) * 16384ull,        16384u, mbf + p * 8);
                        BULK(sl + 49152,  W + (nt0 + 64 + p) * 16384ull,   16384u, mbf + p * 8);
                    }
                }
#pragma unroll 1
                for (int kt = 0; kt < 64; kt++) {
                    const int kdiv = kt / 3;
                    const int s = kt - kdiv * 3;
                    const u32 sA0 = st0 + s * 65536, sA1 = sA0 + 16384, sB = sA0 + 32768;
                    u32 ph;
                    if (s == 0) { ph = (u32)pf0; pf0 ^= 1; }
                    else if (s == 1) { ph = (u32)pf1; pf1 ^= 1; }
                    else { ph = (u32)pf2; pf2 ^= 1; }
                    MWAIT(mbf + s * 8, ph);

                    u64 a0 = DBASE | ((u64)(sA0 >> 4) & 0x3FFF);
                    u64 a1 = DBASE | ((u64)(sA1 >> 4) & 0x3FFF);
                    u64 bd = DBASE | ((u64)(sB >> 4) & 0x3FFF);
#pragma unroll
                    for (int q = 0; q < 4; q++) {
                        u32 en = (kt > 0 || q > 0) ? 1u : 0u;
                        MMA8(tmem, a0 + q * 2, a1 + q * 2, bd + q * 2, IDESC, en);
                    }
                    asm volatile("tcgen05.commit.cta_group::1.mbarrier::arrive::one.shared::cluster.b64 [%0];"
                                 :: "r"(mbc + s * 8) : "memory");

                    if (kt >= 1) {
                        const int sp = (kt - 1) - ((kt - 1) / 3) * 3;
                        u32 p2;
                        if (sp == 0) { p2 = (u32)pc0; pc0 ^= 1; }
                        else if (sp == 1) { p2 = (u32)pc1; pc1 ^= 1; }
                        else { p2 = (u32)pc2; pc2 ^= 1; }
                        MWAIT(mbc + sp * 8, p2);
                    }

                    if (kt + 2 < 64) {
                        const int sd = (kt + 2) - ((kt + 2) / 3) * 3;
                        const u32 dA0 = st0 + sd * 65536;
                        const u64 kk = (u64)(kt + 2);
                        EXPECT_TX(mbf + sd * 8, 65536u);
                        BULK(dA0,          X + (mt0 + kk) * 16384ull,      16384u, mbf + sd * 8);
                        BULK(dA0 + 16384,  X + (mt0 + 64 + kk) * 16384ull, 16384u, mbf + sd * 8);
                        BULK(dA0 + 32768,  W + (nt0 + kk) * 16384ull,      16384u, mbf + sd * 8);
                        BULK(dA0 + 49152,  W + (nt0 + 64 + kk) * 16384ull, 16384u, mbf + sd * 8);
                    }
                }
                // final drain: commit(63) on slot 0
                { u32 p2 = (u32)pc0; pc0 ^= 1; MWAIT(mbc, p2); }

                // next tile's prologue (slots 0,1 free) — overlaps the epilogue
                {
                    const int tn = t + (int)gridDim.x;
                    if (tn < 512) {
                        const u64 nmt0 = (u64)((tn >> 4) * 2) * 64;
                        const u64 nnt0 = (u64)((tn & 15) * 2) * 64;
#pragma unroll
                        for (int p = 0; p < 2; p++) {
                            u32 sl = st0 + p * 65536;
                            EXPECT_TX(mbf + p * 8, 65536u);
                            BULK(sl,          X + (nmt0 + p) * 16384ull,        16384u, mbf + p * 8);
                            BULK(sl + 16384,  X + (nmt0 + 64 + p) * 16384ull,   16384u, mbf + p * 8);
                            BULK(sl + 32768,  W + (nnt0 + p) * 16384ull,        16384u, mbf + p * 8);
                            BULK(sl + 49152,  W + (nnt0 + 64 + p) * 16384ull,   16384u, mbf + p * 8);
                        }
                    }
                }
            }
        }

        __syncthreads();
        asm volatile("tcgen05.fence::after_thread_sync;" ::: "memory");

        {
            const int half = wid >> 2, wr = wid & 3;
            float* dst = out + (u64)(mBase + half * 128 + wr * 32 + lid) * 4096 + nBase;
            const u32 tm = tmem + half * 256;
#pragma unroll
            for (int ch = 0; ch < 8; ch++) {
                u32 rr[32];
                LDTM32(rr, tm + ch * 32);
                asm volatile("tcgen05.wait::ld.sync.aligned;" ::: "memory");
#pragma unroll
                for (int j = 0; j < 8; j++)
                    asm volatile("st.global.cs.v4.b32 [%0], {%1,%2,%3,%4};"
                                 :: "l"(dst + ch * 32 + j * 4),
                                    "r"(rr[4 * j]), "r"(rr[4 * j + 1]),
                                    "r"(rr[4 * j + 2]), "r"(rr[4 * j + 3]) : "memory");
            }
            asm volatile("tcgen05.fence::before_thread_sync;" ::: "memory");
        }
        __syncthreads();   // gates next tile's MMAs behind epilogue (TMEM reuse)
    }

    __syncthreads();
    if (wid == 0) {
        asm volatile("tcgen05.relinquish_alloc_permit.cta_group::1.sync.aligned;");
        asm volatile("tcgen05.dealloc.cta_group::1.sync.aligned.b32 %0, %1;"
                     :: "r"(tmem), "r"(512u));
    }
}

// ---------------- wbuild: fused LoRA GEMM + NF4 dequant (row-major or tiled) ------
extern "C" __global__ void __launch_bounds__(256, 1)
wbuild(const int* __restrict__ qw, const float* __restrict__ am,
       const u16* __restrict__ lb, const u16* __restrict__ lat,
       u16* __restrict__ w, int tiled) {
    extern __shared__ char sm[];
    u32 base = (sm2u32(sm) + 1023) & ~1023u;
    const u32 tptr = base;
    const u32 mb = base + 16;
    const u32 sa = base + 1024;
    const u32 sb = sa + 16384;
    const int tid = threadIdx.x, wid = tid >> 5, lid = tid & 31;
    const int ti = blockIdx.x;
    const int o0 = (ti >> 4) * 128, i0 = (ti & 15) * 256;

    if (wid == 0)
        asm volatile("tcgen05.alloc.cta_group::1.sync.aligned.shared::cta.b32 [%0], %1;"
                     :: "r"(tptr), "r"(256u) : "memory");
    if (tid == 0)
        asm volatile("mbarrier.init.shared.b64 [%0], %1;" :: "r"(mb), "r"(1u) : "memory");
    __syncthreads();
    u32 tmem; asm volatile("ld.shared.b32 %0,[%1];" : "=r"(tmem) : "r"(tptr));

#pragma unroll
    for (int r = 0; r < 4; r++) {
        int i = tid + r * 256; int row = i >> 3, c = i & 7;
        u32 off = (u32)(row * 128 + ((c * 16) ^ ((row & 7) << 4)));
        asm volatile("cp.async.cg.shared.global [%0], [%1], 16;"
                     :: "r"(sa + off), "l"((const char*)lb + (u64)(o0 + row) * 128 + c * 16));
    }
#pragma unroll
    for (int r = 0; r < 8; r++) {
        int i = tid + r * 256; int row = i >> 3, c = i & 7;
        u32 off = (u32)(row * 128 + ((c * 16) ^ ((row & 7) << 4)));
        asm volatile("cp.async.cg.shared.global [%0], [%1], 16;"
                     :: "r"(sb + off), "l"((const char*)lat + (u64)(i0 + row) * 128 + c * 16));
    }
    asm volatile("cp.async.commit_group;" ::: "memory");
    asm volatile("cp.async.wait_group 0;" ::: "memory");
    __syncthreads();

    const u64 DBASE = (2ull << 61) | (1ull << 46) | (64ull << 32) | (1ull << 16);
    const u32 IDESC = (1u << 4) | (32u << 17) | (8u << 24);

    if (wid == 0) {
        u32 ep;
        asm volatile("{ .reg .pred p; elect.sync _|p, 0xFFFFFFFF; selp.b32 %0,1,0,p; }"
                     : "=r"(ep));
        if (ep) {
            asm volatile("fence.proxy.async.shared::cta;" ::: "memory");
            u64 ad = DBASE | ((u64)(sa >> 4) & 0x3FFF);
            u64 bd = DBASE | ((u64)(sb >> 4) & 0x3FFF);
#pragma unroll
            for (int q = 0; q < 4; q++) {
                u32 en = (q > 0) ? 1u : 0u;
                asm volatile("{ .reg .pred p; setp.ne.u32 p, %5, 0; "
                    "tcgen05.mma.cta_group::1.kind::f16 [%0], %1, %2, %3, {%4,%4,%4,%4}, p; }"
                    :: "r"(tmem), "l"(ad + q * 2), "l"(bd + q * 2),
                       "r"(IDESC), "r"(0u), "r"(en) : "memory");
            }
            asm volatile("tcgen05.commit.cta_group::1.mbarrier::arrive::one.shared::cluster.b64 [%0];"
                         :: "r"(mb) : "memory");
        }
    }
    __syncthreads();
    MWAIT(mb, 0u);
    asm volatile("tcgen05.fence::after_thread_sync;" ::: "memory");

    const int half = wid >> 2, wr = wid & 3;
    const int o = o0 + wr * 32 + lid;
#pragma unroll
    for (int c4 = 0; c4 < 4; c4++) {
        u32 rr[32];
        LDTM32(rr, tmem + half * 128 + c4 * 32);
        asm volatile("tcgen05.wait::ld.sync.aligned;" ::: "memory");
        const int ib = i0 + half * 128 + c4 * 32;
        const u64 k = (u64)o * 4096 + (u64)ib;
        const float a = am[k >> 6];
        const int4* qp = (const int4*)qw + (k >> 3);
        u32 ov[16];
#pragma unroll
        for (int u = 0; u < 4; u++) {
            int4 qv = qp[u];
            int e[8] = {qv.x & 15, (qv.x >> 4) & 15, qv.y & 15, (qv.y >> 4) & 15,
                        qv.z & 15, (qv.z >> 4) & 15, qv.w & 15, (qv.w >> 4) & 15};
#pragma unroll
            for (int j = 0; j < 4; j++) {
                union { u32 u_; float f_; } c0, c1;
                c0.u_ = rr[u * 8 + 2 * j];
                c1.u_ = rr[u * 8 + 2 * j + 1];
                float w0 = NF4D[e[2 * j]] * a + c0.f_;
                float w1 = NF4D[e[2 * j + 1]] * a + c1.f_;
                asm("cvt.rn.f16x2.f32 %0, %1, %2;" : "=r"(ov[u * 4 + j]) : "f"(w1), "f"(w0));
            }
        }
        if (!tiled) {
            char* wp = (char*)w + k * 2;
#pragma unroll
            for (int j = 0; j < 4; j++)
                asm volatile("st.global.cs.v4.b32 [%0], {%1,%2,%3,%4};"
                             :: "l"(wp + j * 16), "r"(ov[4 * j]), "r"(ov[4 * j + 1]),
                                "r"(ov[4 * j + 2]), "r"(ov[4 * j + 3]) : "memory");
        } else {
            const u64 tbase = ((u64)((o >> 7) * 64 + (ib >> 6))) * 16384ull;
            const u32 rowoff = (u32)((o & 127) * 128 + (ib & 63) * 2);
#pragma unroll
            for (int j = 0; j < 4; j++) {
                u32 off = rowoff + (u32)(j * 16);
                off = off ^ ((off >> 3) & 0x70);
                asm volatile("st.global.cs.v4.b32 [%0], {%1,%2,%3,%4};"
                             :: "l"((char*)w + tbase + off),
                                "r"(ov[4 * j]), "r"(ov[4 * j + 1]),
                                "r"(ov[4 * j + 2]), "r"(ov[4 * j + 3]) : "memory");
            }
        }
    }
    asm volatile("tcgen05.fence::before_thread_sync;" ::: "memory");
    __syncthreads();
    if (wid == 0) {
        asm volatile("tcgen05.relinquish_alloc_permit.cta_group::1.sync.aligned;");
        asm volatile("tcgen05.dealloc.cta_group::1.sync.aligned.b32 %0, %1;"
                     :: "r"(tmem), "r"(256u));
    }
}
)NVSRC";

// --- driver/nvrtc plumbing ---
typedef int (*nvrtcCreateProgram_t)(void**, const char*, const char*, int,
                                    const char* const*, const char* const*);
typedef int (*nvrtcCompileProgram_t)(void*, int, const char* const*);
typedef int (*nvrtcGetCUBINSize_t)(void*, size_t*);
typedef int (*nvrtcGetCUBIN_t)(void*, char*);
typedef int (*cuInit_t)(unsigned);
typedef int (*cuDevicePrimaryCtxRetain_t)(void**, int);
typedef int (*cuCtxSetCurrent_t)(void*);
typedef int (*cuModuleLoadDataEx_t)(void**, const void*, unsigned, int*, void**);
typedef int (*cuModuleGetFunction_t)(void**, void*, const char*);
typedef int (*cuModuleGetGlobal_t)(unsigned long long*, size_t*, void*, const char*);
typedef int (*cuFuncSetAttribute_t)(void*, int, int);
typedef int (*cuLaunchKernel_t)(void*, unsigned, unsigned, unsigned,
                                unsigned, unsigned, unsigned,
                                unsigned, void*, void**, void**);
typedef int (*cuCtxSynchronize_t)(void);
typedef int (*cuMemcpyDtoH_t)(void*, unsigned long long, size_t);

#if defined(CUDA_API_PER_THREAD_DEFAULT_STREAM) || defined(__CUDA_API_PER_THREAD_DEFAULT_STREAM)
#define DRV_STREAM ((void*)0x2)
#else
#define DRV_STREAM ((void*)0x1)
#endif

static bool g_ok_gemm = false, g_ok_wb = false;
static int g_mode = 0;  // 4 = tiled bulk (7c/7), 1 = row-major (5c/5), 0 = host
static unsigned g_grid = 148;  // GEMM grid (128 for balanced 7c, 148 otherwise)
static cuLaunchKernel_t p_cuLaunchKernel = nullptr;
static void* g_fn_gemm = nullptr;
static void* g_fn_wbuild = nullptr;
static unsigned long long g_gx = 0, g_gw = 0, g_glb = 0, g_glat = 0;
constexpr int SMEM5 = 198656;
constexpr int SMEMW = 51200;

static float h2f(uint16_t h) {
    uint32_t s = (h >> 15) & 1, e = (h >> 10) & 31, m = h & 1023;
    uint32_t f;
    if (e == 0) {
        if (m == 0) f = s << 31;
        else {
            e = 127 - 15 + 1;
            while (!(m & 1024)) { m <<= 1; e--; }
            m &= 1023;
            f = (s << 31) | (e << 23) | (m << 13);
        }
    } else if (e == 31) f = (s << 31) | 0x7F800000 | (m << 13);
    else f = (s << 31) | ((e - 15 + 127) << 23) | (m << 13);
    float r; memcpy(&r, &f, 4); return r;
}

static bool try_init_tcgen05() {
    void* hcu = dlopen("libcuda.so.1", RTLD_NOW | RTLD_GLOBAL);
    if (!hcu) hcu = dlopen("libcuda.so", RTLD_NOW | RTLD_GLOBAL);
    if (!hcu) return false;
    void* hnv = dlopen("libnvrtc.so.13", RTLD_NOW | RTLD_GLOBAL);
    if (!hnv) hnv = dlopen("libnvrtc.so", RTLD_NOW | RTLD_GLOBAL);
    if (!hnv) hnv = dlopen("libnvrtc.so.12", RTLD_NOW | RTLD_GLOBAL);
    if (!hnv) return false;

    auto nCreate  = (nvrtcCreateProgram_t)dlsym(hnv, "nvrtcCreateProgram");
    auto nCompile = (nvrtcCompileProgram_t)dlsym(hnv, "nvrtcCompileProgram");
    auto nCbSize  = (nvrtcGetCUBINSize_t)dlsym(hnv, "nvrtcGetCUBINSize");
    auto nCb      = (nvrtcGetCUBIN_t)dlsym(hnv, "nvrtcGetCUBIN");
    auto cInit    = (cuInit_t)dlsym(hcu, "cuInit");
    auto cRetain  = (cuDevicePrimaryCtxRetain_t)dlsym(hcu, "cuDevicePrimaryCtxRetain");
    auto cSetCur  = (cuCtxSetCurrent_t)dlsym(hcu, "cuCtxSetCurrent");
    auto cModLoad = (cuModuleLoadDataEx_t)dlsym(hcu, "cuModuleLoadDataEx");
    auto cGetFn   = (cuModuleGetFunction_t)dlsym(hcu, "cuModuleGetFunction");
    auto cGetGlb  = (cuModuleGetGlobal_t)dlsym(hcu, "cuModuleGetGlobal_v2");
    auto cSetAttr = (cuFuncSetAttribute_t)dlsym(hcu, "cuFuncSetAttribute");
    auto cLaunch  = (cuLaunchKernel_t)dlsym(hcu, "cuLaunchKernel");
    auto cSync    = (cuCtxSynchronize_t)dlsym(hcu, "cuCtxSynchronize");
    auto cD2H     = (cuMemcpyDtoH_t)dlsym(hcu, "cuMemcpyDtoH_v2");
    if (!nCreate || !nCompile || !nCbSize || !nCb || !cInit || !cRetain ||
        !cSetCur || !cModLoad || !cGetFn || !cGetGlb || !cSetAttr ||
        !cLaunch || !cSync || !cD2H)
        return false;

    if (cInit(0)) return false;
    void* ctx = nullptr;
    if (cRetain(&ctx, 0)) return false;
    if (cSetCur(ctx)) return false;

    void* prog = nullptr;
    if (nCreate(&prog, NVRTC_SRC, "gemm7c.cu", 0, nullptr, nullptr)) return false;
    const char* opts[] = {"--gpu-architecture=sm_103a"};
    if (nCompile(prog, 1, opts)) return false;
    size_t cbsz = 0;
    if (nCbSize(prog, &cbsz) || cbsz == 0) return false;
    static char* cubin = new char[cbsz];
    if (nCb(prog, cubin)) return false;

    void* mod = nullptr;
    if (cModLoad(&mod, cubin, 0, nullptr, nullptr)) return false;
    void *fG5 = nullptr, *fG5c = nullptr, *fG7 = nullptr, *fG7c = nullptr;
    void *fInit = nullptr, *fInit7 = nullptr, *fWb = nullptr, *fWti = nullptr;
    if (cGetFn(&fG5, mod, "gemm5")) return false;
    if (cGetFn(&fG5c, mod, "gemm5c")) return false;
    if (cGetFn(&fG7, mod, "gemm7")) return false;
    if (cGetFn(&fG7c, mod, "gemm7c")) return false;
    if (cGetFn(&fInit, mod, "initt")) return false;
    if (cGetFn(&fInit7, mod, "init7")) return false;
    if (cGetFn(&fWb, mod, "wbuild")) return false;
    if (cGetFn(&fWti, mod, "wtinit")) return false;
    unsigned long long gx = 0, gw = 0, gout = 0, glb = 0, glat = 0,
                       gtqw = 0, gtam = 0;
    size_t sz;
    if (cGetGlb(&gx, &sz, mod, "GX")) return false;
    if (cGetGlb(&gw, &sz, mod, "GW")) return false;
    if (cGetGlb(&gout, &sz, mod, "GOUT")) return false;
    if (cGetGlb(&glb, &sz, mod, "GLB")) return false;
    if (cGetGlb(&glat, &sz, mod, "GLAT")) return false;
    if (cGetGlb(&gtqw, &sz, mod, "GTQW")) return false;
    if (cGetGlb(&gtam, &sz, mod, "GTAM")) return false;
    if (cSetAttr(fG5, 8, SMEM5)) return false;
    if (cSetAttr(fG5c, 8, SMEM5)) return false;
    if (cSetAttr(fG7, 8, SMEM5)) return false;
    if (cSetAttr(fG7c, 8, SMEM5)) return false;
    if (cSetAttr(fWb, 8, SMEMW)) return false;

    p_cuLaunchKernel = cLaunch;
    g_gx = gx; g_gw = gw; g_glb = glb; g_glat = glat;

    static float row[OUT_F];
    const int ms4[4] = {0, 97, 4095, 8191};
    auto check_out = [&](unsigned long long gout_) -> bool {
        for (int ri = 0; ri < 4; ri++) {
            int m = ms4[ri];
            if (cD2H(row, gout_ + (unsigned long long)m * OUT_F * 4, OUT_F * 4))
                return false;
            for (int n = 0; n < OUT_F; n++) {
                float ref = 0.0f;
                for (int k = 0; k < IN_F; k++) {
                    int av = (k * 131 + m * 7) % 9 - 4;
                    int bv = (k * 17 + n * 3) % 7 - 3;
                    ref += (av * 0.25f) * (bv * 0.25f);
                }
                if (fabsf(row[n] - ref) > 0.01f) return false;
            }
        }
        return true;
    };

    // ---- tiled init ----
    bool tiled_ready =
        (cLaunch(fInit7, 131072, 1, 1, 256, 1, 1, 0, DRV_STREAM, nullptr, nullptr) == 0 &&
         cSync() == 0);

    // ---- TEST gemm7c at grid=128 (perfect 4-tiles/CTA balance), then gemm7@148 ----
    bool g7cok = false, g7ok = false;
    if (tiled_ready) {
        unsigned long long px = gx, pw = gw, po = gout;
        void* args[3] = {&px, &pw, &po};
        if (cLaunch(fG7c, 128, 1, 1, 256, 1, 1, SMEM5, DRV_STREAM, args, nullptr) == 0 &&
            cSync() == 0 && check_out(gout))
            g7cok = true;
        if (!g7cok) {
            if (cLaunch(fG7, 148, 1, 1, 256, 1, 1, SMEM5, DRV_STREAM, args, nullptr) == 0 &&
                cSync() == 0 && check_out(gout))
                g7ok = true;
        }
    }

    // ---- wbuild math + tiled layout tests ----
    bool wb_math_ok = false, wb_tiled_ok = false;
    if (cLaunch(fWti, 32768, 1, 1, 256, 1, 1, 0, DRV_STREAM, nullptr, nullptr) == 0 &&
        cSync() == 0) {
        auto wref = [&](int o, int i) -> float {
            uint64_t k = (uint64_t)o * 4096 + i;
            int qv = (int)(((k >> 1) * 37ull) & 255ull);
            int nib = (k & 1) ? (qv >> 4) & 15 : qv & 15;
            float a = (float)(((uint32_t)((k >> 6) * 13ull)) % 31u + 1u) * 0.03125f;
            float lora = 0.0f;
            for (int r = 0; r < 64; r++) {
                float lb = (float)((int)(((uint32_t)o * 3u + r * 7u) % 17u) - 8) * 0.015625f;
                float la = (float)((int)(((uint32_t)i * 5u + r * 11u) % 19u) - 9) * 0.015625f;
                lora += lb * la;
            }
            return NF4H[nib] * a + lora;
        };
        auto run_wb = [&](int tiled) -> bool {
            unsigned long long pq = gtqw, pa = gtam, pl = glb, pt = glat, pw2 = gw;
            int tf = tiled;
            void* args[6] = {&pq, &pa, &pl, &pt, &pw2, &tf};
            if (cLaunch(fWb, 512, 1, 1, 256, 1, 1, SMEMW, DRV_STREAM, args, nullptr))
                return false;
            return cSync() == 0;
        };
        const int os[4] = {0, 1, 255, 4095};
        static uint16_t wrow[IN_F];
        if (run_wb(0)) {
            bool ok = true;
            for (int oi = 0; oi < 4 && ok; oi++) {
                int o = os[oi];
                if (cD2H(wrow, gw + (unsigned long long)o * IN_F * 2, IN_F * 2)) { ok = false; break; }
                for (int i = 0; i < IN_F; i++)
                    if (fabsf(h2f(wrow[i]) - wref(o, i)) > 0.01f) { ok = false; break; }
            }
            wb_math_ok = ok;
        }
        if (wb_math_ok && (g7cok || g7ok) && run_wb(1)) {
            static uint16_t* hw = new uint16_t[16777216];
            if (cD2H(hw, gw, (size_t)16777216 * 2) == 0) {
                bool ok = true;
                for (int oi = 0; oi < 4 && ok; oi++) {
                    int o = os[oi];
                    for (int i = 0; i < IN_F; i++) {
                        uint32_t off = (uint32_t)((o & 127) * 128 + (i & 63) * 2);
                        off = off ^ ((off >> 3) & 0x70);
                        uint64_t boff = ((uint64_t)((o >> 7) * 64 + (i >> 6))) * 16384ull + off;
                        if (fabsf(h2f(hw[boff >> 1]) - wref(o, i)) > 0.01f) { ok = false; break; }
                    }
                }
                wb_tiled_ok = ok;
            }
        }
    }

    if ((g7cok || g7ok) && wb_tiled_ok) {
        g_fn_gemm = g7cok ? fG7c : fG7;
        g_grid = g7cok ? 128u : 148u;
        g_ok_gemm = true; g_mode = 4;
        g_fn_wbuild = fWb; g_ok_wb = true;
        return true;
    }
    // row-major ladder
    if (cLaunch(fInit, 131072, 1, 1, 256, 1, 1, 0, DRV_STREAM, nullptr, nullptr) ||
        cSync())
        return false;
    {
        unsigned long long px = gx, pw = gw, po = gout;
        void* args[3] = {&px, &pw, &po};
        if (cLaunch(fG5c, 148, 1, 1, 256, 1, 1, SMEM5, DRV_STREAM, args, nullptr) == 0 &&
            cSync() == 0 && check_out(gout)) {
            g_fn_gemm = fG5c; g_ok_gemm = true; g_mode = 1; g_grid = 148u;
        } else if (cLaunch(fG5, 148, 1, 1, 256, 1, 1, SMEM5, DRV_STREAM, args, nullptr) == 0 &&
                   cSync() == 0 && check_out(gout)) {
            g_fn_gemm = fG5; g_ok_gemm = true; g_mode = 1; g_grid = 148u;
        }
    }
    if (g_ok_gemm && wb_math_ok) { g_fn_wbuild = fWb; g_ok_wb = true; }
    return g_ok_gemm;
}

__attribute__((constructor))
static void _init_drv() {
    try_init_tcgen05();
}

// ---------------------------------------------------------------------------
extern "C" void kernel_launch(void* const* d_in, const int* in_sizes, int n_in,
                              void* d_out, int out_size) {
    const float* x  = (const float*)d_in[0];
    const int*   qw = (const int*)d_in[1];
    const float* am = (const float*)d_in[2];
    const float* lA = (const float*)d_in[3];
    const float* lB = (const float*)d_in[4];
    float*       out = (float*)d_out;

    (void)in_sizes; (void)n_in; (void)out_size;

    if (g_ok_gemm) {
        __half* xh = (__half*)(uintptr_t)g_gx;
        __half* wh = (__half*)(uintptr_t)g_gw;

        if (g_mode >= 4)
            convert_x_tiled_kernel<<<(M_ROWS * IN_F / 8) / 256, 256>>>(x, (char*)xh);
        else
            convert_x_kernel<<<(M_ROWS * IN_F / 8) / 256, 256>>>(x, xh);

        if (g_ok_wb) {
            cvt_lb_kernel<<<256, 256>>>(lB, (__half*)(uintptr_t)g_glb);
            cvt_lat_kernel<<<64, 256>>>(lA, (__half*)(uintptr_t)g_glat);
            unsigned long long pq = (unsigned long long)(uintptr_t)qw;
            unsigned long long pa = (unsigned long long)(uintptr_t)am;
            unsigned long long pl = g_glb, pt = g_glat, pw = g_gw;
            int tf = (g_mode >= 4) ? 1 : 0;
            void* args[6] = {&pq, &pa, &pl, &pt, &pw, &tf};
            p_cuLaunchKernel(g_fn_wbuild, 512, 1, 1, 256, 1, 1, SMEMW,
                             DRV_STREAM, args, nullptr);
        } else {
            build_weff_kernel<<<dim3(IN_F / 128, OUT_F / 64), 256>>>(qw, am, lA, lB, wh);
        }

        unsigned long long px = g_gx, pw2 = g_gw;
        void* po = (void*)out;
        void* args[3] = {&px, &pw2, &po};
        p_cuLaunchKernel(g_fn_gemm, g_grid, 1, 1, 256, 1, 1, SMEM5,
                         DRV_STREAM, args, nullptr);
    } else {
        __half* xh; __half* wh;
        cudaGetSymbolAddress((void**)&xh, g_Xh);
        cudaGetSymbolAddress((void**)&wh, g_Wh);
        convert_x_kernel<<<(M_ROWS * IN_F / 8) / 256, 256>>>(x, xh);
        build_weff_kernel<<<dim3(IN_F / 128, OUT_F / 64), 256>>>(qw, am, lA, lB, wh);
        cudaFuncSetAttribute(gemm_f16_kernel,
                             cudaFuncAttributeMaxDynamicSharedMemorySize, SMEM_TOTAL);
        gemm_f16_kernel<<<148, 512, SMEM_TOTAL>>>(xh, wh, out);
    }
}